// round 6
// baseline (speedup 1.0000x reference)
#include <cuda_runtime.h>
#include <cuda_bf16.h>
#include <cstdint>

// Problem constants
#define B_  2
#define S_  2048
#define D_  1024
#define H_  16
#define DH_ 64
#define M_  (B_*S_)          // 4096 rows total

// ---------------------------------------------------------------------------
// Scratch (allocation-free __device__ globals), all bf16 hi/lo pairs
// ---------------------------------------------------------------------------
__device__ __nv_bfloat16 g_qhi[(size_t)B_*H_*S_*DH_];   // head-major
__device__ __nv_bfloat16 g_qlo[(size_t)B_*H_*S_*DH_];
__device__ __nv_bfloat16 g_khi[(size_t)B_*H_*S_*DH_];
__device__ __nv_bfloat16 g_klo[(size_t)B_*H_*S_*DH_];
__device__ __nv_bfloat16 g_vhi[(size_t)B_*H_*S_*DH_];
__device__ __nv_bfloat16 g_vlo[(size_t)B_*H_*S_*DH_];
__device__ __nv_bfloat16 g_chi[(size_t)M_*D_];          // ctx row-major
__device__ __nv_bfloat16 g_clo[(size_t)M_*D_];
__device__ __nv_bfloat16 g_xhi[(size_t)M_*D_];
__device__ __nv_bfloat16 g_xlo[(size_t)M_*D_];
__device__ __nv_bfloat16 g_whi[(size_t)4*D_*D_];
__device__ __nv_bfloat16 g_wlo[(size_t)4*D_*D_];

// ---------------------------------------------------------------------------
// PTX helpers (plain sm_80-class PTX: valid under compute_103)
// ---------------------------------------------------------------------------
__device__ __forceinline__ uint32_t smem_u32(const void* p) {
    uint32_t a;
    asm("{ .reg .u64 t; cvta.to.shared.u64 t, %1; cvt.u32.u64 %0, t; }"
        : "=r"(a) : "l"(p));
    return a;
}
__device__ __forceinline__ void cp16(uint32_t dst, const void* src) {
    asm volatile("cp.async.cg.shared.global [%0], [%1], 16;"
                 :: "r"(dst), "l"(src) : "memory");
}
__device__ __forceinline__ void cp_commit() {
    asm volatile("cp.async.commit_group;" ::: "memory");
}
__device__ __forceinline__ void cp_wait0() {
    asm volatile("cp.async.wait_group 0;" ::: "memory");
}
__device__ __forceinline__ void cp_wait1() {
    asm volatile("cp.async.wait_group 1;" ::: "memory");
}
__device__ __forceinline__ void ldsm4(uint32_t& r0, uint32_t& r1, uint32_t& r2,
                                      uint32_t& r3, uint32_t addr) {
    asm volatile("ldmatrix.sync.aligned.m8n8.x4.shared.b16 {%0,%1,%2,%3}, [%4];"
                 : "=r"(r0), "=r"(r1), "=r"(r2), "=r"(r3) : "r"(addr));
}
__device__ __forceinline__ void ldsm4t(uint32_t& r0, uint32_t& r1, uint32_t& r2,
                                       uint32_t& r3, uint32_t addr) {
    asm volatile("ldmatrix.sync.aligned.m8n8.x4.trans.shared.b16 {%0,%1,%2,%3}, [%4];"
                 : "=r"(r0), "=r"(r1), "=r"(r2), "=r"(r3) : "r"(addr));
}
__device__ __forceinline__ void mma16816(float* c, const uint32_t* a, const uint32_t* b) {
    asm volatile(
        "mma.sync.aligned.m16n8k16.row.col.f32.bf16.bf16.f32 "
        "{%0,%1,%2,%3}, {%4,%5,%6,%7}, {%8,%9}, {%0,%1,%2,%3};"
        : "+f"(c[0]), "+f"(c[1]), "+f"(c[2]), "+f"(c[3])
        : "r"(a[0]), "r"(a[1]), "r"(a[2]), "r"(a[3]), "r"(b[0]), "r"(b[1]));
}
__device__ __forceinline__ float ex2(float x) {
    float y; asm("ex2.approx.ftz.f32 %0, %1;" : "=f"(y) : "f"(x)); return y;
}
// Swizzle<3,4,3>: XOR 16B-column bits [6:4] with row bits [9:7]
__device__ __forceinline__ uint32_t swz(uint32_t off) {
    return off ^ ((off >> 3) & 0x70);
}
__device__ __forceinline__ uint32_t packbf(__nv_bfloat16 a, __nv_bfloat16 b) {
    __nv_bfloat162 h = __halves2bfloat162(a, b);
    return *(uint32_t*)&h;
}

// ---------------------------------------------------------------------------
// fp32 -> bf16 hi/lo splits
// ---------------------------------------------------------------------------
__global__ void split_bf16(const float* __restrict__ src,
                           __nv_bfloat16* __restrict__ hi,
                           __nv_bfloat16* __restrict__ lo)
{
    const size_t i = ((size_t)blockIdx.x * blockDim.x + threadIdx.x) * 4;
    float4 v = *(const float4*)(src + i);
    __nv_bfloat16 h0 = __float2bfloat16(v.x), h1 = __float2bfloat16(v.y);
    __nv_bfloat16 h2 = __float2bfloat16(v.z), h3 = __float2bfloat16(v.w);
    *(__nv_bfloat162*)(hi + i)     = __halves2bfloat162(h0, h1);
    *(__nv_bfloat162*)(hi + i + 2) = __halves2bfloat162(h2, h3);
    *(__nv_bfloat162*)(lo + i) = __halves2bfloat162(
        __float2bfloat16(v.x - __bfloat162float(h0)),
        __float2bfloat16(v.y - __bfloat162float(h1)));
    *(__nv_bfloat162*)(lo + i + 2) = __halves2bfloat162(
        __float2bfloat16(v.z - __bfloat162float(h2)),
        __float2bfloat16(v.w - __bfloat162float(h3)));
}

__global__ void split4_bf16(const float* __restrict__ a, const float* __restrict__ b,
                            const float* __restrict__ c, const float* __restrict__ d,
                            __nv_bfloat16* __restrict__ hi,
                            __nv_bfloat16* __restrict__ lo)
{
    const int w = blockIdx.y;
    const float* src = (w == 0) ? a : (w == 1) ? b : (w == 2) ? c : d;
    const size_t base = (size_t)w * D_ * D_;
    const size_t i = ((size_t)blockIdx.x * blockDim.x + threadIdx.x) * 4;
    float4 v = *(const float4*)(src + i);
    __nv_bfloat16 h0 = __float2bfloat16(v.x), h1 = __float2bfloat16(v.y);
    __nv_bfloat16 h2 = __float2bfloat16(v.z), h3 = __float2bfloat16(v.w);
    *(__nv_bfloat162*)(hi + base + i)     = __halves2bfloat162(h0, h1);
    *(__nv_bfloat162*)(hi + base + i + 2) = __halves2bfloat162(h2, h3);
    *(__nv_bfloat162*)(lo + base + i) = __halves2bfloat162(
        __float2bfloat16(v.x - __bfloat162float(h0)),
        __float2bfloat16(v.y - __bfloat162float(h1)));
    *(__nv_bfloat162*)(lo + base + i + 2) = __halves2bfloat162(
        __float2bfloat16(v.z - __bfloat162float(h2)),
        __float2bfloat16(v.w - __bfloat162float(h3)));
}

// ---------------------------------------------------------------------------
// HMMA bf16x3 GEMM: C[m,n] = sum_k A[m,k]*W[n,k]   (A,W split hi/lo)
// 128x128 CTA tile, BK=64, 256 threads (8 warps = 2m x 4n, warp tile 64x32).
// THREE-stage cp.async pipeline (prefetch depth 2), one barrier per chunk.
// MODE 0: fused-QKV store to g_q/g_k/g_v (bf16 hi/lo, head-major); N=3072
// MODE 1: store fp32 row-major + bias
// ---------------------------------------------------------------------------
#define TILE_B  16384                // 128 x 128B
#define STG_B   (4*TILE_B)           // 64 KB: Ahi,Alo,Bhi,Blo
#define TG_SMEM (3*STG_B)            // 192 KB
#define NCHUNK  (D_/64)              // 16

template<int MODE>
__global__ __launch_bounds__(256, 1) void tgemm(const __nv_bfloat16* __restrict__ Ahi,
                                                const __nv_bfloat16* __restrict__ Alo,
                                                const __nv_bfloat16* __restrict__ Bhi,
                                                const __nv_bfloat16* __restrict__ Blo,
                                                const float* __restrict__ bias,
                                                float* __restrict__ outf)
{
    extern __shared__ char smem[];
    const uint32_t sb = smem_u32(smem);
    const int tid  = threadIdx.x;
    const int wid  = tid >> 5;
    const int lane = tid & 31;
    const int wm   = wid >> 2;          // 0..1
    const int wn   = wid & 3;           // 0..3
    const int m0   = blockIdx.y * 128;
    const int n0   = blockIdx.x * 128;

    const char* gsrc[4] = {
        (const char*)(Ahi + (size_t)m0 * D_),
        (const char*)(Alo + (size_t)m0 * D_),
        (const char*)(Bhi + (size_t)n0 * D_),
        (const char*)(Blo + (size_t)n0 * D_) };

    auto load_stage = [&](int chunk, int stg) {
        const uint32_t koff = (uint32_t)chunk * 128;
        const uint32_t stage = sb + (uint32_t)stg * STG_B;
#pragma unroll
        for (int t = 0; t < 4; ++t) {
            const char* base = gsrc[t] + koff;
            const uint32_t dstt = stage + t * TILE_B;
#pragma unroll
            for (int it = 0; it < 4; ++it) {
                const int c = tid + it * 256;
                const int r = c >> 3, c16 = c & 7;
                cp16(dstt + swz((uint32_t)(r * 128 + c16 * 16)),
                     base + (size_t)r * (D_ * 2) + c16 * 16);
            }
        }
        cp_commit();
    };

    float acc[4][4][4];
#pragma unroll
    for (int i = 0; i < 4; i++)
#pragma unroll
        for (int j = 0; j < 4; j++)
#pragma unroll
            for (int q = 0; q < 4; q++) acc[i][j][q] = 0.f;

    load_stage(0, 0);
    load_stage(1, 1);

    int stg = 0;
    for (int c = 0; c < NCHUNK; ++c) {
        if (c < NCHUNK - 1) cp_wait1(); else cp_wait0();
        __syncthreads();
        if (c + 2 < NCHUNK) {
            int ns = stg + 2; if (ns >= 3) ns -= 3;
            load_stage(c + 2, ns);
        }
        const uint32_t cur = sb + (uint32_t)stg * STG_B;
        const uint32_t aHi = cur;
        const uint32_t aLo = cur + TILE_B;
        const uint32_t bHi = cur + 2 * TILE_B;
        const uint32_t bLo = cur + 3 * TILE_B;

#pragma unroll
        for (int ks = 0; ks < 4; ++ks) {
            uint32_t ahi[4][4], alo[4][4];
            {
                const int rA = wm * 64 + (lane & 15);
                const uint32_t colA = (uint32_t)(ks * 32 + (lane >> 4) * 16);
#pragma unroll
                for (int mf = 0; mf < 4; ++mf) {
                    const uint32_t off = swz((uint32_t)(rA + mf * 16) * 128 + colA);
                    ldsm4(ahi[mf][0], ahi[mf][1], ahi[mf][2], ahi[mf][3], aHi + off);
                    ldsm4(alo[mf][0], alo[mf][1], alo[mf][2], alo[mf][3], aLo + off);
                }
            }
            uint32_t bhi[4][2], blo[4][2];
            {
                const int t = lane >> 3;
                const int rB0 = wn * 32 + ((t >> 1) * 8) + (lane & 7);
                const uint32_t colB = (uint32_t)(ks * 32 + (t & 1) * 16);
#pragma unroll
                for (int p = 0; p < 2; ++p) {
                    const uint32_t off = swz((uint32_t)(rB0 + p * 16) * 128 + colB);
                    ldsm4(bhi[2*p][0], bhi[2*p][1], bhi[2*p+1][0], bhi[2*p+1][1], bHi + off);
                    ldsm4(blo[2*p][0], blo[2*p][1], blo[2*p+1][0], blo[2*p+1][1], bLo + off);
                }
            }
#pragma unroll
            for (int mf = 0; mf < 4; ++mf)
#pragma unroll
                for (int nf = 0; nf < 4; ++nf) {
                    mma16816(acc[mf][nf], ahi[mf], bhi[nf]);
                    mma16816(acc[mf][nf], ahi[mf], blo[nf]);
                    mma16816(acc[mf][nf], alo[mf], bhi[nf]);
                }
        }
        if (++stg >= 3) stg -= 3;
    }

    // ---- epilogue ----
    const int gid = lane >> 2, tig = lane & 3;
    __nv_bfloat16 *dhi = nullptr, *dlo = nullptr;
    if (MODE == 0) {
        const int sel = n0 >> 10;
        dhi = (sel == 0) ? g_qhi : (sel == 1) ? g_khi : g_vhi;
        dlo = (sel == 0) ? g_qlo : (sel == 1) ? g_klo : g_vlo;
    }
#pragma unroll
    for (int mf = 0; mf < 4; ++mf)
#pragma unroll
        for (int nf = 0; nf < 4; ++nf)
#pragma unroll
            for (int half = 0; half < 2; ++half) {
                const int m = m0 + wm * 64 + mf * 16 + gid + half * 8;
                const int n = n0 + wn * 32 + nf * 8 + tig * 2;
                float2 v = make_float2(acc[mf][nf][half*2], acc[mf][nf][half*2+1]);
                if (MODE == 1) {
                    v.x += bias[n]; v.y += bias[n+1];
                    *(float2*)(outf + (size_t)m * D_ + n) = v;
                } else {
                    const int nl = n & (D_ - 1);
                    const int b  = m >> 11;
                    const int s  = m & (S_ - 1);
                    const int h  = nl >> 6;
                    const int dh = nl & (DH_ - 1);
                    const size_t idx = ((size_t)(b * H_ + h) * S_ + s) * DH_ + dh;
                    __nv_bfloat16 h0 = __float2bfloat16(v.x);
                    __nv_bfloat16 h1 = __float2bfloat16(v.y);
                    *(__nv_bfloat162*)(dhi + idx) = __halves2bfloat162(h0, h1);
                    *(__nv_bfloat162*)(dlo + idx) = __halves2bfloat162(
                        __float2bfloat16(v.x - __bfloat162float(h0)),
                        __float2bfloat16(v.y - __bfloat162float(h1)));
                }
            }
}

// ---------------------------------------------------------------------------
// HMMA flash attention, causal. Same math as R4/R5; P-pack interleaved with
// P·V MMAs (no phA/plA staging arrays -> ~64 fewer live registers, no spills).
// ---------------------------------------------------------------------------
#define SM_Q    0
#define SM_KV   32768
#define KV_STG  65536
#define ATT_SMEM (32768 + 2*KV_STG)     // 163840 B

__global__ __launch_bounds__(256, 1) void attn_tc()
{
    extern __shared__ char smem[];
    const uint32_t sb = smem_u32(smem);
    const int tid  = threadIdx.x;
    const int w    = tid >> 5;
    const int lane = tid & 31;
    const int gid  = lane >> 2;
    const int tig  = lane & 3;
    const int qt   = (int)(gridDim.x - 1 - blockIdx.x);
    const int bh   = blockIdx.y;
    const int q0   = qt * 128;
    const int b    = bh >> 4;
    const int h    = bh & (H_ - 1);

    const size_t headoff = (size_t)bh * S_ * DH_;

    {
        const char* qh = (const char*)(g_qhi + headoff + (size_t)q0 * DH_);
        const char* ql = (const char*)(g_qlo + headoff + (size_t)q0 * DH_);
#pragma unroll
        for (int it = 0; it < 4; ++it) {
            const int c = tid + it * 256;
            const int r = c >> 3, c16 = c & 7;
            const uint32_t off = swz((uint32_t)(r * 128 + c16 * 16));
            cp16(sb + SM_Q + off,         qh + r * 128 + c16 * 16);
            cp16(sb + SM_Q + 16384 + off, ql + r * 128 + c16 * 16);
        }
    }
    auto load_kv = [&](int kt, int stg) {
        const uint32_t base = sb + SM_KV + stg * KV_STG;
        const size_t g = headoff + (size_t)kt * 128 * DH_;
        const char* srcs[4] = { (const char*)(g_khi + g), (const char*)(g_klo + g),
                                (const char*)(g_vhi + g), (const char*)(g_vlo + g) };
#pragma unroll
        for (int t = 0; t < 4; ++t) {
#pragma unroll
            for (int it = 0; it < 4; ++it) {
                const int c = tid + it * 256;
                const int r = c >> 3, c16 = c & 7;
                cp16(base + t * 16384 + swz((uint32_t)(r * 128 + c16 * 16)),
                     srcs[t] + r * 128 + c16 * 16);
            }
        }
        cp_commit();
    };
    load_kv(0, 0);

    float m0v = -1e30f, m1v = -1e30f, l0v = 0.f, l1v = 0.f;
    float o[8][4];
#pragma unroll
    for (int i = 0; i < 8; i++)
#pragma unroll
        for (int j = 0; j < 4; j++) o[i][j] = 0.f;

    uint32_t qh[4][4], ql[4][4];
    const int qrow0 = q0 + w * 16 + gid;
    const int qrow1 = qrow0 + 8;
    const float SC = 0.18033688011112042f;   // (1/sqrt(64)) * log2(e)

    for (int kt = 0; kt <= qt; ++kt) {
        cp_wait0();
        __syncthreads();
        if (kt == 0) {
            const int rA = w * 16 + (lane & 15);
            const uint32_t colA = (uint32_t)((lane >> 4) * 16);
#pragma unroll
            for (int ks = 0; ks < 4; ++ks) {
                const uint32_t off = swz((uint32_t)rA * 128 + ks * 32 + colA);
                ldsm4(qh[ks][0], qh[ks][1], qh[ks][2], qh[ks][3], sb + SM_Q + off);
                ldsm4(ql[ks][0], ql[ks][1], ql[ks][2], ql[ks][3], sb + SM_Q + 16384 + off);
            }
        }
        if (kt < qt) load_kv(kt + 1, (kt + 1) & 1);

        const uint32_t cur = sb + SM_KV + (kt & 1) * KV_STG;
        const uint32_t KHI = cur, KLO = cur + 16384, VHI = cur + 32768, VLO = cur + 49152;
        const int k0 = kt * 128;

        float sacc[16][4];
#pragma unroll
        for (int i = 0; i < 16; i++)
#pragma unroll
            for (int j = 0; j < 4; j++) sacc[i][j] = 0.f;

#pragma unroll
        for (int ks = 0; ks < 4; ++ks) {
            const int t = lane >> 3;
            const uint32_t colB = (uint32_t)(ks * 32 + (t & 1) * 16);
#pragma unroll
            for (int ng = 0; ng < 8; ++ng) {
                const int rK = ng * 16 + ((t >> 1) * 8) + (lane & 7);
                const uint32_t off = swz((uint32_t)rK * 128 + colB);
                uint32_t kh[4], kl[4];
                ldsm4(kh[0], kh[1], kh[2], kh[3], KHI + off);
                ldsm4(kl[0], kl[1], kl[2], kl[3], KLO + off);
                mma16816(sacc[2*ng],   qh[ks], kh);
                mma16816(sacc[2*ng],   qh[ks], kl);
                mma16816(sacc[2*ng],   ql[ks], kh);
                mma16816(sacc[2*ng+1], qh[ks], kh + 2);
                mma16816(sacc[2*ng+1], qh[ks], kl + 2);
                mma16816(sacc[2*ng+1], ql[ks], kh + 2);
            }
        }

        if (kt == qt) {
#pragma unroll
            for (int nf = 0; nf < 16; ++nf) {
                const int col = k0 + nf * 8 + tig * 2;
                sacc[nf][0] = (col     > qrow0) ? -1e30f : sacc[nf][0] * SC;
                sacc[nf][1] = (col + 1 > qrow0) ? -1e30f : sacc[nf][1] * SC;
                sacc[nf][2] = (col     > qrow1) ? -1e30f : sacc[nf][2] * SC;
                sacc[nf][3] = (col + 1 > qrow1) ? -1e30f : sacc[nf][3] * SC;
            }
        } else {
#pragma unroll
            for (int nf = 0; nf < 16; ++nf)
#pragma unroll
                for (int j = 0; j < 4; ++j) sacc[nf][j] *= SC;
        }

        float rm0 = -1e30f, rm1 = -1e30f;
#pragma unroll
        for (int nf = 0; nf < 16; ++nf) {
            rm0 = fmaxf(rm0, fmaxf(sacc[nf][0], sacc[nf][1]));
            rm1 = fmaxf(rm1, fmaxf(sacc[nf][2], sacc[nf][3]));
        }
        rm0 = fmaxf(rm0, __shfl_xor_sync(0xffffffffu, rm0, 1));
        rm0 = fmaxf(rm0, __shfl_xor_sync(0xffffffffu, rm0, 2));
        rm1 = fmaxf(rm1, __shfl_xor_sync(0xffffffffu, rm1, 1));
        rm1 = fmaxf(rm1, __shfl_xor_sync(0xffffffffu, rm1, 2));
        const float mn0 = fmaxf(m0v, rm0);
        const float mn1 = fmaxf(m1v, rm1);
        const float al0 = ex2(m0v - mn0);
        const float al1 = ex2(m1v - mn1);
        float rs0 = 0.f, rs1 = 0.f;
#pragma unroll
        for (int nf = 0; nf < 16; ++nf) {
            sacc[nf][0] = ex2(sacc[nf][0] - mn0);
            sacc[nf][1] = ex2(sacc[nf][1] - mn0);
            sacc[nf][2] = ex2(sacc[nf][2] - mn1);
            sacc[nf][3] = ex2(sacc[nf][3] - mn1);
            rs0 += sacc[nf][0] + sacc[nf][1];
            rs1 += sacc[nf][2] + sacc[nf][3];
        }
        rs0 += __shfl_xor_sync(0xffffffffu, rs0, 1);
        rs0 += __shfl_xor_sync(0xffffffffu, rs0, 2);
        rs1 += __shfl_xor_sync(0xffffffffu, rs1, 1);
        rs1 += __shfl_xor_sync(0xffffffffu, rs1, 2);
        l0v = l0v * al0 + rs0;  m0v = mn0;
        l1v = l1v * al1 + rs1;  m1v = mn1;
#pragma unroll
        for (int nf = 0; nf < 8; ++nf) {
            o[nf][0] *= al0; o[nf][1] *= al0;
            o[nf][2] *= al1; o[nf][3] *= al1;
        }

        // ---- P·V with P packed per-ks2 (no staging arrays) ----
        const int t = lane >> 3;
#pragma unroll
        for (int ks2 = 0; ks2 < 8; ++ks2) {
            uint32_t pA[4], pL[4];
#pragma unroll
            for (int q = 0; q < 4; ++q) {
                const int nf = 2 * ks2 + (q >> 1);
                const int e  = (q & 1) * 2;
                const float x = sacc[nf][e], y = sacc[nf][e + 1];
                const __nv_bfloat16 hx = __float2bfloat16(x);
                const __nv_bfloat16 hy = __float2bfloat16(y);
                pA[q] = packbf(hx, hy);
                pL[q] = packbf(__float2bfloat16(x - __bfloat162float(hx)),
                               __float2bfloat16(y - __bfloat162float(hy)));
            }
            const int kq = ks2 * 16 + (t & 1) * 8 + (lane & 7);
#pragma unroll
            for (int og = 0; og < 4; ++og) {
                const uint32_t off = swz((uint32_t)kq * 128 + og * 32 + (t >> 1) * 16);
                uint32_t vh[4], vl[4];
                ldsm4t(vh[0], vh[1], vh[2], vh[3], VHI + off);
                ldsm4t(vl[0], vl[1], vl[2], vl[3], VLO + off);
                mma16816(o[2*og],   pA, vh);
                mma16816(o[2*og],   pA, vl);
                mma16816(o[2*og],   pL, vh);
                mma16816(o[2*og+1], pA, vh + 2);
                mma16816(o[2*og+1], pA, vl + 2);
                mma16816(o[2*og+1], pL, vh + 2);
            }
        }
        __syncthreads();
    }

    const float inv0 = 1.f / l0v;
    const float inv1 = 1.f / l1v;
#pragma unroll
    for (int nf = 0; nf < 8; ++nf) {
        const int dh = nf * 8 + tig * 2;
        {
            const float x = o[nf][0] * inv0, y = o[nf][1] * inv0;
            const __nv_bfloat16 hx = __float2bfloat16(x), hy = __float2bfloat16(y);
            *(__nv_bfloat162*)(g_chi + (size_t)(b * S_ + qrow0) * D_ + h * DH_ + dh) =
                __halves2bfloat162(hx, hy);
            *(__nv_bfloat162*)(g_clo + (size_t)(b * S_ + qrow0) * D_ + h * DH_ + dh) =
                __halves2bfloat162(__float2bfloat16(x - __bfloat162float(hx)),
                                   __float2bfloat16(y - __bfloat162float(hy)));
        }
        {
            const float x = o[nf][2] * inv1, y = o[nf][3] * inv1;
            const __nv_bfloat16 hx = __float2bfloat16(x), hy = __float2bfloat16(y);
            *(__nv_bfloat162*)(g_chi + (size_t)(b * S_ + qrow1) * D_ + h * DH_ + dh) =
                __halves2bfloat162(hx, hy);
            *(__nv_bfloat162*)(g_clo + (size_t)(b * S_ + qrow1) * D_ + h * DH_ + dh) =
                __halves2bfloat162(__float2bfloat16(x - __bfloat162float(hx)),
                                   __float2bfloat16(y - __bfloat162float(hy)));
        }
    }
}

// ---------------------------------------------------------------------------
extern "C" void kernel_launch(void* const* d_in, const int* in_sizes, int n_in,
                              void* d_out, int out_size)
{
    const float* x  = (const float*)d_in[0];
    const float* Wq = (const float*)d_in[1];
    const float* Wk = (const float*)d_in[2];
    const float* Wv = (const float*)d_in[3];
    const float* Wo = (const float*)d_in[4];
    const float* bo = (const float*)d_in[5];
    float* out = (float*)d_out;

    __nv_bfloat16 *xhi, *xlo, *whi, *wlo, *chi, *clo;
    cudaGetSymbolAddress((void**)&xhi, g_xhi);
    cudaGetSymbolAddress((void**)&xlo, g_xlo);
    cudaGetSymbolAddress((void**)&whi, g_whi);
    cudaGetSymbolAddress((void**)&wlo, g_wlo);
    cudaGetSymbolAddress((void**)&chi, g_chi);
    cudaGetSymbolAddress((void**)&clo, g_clo);

    cudaFuncSetAttribute(tgemm<0>, cudaFuncAttributeMaxDynamicSharedMemorySize, TG_SMEM);
    cudaFuncSetAttribute(tgemm<1>, cudaFuncAttributeMaxDynamicSharedMemorySize, TG_SMEM);
    cudaFuncSetAttribute(attn_tc,  cudaFuncAttributeMaxDynamicSharedMemorySize, ATT_SMEM);

    const int nx = M_ * D_;     // 4M
    const int nw = D_ * D_;     // 1M
    split_bf16<<<nx/1024, 256>>>(x, xhi, xlo);
    split4_bf16<<<dim3(nw/1024, 4), 256>>>(Wq, Wk, Wv, Wo, whi, wlo);

    // fused QKV projection: N = 3072 against stacked Wq|Wk|Wv
    tgemm<0><<<dim3(3*D_/128, M_/128), 256, TG_SMEM>>>(xhi, xlo, whi, wlo,
                                                       nullptr, nullptr);

    attn_tc<<<dim3(S_/128, B_*H_), 256, ATT_SMEM>>>();

    tgemm<1><<<dim3(D_/128, M_/128), 256, TG_SMEM>>>(chi, clo,
                                                     whi + 3*(size_t)nw, wlo + 3*(size_t)nw,
                                                     bo, out);
}

// round 7
// speedup vs baseline: 1.0292x; 1.0292x over previous
#include <cuda_runtime.h>
#include <cuda_bf16.h>
#include <cstdint>

// Problem constants
#define B_  2
#define S_  2048
#define D_  1024
#define H_  16
#define DH_ 64
#define M_  (B_*S_)          // 4096 rows total

// ---------------------------------------------------------------------------
// Scratch (allocation-free __device__ globals), all bf16 hi/lo pairs
// ---------------------------------------------------------------------------
__device__ __nv_bfloat16 g_qhi[(size_t)B_*H_*S_*DH_];   // head-major
__device__ __nv_bfloat16 g_qlo[(size_t)B_*H_*S_*DH_];
__device__ __nv_bfloat16 g_khi[(size_t)B_*H_*S_*DH_];
__device__ __nv_bfloat16 g_klo[(size_t)B_*H_*S_*DH_];
__device__ __nv_bfloat16 g_vhi[(size_t)B_*H_*S_*DH_];
__device__ __nv_bfloat16 g_vlo[(size_t)B_*H_*S_*DH_];
__device__ __nv_bfloat16 g_chi[(size_t)M_*D_];          // ctx row-major
__device__ __nv_bfloat16 g_clo[(size_t)M_*D_];
__device__ __nv_bfloat16 g_xhi[(size_t)M_*D_];
__device__ __nv_bfloat16 g_xlo[(size_t)M_*D_];
__device__ __nv_bfloat16 g_whi[(size_t)4*D_*D_];
__device__ __nv_bfloat16 g_wlo[(size_t)4*D_*D_];

// ---------------------------------------------------------------------------
// PTX helpers (plain sm_80-class PTX: valid under compute_103)
// ---------------------------------------------------------------------------
__device__ __forceinline__ uint32_t smem_u32(const void* p) {
    uint32_t a;
    asm("{ .reg .u64 t; cvta.to.shared.u64 t, %1; cvt.u32.u64 %0, t; }"
        : "=r"(a) : "l"(p));
    return a;
}
__device__ __forceinline__ void cp16(uint32_t dst, const void* src) {
    asm volatile("cp.async.cg.shared.global [%0], [%1], 16;"
                 :: "r"(dst), "l"(src) : "memory");
}
__device__ __forceinline__ void cp_commit() {
    asm volatile("cp.async.commit_group;" ::: "memory");
}
__device__ __forceinline__ void cp_wait0() {
    asm volatile("cp.async.wait_group 0;" ::: "memory");
}
__device__ __forceinline__ void cp_wait1() {
    asm volatile("cp.async.wait_group 1;" ::: "memory");
}
__device__ __forceinline__ void cp_wait2() {
    asm volatile("cp.async.wait_group 2;" ::: "memory");
}
__device__ __forceinline__ void ldsm4(uint32_t& r0, uint32_t& r1, uint32_t& r2,
                                      uint32_t& r3, uint32_t addr) {
    asm volatile("ldmatrix.sync.aligned.m8n8.x4.shared.b16 {%0,%1,%2,%3}, [%4];"
                 : "=r"(r0), "=r"(r1), "=r"(r2), "=r"(r3) : "r"(addr));
}
__device__ __forceinline__ void ldsm4t(uint32_t& r0, uint32_t& r1, uint32_t& r2,
                                       uint32_t& r3, uint32_t addr) {
    asm volatile("ldmatrix.sync.aligned.m8n8.x4.trans.shared.b16 {%0,%1,%2,%3}, [%4];"
                 : "=r"(r0), "=r"(r1), "=r"(r2), "=r"(r3) : "r"(addr));
}
__device__ __forceinline__ void mma16816(float* c, const uint32_t* a, const uint32_t* b) {
    asm volatile(
        "mma.sync.aligned.m16n8k16.row.col.f32.bf16.bf16.f32 "
        "{%0,%1,%2,%3}, {%4,%5,%6,%7}, {%8,%9}, {%0,%1,%2,%3};"
        : "+f"(c[0]), "+f"(c[1]), "+f"(c[2]), "+f"(c[3])
        : "r"(a[0]), "r"(a[1]), "r"(a[2]), "r"(a[3]), "r"(b[0]), "r"(b[1]));
}
__device__ __forceinline__ float ex2(float x) {
    float y; asm("ex2.approx.ftz.f32 %0, %1;" : "=f"(y) : "f"(x)); return y;
}
// Swizzle<3,4,3>: XOR 16B-column bits [6:4] with row bits [9:7]
__device__ __forceinline__ uint32_t swz(uint32_t off) {
    return off ^ ((off >> 3) & 0x70);
}
__device__ __forceinline__ uint32_t packbf(__nv_bfloat16 a, __nv_bfloat16 b) {
    __nv_bfloat162 h = __halves2bfloat162(a, b);
    return *(uint32_t*)&h;
}

// ---------------------------------------------------------------------------
// fp32 -> bf16 hi/lo splits
// ---------------------------------------------------------------------------
__global__ void split_bf16(const float* __restrict__ src,
                           __nv_bfloat16* __restrict__ hi,
                           __nv_bfloat16* __restrict__ lo)
{
    const size_t i = ((size_t)blockIdx.x * blockDim.x + threadIdx.x) * 4;
    float4 v = *(const float4*)(src + i);
    __nv_bfloat16 h0 = __float2bfloat16(v.x), h1 = __float2bfloat16(v.y);
    __nv_bfloat16 h2 = __float2bfloat16(v.z), h3 = __float2bfloat16(v.w);
    *(__nv_bfloat162*)(hi + i)     = __halves2bfloat162(h0, h1);
    *(__nv_bfloat162*)(hi + i + 2) = __halves2bfloat162(h2, h3);
    *(__nv_bfloat162*)(lo + i) = __halves2bfloat162(
        __float2bfloat16(v.x - __bfloat162float(h0)),
        __float2bfloat16(v.y - __bfloat162float(h1)));
    *(__nv_bfloat162*)(lo + i + 2) = __halves2bfloat162(
        __float2bfloat16(v.z - __bfloat162float(h2)),
        __float2bfloat16(v.w - __bfloat162float(h3)));
}

__global__ void split4_bf16(const float* __restrict__ a, const float* __restrict__ b,
                            const float* __restrict__ c, const float* __restrict__ d,
                            __nv_bfloat16* __restrict__ hi,
                            __nv_bfloat16* __restrict__ lo)
{
    const int w = blockIdx.y;
    const float* src = (w == 0) ? a : (w == 1) ? b : (w == 2) ? c : d;
    const size_t base = (size_t)w * D_ * D_;
    const size_t i = ((size_t)blockIdx.x * blockDim.x + threadIdx.x) * 4;
    float4 v = *(const float4*)(src + i);
    __nv_bfloat16 h0 = __float2bfloat16(v.x), h1 = __float2bfloat16(v.y);
    __nv_bfloat16 h2 = __float2bfloat16(v.z), h3 = __float2bfloat16(v.w);
    *(__nv_bfloat162*)(hi + base + i)     = __halves2bfloat162(h0, h1);
    *(__nv_bfloat162*)(hi + base + i + 2) = __halves2bfloat162(h2, h3);
    *(__nv_bfloat162*)(lo + base + i) = __halves2bfloat162(
        __float2bfloat16(v.x - __bfloat162float(h0)),
        __float2bfloat16(v.y - __bfloat162float(h1)));
    *(__nv_bfloat162*)(lo + base + i + 2) = __halves2bfloat162(
        __float2bfloat16(v.z - __bfloat162float(h2)),
        __float2bfloat16(v.w - __bfloat162float(h3)));
}

// ---------------------------------------------------------------------------
// HMMA bf16x3 GEMM (R5 config: 128x256 CTA tile, BK=64, 2-stage, 256 thr)
// MODE 0: fused-QKV store to g_q/g_k/g_v (bf16 hi/lo, head-major); N=3072
// MODE 1: store fp32 row-major + bias
// ---------------------------------------------------------------------------
#define A_TB   16384                 // 128 x 128B
#define B_TB   32768                 // 256 x 128B
#define STAGE_B (2*A_TB + 2*B_TB)    // 96 KB
#define TG_SMEM (2*STAGE_B)          // 192 KB
#define NCHUNK  (D_/64)              // 16

template<int MODE>
__global__ __launch_bounds__(256, 1) void tgemm(const __nv_bfloat16* __restrict__ Ahi,
                                                const __nv_bfloat16* __restrict__ Alo,
                                                const __nv_bfloat16* __restrict__ Bhi,
                                                const __nv_bfloat16* __restrict__ Blo,
                                                const float* __restrict__ bias,
                                                float* __restrict__ outf)
{
    extern __shared__ char smem[];
    const uint32_t sb = smem_u32(smem);
    const int tid  = threadIdx.x;
    const int wid  = tid >> 5;
    const int lane = tid & 31;
    const int wm   = wid >> 2;
    const int wn   = wid & 3;
    const int m0   = blockIdx.y * 128;
    const int n0   = blockIdx.x * 256;

    const char* gA[2] = { (const char*)(Ahi + (size_t)m0 * D_),
                          (const char*)(Alo + (size_t)m0 * D_) };
    const char* gB[2] = { (const char*)(Bhi + (size_t)n0 * D_),
                          (const char*)(Blo + (size_t)n0 * D_) };

    auto load_stage = [&](int chunk, uint32_t stage) {
        const uint32_t koff = (uint32_t)chunk * 128;
#pragma unroll
        for (int t = 0; t < 2; ++t) {
            const char* base = gA[t] + koff;
            const uint32_t dstt = stage + t * A_TB;
#pragma unroll
            for (int it = 0; it < 4; ++it) {
                const int c = tid + it * 256;
                const int r = c >> 3, c16 = c & 7;
                cp16(dstt + swz((uint32_t)(r * 128 + c16 * 16)),
                     base + (size_t)r * (D_ * 2) + c16 * 16);
            }
        }
#pragma unroll
        for (int t = 0; t < 2; ++t) {
            const char* base = gB[t] + koff;
            const uint32_t dstt = stage + 2 * A_TB + t * B_TB;
#pragma unroll
            for (int it = 0; it < 8; ++it) {
                const int c = tid + it * 256;
                const int r = c >> 3, c16 = c & 7;
                cp16(dstt + swz((uint32_t)(r * 128 + c16 * 16)),
                     base + (size_t)r * (D_ * 2) + c16 * 16);
            }
        }
        cp_commit();
    };

    float acc[4][8][4];
#pragma unroll
    for (int i = 0; i < 4; i++)
#pragma unroll
        for (int j = 0; j < 8; j++)
#pragma unroll
            for (int q = 0; q < 4; q++) acc[i][j][q] = 0.f;

    load_stage(0, sb);

    for (int c = 0; c < NCHUNK; ++c) {
        cp_wait0();
        __syncthreads();
        const uint32_t cur = sb + (c & 1) * STAGE_B;
        if (c + 1 < NCHUNK) load_stage(c + 1, sb + ((c + 1) & 1) * STAGE_B);

        const uint32_t aHi = cur;
        const uint32_t aLo = cur + A_TB;
        const uint32_t bHi = cur + 2 * A_TB;
        const uint32_t bLo = cur + 2 * A_TB + B_TB;

#pragma unroll
        for (int ks = 0; ks < 4; ++ks) {
            uint32_t ahi[4][4], alo[4][4];
            {
                const int rA = wm * 64 + (lane & 15);
                const uint32_t colA = (uint32_t)(ks * 32 + (lane >> 4) * 16);
#pragma unroll
                for (int mf = 0; mf < 4; ++mf) {
                    const uint32_t off = swz((uint32_t)(rA + mf * 16) * 128 + colA);
                    ldsm4(ahi[mf][0], ahi[mf][1], ahi[mf][2], ahi[mf][3], aHi + off);
                    ldsm4(alo[mf][0], alo[mf][1], alo[mf][2], alo[mf][3], aLo + off);
                }
            }
            const int t = lane >> 3;
            const uint32_t colB = (uint32_t)(ks * 32 + (t & 1) * 16);
#pragma unroll
            for (int ng = 0; ng < 4; ++ng) {
                const int rB = wn * 64 + ng * 16 + ((t >> 1) * 8) + (lane & 7);
                const uint32_t off = swz((uint32_t)rB * 128 + colB);
                uint32_t bh[4], bl[4];
                ldsm4(bh[0], bh[1], bh[2], bh[3], bHi + off);
                ldsm4(bl[0], bl[1], bl[2], bl[3], bLo + off);
#pragma unroll
                for (int mf = 0; mf < 4; ++mf) {
                    mma16816(acc[mf][2*ng],   ahi[mf], bh);
                    mma16816(acc[mf][2*ng],   ahi[mf], bl);
                    mma16816(acc[mf][2*ng],   alo[mf], bh);
                    mma16816(acc[mf][2*ng+1], ahi[mf], bh + 2);
                    mma16816(acc[mf][2*ng+1], ahi[mf], bl + 2);
                    mma16816(acc[mf][2*ng+1], alo[mf], bh + 2);
                }
            }
        }
        __syncthreads();
    }

    const int gid = lane >> 2, tig = lane & 3;
    __nv_bfloat16 *dhi = nullptr, *dlo = nullptr;
    if (MODE == 0) {
        const int sel = n0 >> 10;
        dhi = (sel == 0) ? g_qhi : (sel == 1) ? g_khi : g_vhi;
        dlo = (sel == 0) ? g_qlo : (sel == 1) ? g_klo : g_vlo;
    }
#pragma unroll
    for (int mf = 0; mf < 4; ++mf)
#pragma unroll
        for (int nf = 0; nf < 8; ++nf)
#pragma unroll
            for (int half = 0; half < 2; ++half) {
                const int m = m0 + wm * 64 + mf * 16 + gid + half * 8;
                const int n = n0 + wn * 64 + nf * 8 + tig * 2;
                float2 v = make_float2(acc[mf][nf][half*2], acc[mf][nf][half*2+1]);
                if (MODE == 1) {
                    v.x += bias[n]; v.y += bias[n+1];
                    *(float2*)(outf + (size_t)m * D_ + n) = v;
                } else {
                    const int nl = n & (D_ - 1);
                    const int b  = m >> 11;
                    const int s  = m & (S_ - 1);
                    const int h  = nl >> 6;
                    const int dh = nl & (DH_ - 1);
                    const size_t idx = ((size_t)(b * H_ + h) * S_ + s) * DH_ + dh;
                    __nv_bfloat16 h0 = __float2bfloat16(v.x);
                    __nv_bfloat16 h1 = __float2bfloat16(v.y);
                    *(__nv_bfloat162*)(dhi + idx) = __halves2bfloat162(h0, h1);
                    *(__nv_bfloat162*)(dlo + idx) = __halves2bfloat162(
                        __float2bfloat16(v.x - __bfloat162float(h0)),
                        __float2bfloat16(v.y - __bfloat162float(h1)));
                }
            }
}

// ---------------------------------------------------------------------------
// HMMA flash attention v2: BLOCK_M=128, BLOCK_N=64 (halved score registers,
// no spills), 3-stage cp.async KV pipeline, 256 threads.
// ---------------------------------------------------------------------------
#define SM_Q     0                      // 32 KB (qhi 16K + qlo 16K)
#define SM_KV    32768
#define KV_STG_B 32768                  // K hi/lo + V hi/lo, 64 keys each 8KB
#define ATT_SMEM (32768 + 3*KV_STG_B)   // 131072 B

__global__ __launch_bounds__(256, 1) void attn_tc()
{
    extern __shared__ char smem[];
    const uint32_t sb = smem_u32(smem);
    const int tid  = threadIdx.x;
    const int w    = tid >> 5;
    const int lane = tid & 31;
    const int gid  = lane >> 2;
    const int tig  = lane & 3;
    const int qt   = (int)(gridDim.x - 1 - blockIdx.x);   // heavy tiles first
    const int bh   = blockIdx.y;
    const int q0   = qt * 128;
    const int b    = bh >> 4;
    const int h    = bh & (H_ - 1);
    const int jmax = 2 * qt + 1;        // 64-key tiles: keys [0, q0+128)

    const size_t headoff = (size_t)bh * S_ * DH_;

    // stage-j KV load: 64 keys from j*64
    auto load_kv = [&](int j, int stg) {
        const uint32_t base = sb + SM_KV + (uint32_t)stg * KV_STG_B;
        const size_t g = headoff + (size_t)j * 64 * DH_;
        const char* srcs[4] = { (const char*)(g_khi + g), (const char*)(g_klo + g),
                                (const char*)(g_vhi + g), (const char*)(g_vlo + g) };
#pragma unroll
        for (int t = 0; t < 4; ++t) {
#pragma unroll
            for (int it = 0; it < 2; ++it) {
                const int c = tid + it * 256;       // 0..511
                const int r = c >> 3, c16 = c & 7;
                cp16(base + t * 8192 + swz((uint32_t)(r * 128 + c16 * 16)),
                     srcs[t] + r * 128 + c16 * 16);
            }
        }
        cp_commit();
    };

    // group 0: Q tile + kv(0)
    {
        const char* qh = (const char*)(g_qhi + headoff + (size_t)q0 * DH_);
        const char* ql = (const char*)(g_qlo + headoff + (size_t)q0 * DH_);
#pragma unroll
        for (int it = 0; it < 4; ++it) {
            const int c = tid + it * 256;
            const int r = c >> 3, c16 = c & 7;
            const uint32_t off = swz((uint32_t)(r * 128 + c16 * 16));
            cp16(sb + SM_Q + off,         qh + r * 128 + c16 * 16);
            cp16(sb + SM_Q + 16384 + off, ql + r * 128 + c16 * 16);
        }
    }
    load_kv(0, 0);                       // commits group (Q + kv0)
    if (1 <= jmax) load_kv(1, 1);        // group kv1

    float m0v = -1e30f, m1v = -1e30f, l0v = 0.f, l1v = 0.f;
    float o[8][4];
#pragma unroll
    for (int i = 0; i < 8; i++)
#pragma unroll
        for (int j = 0; j < 4; j++) o[i][j] = 0.f;

    uint32_t qh[4][4], ql[4][4];
    const int qrow0 = q0 + w * 16 + gid;
    const int qrow1 = qrow0 + 8;
    const float SC = 0.18033688011112042f;   // (1/sqrt(64)) * log2(e)
    const int t8 = lane >> 3;

    for (int j = 0; j <= jmax; ++j) {
        // prefetch j+2, then wait for tile j
        if (j + 2 <= jmax) {
            int ns = j + 2; ns = ns - (ns / 3) * 3;   // (j+2) % 3
            load_kv(j + 2, ns);
            cp_wait2();
        } else if (j + 1 <= jmax) {
            cp_wait1();
        } else {
            cp_wait0();
        }
        __syncthreads();

        if (j == 0) {   // Q fragments once
            const int rA = w * 16 + (lane & 15);
            const uint32_t colA = (uint32_t)((lane >> 4) * 16);
#pragma unroll
            for (int ks = 0; ks < 4; ++ks) {
                const uint32_t off = swz((uint32_t)rA * 128 + ks * 32 + colA);
                ldsm4(qh[ks][0], qh[ks][1], qh[ks][2], qh[ks][3], sb + SM_Q + off);
                ldsm4(ql[ks][0], ql[ks][1], ql[ks][2], ql[ks][3], sb + SM_Q + 16384 + off);
            }
        }

        int stg = j - (j / 3) * 3;
        const uint32_t cur = sb + SM_KV + (uint32_t)stg * KV_STG_B;
        const uint32_t KHI = cur, KLO = cur + 8192, VHI = cur + 16384, VLO = cur + 24576;
        const int k0 = j * 64;

        // ---- S = Q @ K^T  (8 n8-frags per warp, 64 keys) ----
        float sacc[8][4];
#pragma unroll
        for (int i = 0; i < 8; i++)
#pragma unroll
            for (int q = 0; q < 4; q++) sacc[i][q] = 0.f;

#pragma unroll
        for (int ks = 0; ks < 4; ++ks) {
            const uint32_t colB = (uint32_t)(ks * 32 + (t8 & 1) * 16);
#pragma unroll
            for (int ng = 0; ng < 4; ++ng) {
                const int rK = ng * 16 + ((t8 >> 1) * 8) + (lane & 7);
                const uint32_t off = swz((uint32_t)rK * 128 + colB);
                uint32_t kh[4], kl[4];
                ldsm4(kh[0], kh[1], kh[2], kh[3], KHI + off);
                ldsm4(kl[0], kl[1], kl[2], kl[3], KLO + off);
                mma16816(sacc[2*ng],   qh[ks], kh);
                mma16816(sacc[2*ng],   qh[ks], kl);
                mma16816(sacc[2*ng],   ql[ks], kh);
                mma16816(sacc[2*ng+1], qh[ks], kh + 2);
                mma16816(sacc[2*ng+1], qh[ks], kl + 2);
                mma16816(sacc[2*ng+1], ql[ks], kh + 2);
            }
        }

        // ---- scale (+ causal mask on the last two tiles) ----
        if (j >= 2 * qt) {
#pragma unroll
            for (int nf = 0; nf < 8; ++nf) {
                const int col = k0 + nf * 8 + tig * 2;
                sacc[nf][0] = (col     > qrow0) ? -1e30f : sacc[nf][0] * SC;
                sacc[nf][1] = (col + 1 > qrow0) ? -1e30f : sacc[nf][1] * SC;
                sacc[nf][2] = (col     > qrow1) ? -1e30f : sacc[nf][2] * SC;
                sacc[nf][3] = (col + 1 > qrow1) ? -1e30f : sacc[nf][3] * SC;
            }
        } else {
#pragma unroll
            for (int nf = 0; nf < 8; ++nf)
#pragma unroll
                for (int q = 0; q < 4; ++q) sacc[nf][q] *= SC;
        }

        // ---- online softmax (rows gid / gid+8; reduce across tig quad) ----
        float rm0 = -1e30f, rm1 = -1e30f;
#pragma unroll
        for (int nf = 0; nf < 8; ++nf) {
            rm0 = fmaxf(rm0, fmaxf(sacc[nf][0], sacc[nf][1]));
            rm1 = fmaxf(rm1, fmaxf(sacc[nf][2], sacc[nf][3]));
        }
        rm0 = fmaxf(rm0, __shfl_xor_sync(0xffffffffu, rm0, 1));
        rm0 = fmaxf(rm0, __shfl_xor_sync(0xffffffffu, rm0, 2));
        rm1 = fmaxf(rm1, __shfl_xor_sync(0xffffffffu, rm1, 1));
        rm1 = fmaxf(rm1, __shfl_xor_sync(0xffffffffu, rm1, 2));
        const float mn0 = fmaxf(m0v, rm0);
        const float mn1 = fmaxf(m1v, rm1);
        const float al0 = ex2(m0v - mn0);
        const float al1 = ex2(m1v - mn1);
        float rs0 = 0.f, rs1 = 0.f;
#pragma unroll
        for (int nf = 0; nf < 8; ++nf) {
            sacc[nf][0] = ex2(sacc[nf][0] - mn0);
            sacc[nf][1] = ex2(sacc[nf][1] - mn0);
            sacc[nf][2] = ex2(sacc[nf][2] - mn1);
            sacc[nf][3] = ex2(sacc[nf][3] - mn1);
            rs0 += sacc[nf][0] + sacc[nf][1];
            rs1 += sacc[nf][2] + sacc[nf][3];
        }
        rs0 += __shfl_xor_sync(0xffffffffu, rs0, 1);
        rs0 += __shfl_xor_sync(0xffffffffu, rs0, 2);
        rs1 += __shfl_xor_sync(0xffffffffu, rs1, 1);
        rs1 += __shfl_xor_sync(0xffffffffu, rs1, 2);
        l0v = l0v * al0 + rs0;  m0v = mn0;
        l1v = l1v * al1 + rs1;  m1v = mn1;
#pragma unroll
        for (int nf = 0; nf < 8; ++nf) {
            o[nf][0] *= al0; o[nf][1] *= al0;
            o[nf][2] *= al1; o[nf][3] *= al1;
        }

        // ---- O += P @ V  (P packed per 16-key chunk; V via trans-ldmatrix) ----
#pragma unroll
        for (int ks2 = 0; ks2 < 4; ++ks2) {
            uint32_t pA[4], pL[4];
#pragma unroll
            for (int q = 0; q < 4; ++q) {
                const int nf = 2 * ks2 + (q >> 1);
                const int e  = (q & 1) * 2;
                const float x = sacc[nf][e], y = sacc[nf][e + 1];
                const __nv_bfloat16 hx = __float2bfloat16(x);
                const __nv_bfloat16 hy = __float2bfloat16(y);
                pA[q] = packbf(hx, hy);
                pL[q] = packbf(__float2bfloat16(x - __bfloat162float(hx)),
                               __float2bfloat16(y - __bfloat162float(hy)));
            }
            const int kq = ks2 * 16 + (t8 & 1) * 8 + (lane & 7);
#pragma unroll
            for (int og = 0; og < 4; ++og) {
                const uint32_t off = swz((uint32_t)kq * 128 + og * 32 + (t8 >> 1) * 16);
                uint32_t vh[4], vl[4];
                ldsm4t(vh[0], vh[1], vh[2], vh[3], VHI + off);
                ldsm4t(vl[0], vl[1], vl[2], vl[3], VLO + off);
                mma16816(o[2*og],   pA, vh);
                mma16816(o[2*og],   pA, vl);
                mma16816(o[2*og],   pL, vh);
                mma16816(o[2*og+1], pA, vh + 2);
                mma16816(o[2*og+1], pA, vl + 2);
                mma16816(o[2*og+1], pL, vh + 2);
            }
        }
        __syncthreads();
    }

    // ---- normalize, write ctx as bf16 hi/lo row-major ----
    const float inv0 = 1.f / l0v;
    const float inv1 = 1.f / l1v;
#pragma unroll
    for (int nf = 0; nf < 8; ++nf) {
        const int dh = nf * 8 + tig * 2;
        {
            const float x = o[nf][0] * inv0, y = o[nf][1] * inv0;
            const __nv_bfloat16 hx = __float2bfloat16(x), hy = __float2bfloat16(y);
            *(__nv_bfloat162*)(g_chi + (size_t)(b * S_ + qrow0) * D_ + h * DH_ + dh) =
                __halves2bfloat162(hx, hy);
            *(__nv_bfloat162*)(g_clo + (size_t)(b * S_ + qrow0) * D_ + h * DH_ + dh) =
                __halves2bfloat162(__float2bfloat16(x - __bfloat162float(hx)),
                                   __float2bfloat16(y - __bfloat162float(hy)));
        }
        {
            const float x = o[nf][2] * inv1, y = o[nf][3] * inv1;
            const __nv_bfloat16 hx = __float2bfloat16(x), hy = __float2bfloat16(y);
            *(__nv_bfloat162*)(g_chi + (size_t)(b * S_ + qrow1) * D_ + h * DH_ + dh) =
                __halves2bfloat162(hx, hy);
            *(__nv_bfloat162*)(g_clo + (size_t)(b * S_ + qrow1) * D_ + h * DH_ + dh) =
                __halves2bfloat162(__float2bfloat16(x - __bfloat162float(hx)),
                                   __float2bfloat16(y - __bfloat162float(hy)));
        }
    }
}

// ---------------------------------------------------------------------------
extern "C" void kernel_launch(void* const* d_in, const int* in_sizes, int n_in,
                              void* d_out, int out_size)
{
    const float* x  = (const float*)d_in[0];
    const float* Wq = (const float*)d_in[1];
    const float* Wk = (const float*)d_in[2];
    const float* Wv = (const float*)d_in[3];
    const float* Wo = (const float*)d_in[4];
    const float* bo = (const float*)d_in[5];
    float* out = (float*)d_out;

    __nv_bfloat16 *xhi, *xlo, *whi, *wlo, *chi, *clo;
    cudaGetSymbolAddress((void**)&xhi, g_xhi);
    cudaGetSymbolAddress((void**)&xlo, g_xlo);
    cudaGetSymbolAddress((void**)&whi, g_whi);
    cudaGetSymbolAddress((void**)&wlo, g_wlo);
    cudaGetSymbolAddress((void**)&chi, g_chi);
    cudaGetSymbolAddress((void**)&clo, g_clo);

    cudaFuncSetAttribute(tgemm<0>, cudaFuncAttributeMaxDynamicSharedMemorySize, TG_SMEM);
    cudaFuncSetAttribute(tgemm<1>, cudaFuncAttributeMaxDynamicSharedMemorySize, TG_SMEM);
    cudaFuncSetAttribute(attn_tc,  cudaFuncAttributeMaxDynamicSharedMemorySize, ATT_SMEM);

    const int nx = M_ * D_;     // 4M
    const int nw = D_ * D_;     // 1M
    split_bf16<<<nx/1024, 256>>>(x, xhi, xlo);
    split4_bf16<<<dim3(nw/1024, 4), 256>>>(Wq, Wk, Wv, Wo, whi, wlo);

    // fused QKV projection: N = 3072 against stacked Wq|Wk|Wv
    tgemm<0><<<dim3(3*D_/256, M_/128), 256, TG_SMEM>>>(xhi, xlo, whi, wlo,
                                                       nullptr, nullptr);

    attn_tc<<<dim3(S_/128, B_*H_), 256, ATT_SMEM>>>();

    tgemm<1><<<dim3(D_/256, M_/128), 256, TG_SMEM>>>(chi, clo,
                                                     whi + 3*(size_t)nw, wlo + 3*(size_t)nw,
                                                     bo, out);
}

// round 8
// speedup vs baseline: 1.1776x; 1.1441x over previous
#include <cuda_runtime.h>
#include <cuda_bf16.h>
#include <cuda_fp16.h>
#include <cstdint>

// Problem constants
#define B_  2
#define S_  2048
#define D_  1024
#define H_  16
#define DH_ 64
#define M_  (B_*S_)          // 4096 rows total

// ---------------------------------------------------------------------------
// Scratch (allocation-free __device__ globals)
// Attention operands in fp16 (Q hi/lo, K single, V hi/lo); ctx + x/w in bf16.
// ---------------------------------------------------------------------------
__device__ __half g_qh[(size_t)B_*H_*S_*DH_];    // head-major
__device__ __half g_ql[(size_t)B_*H_*S_*DH_];
__device__ __half g_k1[(size_t)B_*H_*S_*DH_];
__device__ __half g_vh[(size_t)B_*H_*S_*DH_];
__device__ __half g_vl[(size_t)B_*H_*S_*DH_];
__device__ __nv_bfloat16 g_chi[(size_t)M_*D_];   // ctx row-major
__device__ __nv_bfloat16 g_clo[(size_t)M_*D_];
__device__ __nv_bfloat16 g_xhi[(size_t)M_*D_];
__device__ __nv_bfloat16 g_xlo[(size_t)M_*D_];
__device__ __nv_bfloat16 g_whi[(size_t)4*D_*D_];
__device__ __nv_bfloat16 g_wlo[(size_t)4*D_*D_];

// ---------------------------------------------------------------------------
// PTX helpers (plain sm_80-class PTX: valid under compute_103)
// ---------------------------------------------------------------------------
__device__ __forceinline__ uint32_t smem_u32(const void* p) {
    uint32_t a;
    asm("{ .reg .u64 t; cvta.to.shared.u64 t, %1; cvt.u32.u64 %0, t; }"
        : "=r"(a) : "l"(p));
    return a;
}
__device__ __forceinline__ void cp16(uint32_t dst, const void* src) {
    asm volatile("cp.async.cg.shared.global [%0], [%1], 16;"
                 :: "r"(dst), "l"(src) : "memory");
}
__device__ __forceinline__ void cp_commit() {
    asm volatile("cp.async.commit_group;" ::: "memory");
}
__device__ __forceinline__ void cp_wait0() {
    asm volatile("cp.async.wait_group 0;" ::: "memory");
}
__device__ __forceinline__ void cp_wait1() {
    asm volatile("cp.async.wait_group 1;" ::: "memory");
}
__device__ __forceinline__ void cp_wait2() {
    asm volatile("cp.async.wait_group 2;" ::: "memory");
}
__device__ __forceinline__ void ldsm4(uint32_t& r0, uint32_t& r1, uint32_t& r2,
                                      uint32_t& r3, uint32_t addr) {
    asm volatile("ldmatrix.sync.aligned.m8n8.x4.shared.b16 {%0,%1,%2,%3}, [%4];"
                 : "=r"(r0), "=r"(r1), "=r"(r2), "=r"(r3) : "r"(addr));
}
__device__ __forceinline__ void ldsm4t(uint32_t& r0, uint32_t& r1, uint32_t& r2,
                                       uint32_t& r3, uint32_t addr) {
    asm volatile("ldmatrix.sync.aligned.m8n8.x4.trans.shared.b16 {%0,%1,%2,%3}, [%4];"
                 : "=r"(r0), "=r"(r1), "=r"(r2), "=r"(r3) : "r"(addr));
}
// bf16 MMA (for projections)
__device__ __forceinline__ void mma16816(float* c, const uint32_t* a, const uint32_t* b) {
    asm volatile(
        "mma.sync.aligned.m16n8k16.row.col.f32.bf16.bf16.f32 "
        "{%0,%1,%2,%3}, {%4,%5,%6,%7}, {%8,%9}, {%0,%1,%2,%3};"
        : "+f"(c[0]), "+f"(c[1]), "+f"(c[2]), "+f"(c[3])
        : "r"(a[0]), "r"(a[1]), "r"(a[2]), "r"(a[3]), "r"(b[0]), "r"(b[1]));
}
// fp16 MMA (for attention)
__device__ __forceinline__ void mma16816h(float* c, const uint32_t* a, const uint32_t* b) {
    asm volatile(
        "mma.sync.aligned.m16n8k16.row.col.f32.f16.f16.f32 "
        "{%0,%1,%2,%3}, {%4,%5,%6,%7}, {%8,%9}, {%0,%1,%2,%3};"
        : "+f"(c[0]), "+f"(c[1]), "+f"(c[2]), "+f"(c[3])
        : "r"(a[0]), "r"(a[1]), "r"(a[2]), "r"(a[3]), "r"(b[0]), "r"(b[1]));
}
__device__ __forceinline__ float ex2(float x) {
    float y; asm("ex2.approx.ftz.f32 %0, %1;" : "=f"(y) : "f"(x)); return y;
}
// Swizzle<3,4,3>: XOR 16B-column bits [6:4] with row bits [9:7]
__device__ __forceinline__ uint32_t swz(uint32_t off) {
    return off ^ ((off >> 3) & 0x70);
}
__device__ __forceinline__ uint32_t packh(float x, float y) {
    __half2 h = __floats2half2_rn(x, y);
    return *(uint32_t*)&h;
}

// ---------------------------------------------------------------------------
// fp32 -> bf16 hi/lo splits
// ---------------------------------------------------------------------------
__global__ void split_bf16(const float* __restrict__ src,
                           __nv_bfloat16* __restrict__ hi,
                           __nv_bfloat16* __restrict__ lo)
{
    const size_t i = ((size_t)blockIdx.x * blockDim.x + threadIdx.x) * 4;
    float4 v = *(const float4*)(src + i);
    __nv_bfloat16 h0 = __float2bfloat16(v.x), h1 = __float2bfloat16(v.y);
    __nv_bfloat16 h2 = __float2bfloat16(v.z), h3 = __float2bfloat16(v.w);
    *(__nv_bfloat162*)(hi + i)     = __halves2bfloat162(h0, h1);
    *(__nv_bfloat162*)(hi + i + 2) = __halves2bfloat162(h2, h3);
    *(__nv_bfloat162*)(lo + i) = __halves2bfloat162(
        __float2bfloat16(v.x - __bfloat162float(h0)),
        __float2bfloat16(v.y - __bfloat162float(h1)));
    *(__nv_bfloat162*)(lo + i + 2) = __halves2bfloat162(
        __float2bfloat16(v.z - __bfloat162float(h2)),
        __float2bfloat16(v.w - __bfloat162float(h3)));
}

__global__ void split4_bf16(const float* __restrict__ a, const float* __restrict__ b,
                            const float* __restrict__ c, const float* __restrict__ d,
                            __nv_bfloat16* __restrict__ hi,
                            __nv_bfloat16* __restrict__ lo)
{
    const int w = blockIdx.y;
    const float* src = (w == 0) ? a : (w == 1) ? b : (w == 2) ? c : d;
    const size_t base = (size_t)w * D_ * D_;
    const size_t i = ((size_t)blockIdx.x * blockDim.x + threadIdx.x) * 4;
    float4 v = *(const float4*)(src + i);
    __nv_bfloat16 h0 = __float2bfloat16(v.x), h1 = __float2bfloat16(v.y);
    __nv_bfloat16 h2 = __float2bfloat16(v.z), h3 = __float2bfloat16(v.w);
    *(__nv_bfloat162*)(hi + base + i)     = __halves2bfloat162(h0, h1);
    *(__nv_bfloat162*)(hi + base + i + 2) = __halves2bfloat162(h2, h3);
    *(__nv_bfloat162*)(lo + base + i) = __halves2bfloat162(
        __float2bfloat16(v.x - __bfloat162float(h0)),
        __float2bfloat16(v.y - __bfloat162float(h1)));
    *(__nv_bfloat162*)(lo + base + i + 2) = __halves2bfloat162(
        __float2bfloat16(v.z - __bfloat162float(h2)),
        __float2bfloat16(v.w - __bfloat162float(h3)));
}

// ---------------------------------------------------------------------------
// HMMA bf16x3 GEMM (128x256 CTA tile, BK=64, 2-stage, 256 thr)
// MODE 0: fused-QKV, store fp16: Q hi/lo, K single, V hi/lo (head-major)
// MODE 1: store fp32 row-major + bias
// ---------------------------------------------------------------------------
#define A_TB   16384                 // 128 x 128B
#define B_TB   32768                 // 256 x 128B
#define STAGE_B (2*A_TB + 2*B_TB)    // 96 KB
#define TG_SMEM (2*STAGE_B)          // 192 KB
#define NCHUNK  (D_/64)              // 16

template<int MODE>
__global__ __launch_bounds__(256, 1) void tgemm(const __nv_bfloat16* __restrict__ Ahi,
                                                const __nv_bfloat16* __restrict__ Alo,
                                                const __nv_bfloat16* __restrict__ Bhi,
                                                const __nv_bfloat16* __restrict__ Blo,
                                                const float* __restrict__ bias,
                                                float* __restrict__ outf)
{
    extern __shared__ char smem[];
    const uint32_t sb = smem_u32(smem);
    const int tid  = threadIdx.x;
    const int wid  = tid >> 5;
    const int lane = tid & 31;
    const int wm   = wid >> 2;
    const int wn   = wid & 3;
    const int m0   = blockIdx.y * 128;
    const int n0   = blockIdx.x * 256;

    const char* gA[2] = { (const char*)(Ahi + (size_t)m0 * D_),
                          (const char*)(Alo + (size_t)m0 * D_) };
    const char* gB[2] = { (const char*)(Bhi + (size_t)n0 * D_),
                          (const char*)(Blo + (size_t)n0 * D_) };

    auto load_stage = [&](int chunk, uint32_t stage) {
        const uint32_t koff = (uint32_t)chunk * 128;
#pragma unroll
        for (int t = 0; t < 2; ++t) {
            const char* base = gA[t] + koff;
            const uint32_t dstt = stage + t * A_TB;
#pragma unroll
            for (int it = 0; it < 4; ++it) {
                const int c = tid + it * 256;
                const int r = c >> 3, c16 = c & 7;
                cp16(dstt + swz((uint32_t)(r * 128 + c16 * 16)),
                     base + (size_t)r * (D_ * 2) + c16 * 16);
            }
        }
#pragma unroll
        for (int t = 0; t < 2; ++t) {
            const char* base = gB[t] + koff;
            const uint32_t dstt = stage + 2 * A_TB + t * B_TB;
#pragma unroll
            for (int it = 0; it < 8; ++it) {
                const int c = tid + it * 256;
                const int r = c >> 3, c16 = c & 7;
                cp16(dstt + swz((uint32_t)(r * 128 + c16 * 16)),
                     base + (size_t)r * (D_ * 2) + c16 * 16);
            }
        }
        cp_commit();
    };

    float acc[4][8][4];
#pragma unroll
    for (int i = 0; i < 4; i++)
#pragma unroll
        for (int j = 0; j < 8; j++)
#pragma unroll
            for (int q = 0; q < 4; q++) acc[i][j][q] = 0.f;

    load_stage(0, sb);

    for (int c = 0; c < NCHUNK; ++c) {
        cp_wait0();
        __syncthreads();
        const uint32_t cur = sb + (c & 1) * STAGE_B;
        if (c + 1 < NCHUNK) load_stage(c + 1, sb + ((c + 1) & 1) * STAGE_B);

        const uint32_t aHi = cur;
        const uint32_t aLo = cur + A_TB;
        const uint32_t bHi = cur + 2 * A_TB;
        const uint32_t bLo = cur + 2 * A_TB + B_TB;

#pragma unroll
        for (int ks = 0; ks < 4; ++ks) {
            uint32_t ahi[4][4], alo[4][4];
            {
                const int rA = wm * 64 + (lane & 15);
                const uint32_t colA = (uint32_t)(ks * 32 + (lane >> 4) * 16);
#pragma unroll
                for (int mf = 0; mf < 4; ++mf) {
                    const uint32_t off = swz((uint32_t)(rA + mf * 16) * 128 + colA);
                    ldsm4(ahi[mf][0], ahi[mf][1], ahi[mf][2], ahi[mf][3], aHi + off);
                    ldsm4(alo[mf][0], alo[mf][1], alo[mf][2], alo[mf][3], aLo + off);
                }
            }
            const int t = lane >> 3;
            const uint32_t colB = (uint32_t)(ks * 32 + (t & 1) * 16);
#pragma unroll
            for (int ng = 0; ng < 4; ++ng) {
                const int rB = wn * 64 + ng * 16 + ((t >> 1) * 8) + (lane & 7);
                const uint32_t off = swz((uint32_t)rB * 128 + colB);
                uint32_t bh[4], bl[4];
                ldsm4(bh[0], bh[1], bh[2], bh[3], bHi + off);
                ldsm4(bl[0], bl[1], bl[2], bl[3], bLo + off);
#pragma unroll
                for (int mf = 0; mf < 4; ++mf) {
                    mma16816(acc[mf][2*ng],   ahi[mf], bh);
                    mma16816(acc[mf][2*ng],   ahi[mf], bl);
                    mma16816(acc[mf][2*ng],   alo[mf], bh);
                    mma16816(acc[mf][2*ng+1], ahi[mf], bh + 2);
                    mma16816(acc[mf][2*ng+1], ahi[mf], bl + 2);
                    mma16816(acc[mf][2*ng+1], alo[mf], bh + 2);
                }
            }
        }
        __syncthreads();
    }

    const int gid = lane >> 2, tig = lane & 3;
    __half *dhi = nullptr, *dlo = nullptr;
    if (MODE == 0) {
        const int sel = n0 >> 10;
        dhi = (sel == 0) ? g_qh : (sel == 1) ? g_k1 : g_vh;
        dlo = (sel == 0) ? g_ql : (sel == 1) ? nullptr : g_vl;
    }
#pragma unroll
    for (int mf = 0; mf < 4; ++mf)
#pragma unroll
        for (int nf = 0; nf < 8; ++nf)
#pragma unroll
            for (int half = 0; half < 2; ++half) {
                const int m = m0 + wm * 64 + mf * 16 + gid + half * 8;
                const int n = n0 + wn * 64 + nf * 8 + tig * 2;
                float2 v = make_float2(acc[mf][nf][half*2], acc[mf][nf][half*2+1]);
                if (MODE == 1) {
                    v.x += bias[n]; v.y += bias[n+1];
                    *(float2*)(outf + (size_t)m * D_ + n) = v;
                } else {
                    const int nl = n & (D_ - 1);
                    const int b  = m >> 11;
                    const int s  = m & (S_ - 1);
                    const int h  = nl >> 6;
                    const int dh = nl & (DH_ - 1);
                    const size_t idx = ((size_t)(b * H_ + h) * S_ + s) * DH_ + dh;
                    __half h0 = __float2half_rn(v.x);
                    __half h1 = __float2half_rn(v.y);
                    *(__half2*)(dhi + idx) = __halves2half2(h0, h1);
                    if (dlo)
                        *(__half2*)(dlo + idx) = __halves2half2(
                            __float2half_rn(v.x - __half2float(h0)),
                            __float2half_rn(v.y - __half2float(h1)));
                }
            }
}

// ---------------------------------------------------------------------------
// fp16 HMMA flash attention, causal. BLOCK_M=128, BLOCK_N=64, 256 threads.
// S = (Qhi+Qlo)·K      (2 MMA terms, K single fp16)
// O += Pf16·(Vhi+Vlo)  (2 MMA terms, P single fp16)
// 3-stage cp.async KV pipeline (24 KB/stage).
// ---------------------------------------------------------------------------
#define SM_Q     0                      // 32 KB (qh 16K + ql 16K)
#define SM_KV    32768
#define KV_STG_B 24576                  // K 8K + Vh 8K + Vl 8K
#define ATT_SMEM (32768 + 3*KV_STG_B)   // 106496 B

__global__ __launch_bounds__(256, 1) void attn_tc()
{
    extern __shared__ char smem[];
    const uint32_t sb = smem_u32(smem);
    const int tid  = threadIdx.x;
    const int w    = tid >> 5;
    const int lane = tid & 31;
    const int gid  = lane >> 2;
    const int tig  = lane & 3;
    const int qt   = (int)(gridDim.x - 1 - blockIdx.x);   // heavy tiles first
    const int bh   = blockIdx.y;
    const int q0   = qt * 128;
    const int b    = bh >> 4;
    const int h    = bh & (H_ - 1);
    const int jmax = 2 * qt + 1;        // 64-key tiles: keys [0, q0+128)

    const size_t headoff = (size_t)bh * S_ * DH_;

    auto load_kv = [&](int j, int stg) {
        const uint32_t base = sb + SM_KV + (uint32_t)stg * KV_STG_B;
        const size_t g = headoff + (size_t)j * 64 * DH_;
        const char* srcs[3] = { (const char*)(g_k1 + g),
                                (const char*)(g_vh + g),
                                (const char*)(g_vl + g) };
#pragma unroll
        for (int t = 0; t < 3; ++t) {
#pragma unroll
            for (int it = 0; it < 2; ++it) {
                const int c = tid + it * 256;       // 0..511
                const int r = c >> 3, c16 = c & 7;
                cp16(base + t * 8192 + swz((uint32_t)(r * 128 + c16 * 16)),
                     srcs[t] + r * 128 + c16 * 16);
            }
        }
        cp_commit();
    };

    // group 0: Q tile (hi/lo) + kv(0)
    {
        const char* qh = (const char*)(g_qh + headoff + (size_t)q0 * DH_);
        const char* ql = (const char*)(g_ql + headoff + (size_t)q0 * DH_);
#pragma unroll
        for (int it = 0; it < 4; ++it) {
            const int c = tid + it * 256;
            const int r = c >> 3, c16 = c & 7;
            const uint32_t off = swz((uint32_t)(r * 128 + c16 * 16));
            cp16(sb + SM_Q + off,         qh + r * 128 + c16 * 16);
            cp16(sb + SM_Q + 16384 + off, ql + r * 128 + c16 * 16);
        }
    }
    load_kv(0, 0);
    if (1 <= jmax) load_kv(1, 1);

    float m0v = -1e30f, m1v = -1e30f, l0v = 0.f, l1v = 0.f;
    float o[8][4];
#pragma unroll
    for (int i = 0; i < 8; i++)
#pragma unroll
        for (int j = 0; j < 4; j++) o[i][j] = 0.f;

    uint32_t qh[4][4], ql[4][4];
    const int qrow0 = q0 + w * 16 + gid;
    const int qrow1 = qrow0 + 8;
    const float SC = 0.18033688011112042f;   // (1/sqrt(64)) * log2(e)
    const int t8 = lane >> 3;

    for (int j = 0; j <= jmax; ++j) {
        if (j + 2 <= jmax) {
            int ns = j + 2; ns = ns - (ns / 3) * 3;
            load_kv(j + 2, ns);
            cp_wait2();
        } else if (j + 1 <= jmax) {
            cp_wait1();
        } else {
            cp_wait0();
        }
        __syncthreads();

        if (j == 0) {   // Q fragments once
            const int rA = w * 16 + (lane & 15);
            const uint32_t colA = (uint32_t)((lane >> 4) * 16);
#pragma unroll
            for (int ks = 0; ks < 4; ++ks) {
                const uint32_t off = swz((uint32_t)rA * 128 + ks * 32 + colA);
                ldsm4(qh[ks][0], qh[ks][1], qh[ks][2], qh[ks][3], sb + SM_Q + off);
                ldsm4(ql[ks][0], ql[ks][1], ql[ks][2], ql[ks][3], sb + SM_Q + 16384 + off);
            }
        }

        int stg = j - (j / 3) * 3;
        const uint32_t cur = sb + SM_KV + (uint32_t)stg * KV_STG_B;
        const uint32_t KK = cur, VHI = cur + 8192, VLO = cur + 16384;
        const int k0 = j * 64;

        // ---- S = Q @ K^T  (2 terms: qh·k + ql·k) ----
        float sacc[8][4];
#pragma unroll
        for (int i = 0; i < 8; i++)
#pragma unroll
            for (int q = 0; q < 4; q++) sacc[i][q] = 0.f;

#pragma unroll
        for (int ks = 0; ks < 4; ++ks) {
            const uint32_t colB = (uint32_t)(ks * 32 + (t8 & 1) * 16);
#pragma unroll
            for (int ng = 0; ng < 4; ++ng) {
                const int rK = ng * 16 + ((t8 >> 1) * 8) + (lane & 7);
                const uint32_t off = swz((uint32_t)rK * 128 + colB);
                uint32_t kk[4];
                ldsm4(kk[0], kk[1], kk[2], kk[3], KK + off);
                mma16816h(sacc[2*ng],   qh[ks], kk);
                mma16816h(sacc[2*ng],   ql[ks], kk);
                mma16816h(sacc[2*ng+1], qh[ks], kk + 2);
                mma16816h(sacc[2*ng+1], ql[ks], kk + 2);
            }
        }

        // ---- scale (+ causal mask on the last two tiles) ----
        if (j >= 2 * qt) {
#pragma unroll
            for (int nf = 0; nf < 8; ++nf) {
                const int col = k0 + nf * 8 + tig * 2;
                sacc[nf][0] = (col     > qrow0) ? -1e30f : sacc[nf][0] * SC;
                sacc[nf][1] = (col + 1 > qrow0) ? -1e30f : sacc[nf][1] * SC;
                sacc[nf][2] = (col     > qrow1) ? -1e30f : sacc[nf][2] * SC;
                sacc[nf][3] = (col + 1 > qrow1) ? -1e30f : sacc[nf][3] * SC;
            }
        } else {
#pragma unroll
            for (int nf = 0; nf < 8; ++nf)
#pragma unroll
                for (int q = 0; q < 4; ++q) sacc[nf][q] *= SC;
        }

        // ---- online softmax ----
        float rm0 = -1e30f, rm1 = -1e30f;
#pragma unroll
        for (int nf = 0; nf < 8; ++nf) {
            rm0 = fmaxf(rm0, fmaxf(sacc[nf][0], sacc[nf][1]));
            rm1 = fmaxf(rm1, fmaxf(sacc[nf][2], sacc[nf][3]));
        }
        rm0 = fmaxf(rm0, __shfl_xor_sync(0xffffffffu, rm0, 1));
        rm0 = fmaxf(rm0, __shfl_xor_sync(0xffffffffu, rm0, 2));
        rm1 = fmaxf(rm1, __shfl_xor_sync(0xffffffffu, rm1, 1));
        rm1 = fmaxf(rm1, __shfl_xor_sync(0xffffffffu, rm1, 2));
        const float mn0 = fmaxf(m0v, rm0);
        const float mn1 = fmaxf(m1v, rm1);
        const float al0 = ex2(m0v - mn0);
        const float al1 = ex2(m1v - mn1);
        float rs0 = 0.f, rs1 = 0.f;
#pragma unroll
        for (int nf = 0; nf < 8; ++nf) {
            sacc[nf][0] = ex2(sacc[nf][0] - mn0);
            sacc[nf][1] = ex2(sacc[nf][1] - mn0);
            sacc[nf][2] = ex2(sacc[nf][2] - mn1);
            sacc[nf][3] = ex2(sacc[nf][3] - mn1);
            rs0 += sacc[nf][0] + sacc[nf][1];
            rs1 += sacc[nf][2] + sacc[nf][3];
        }
        rs0 += __shfl_xor_sync(0xffffffffu, rs0, 1);
        rs0 += __shfl_xor_sync(0xffffffffu, rs0, 2);
        rs1 += __shfl_xor_sync(0xffffffffu, rs1, 1);
        rs1 += __shfl_xor_sync(0xffffffffu, rs1, 2);
        l0v = l0v * al0 + rs0;  m0v = mn0;
        l1v = l1v * al1 + rs1;  m1v = mn1;
#pragma unroll
        for (int nf = 0; nf < 8; ++nf) {
            o[nf][0] *= al0; o[nf][1] *= al0;
            o[nf][2] *= al1; o[nf][3] *= al1;
        }

        // ---- O += P @ V  (P single fp16; V hi/lo via trans-ldmatrix) ----
#pragma unroll
        for (int ks2 = 0; ks2 < 4; ++ks2) {
            uint32_t pA[4];
#pragma unroll
            for (int q = 0; q < 4; ++q) {
                const int nf = 2 * ks2 + (q >> 1);
                const int e  = (q & 1) * 2;
                pA[q] = packh(sacc[nf][e], sacc[nf][e + 1]);
            }
            const int kq = ks2 * 16 + (t8 & 1) * 8 + (lane & 7);
#pragma unroll
            for (int og = 0; og < 4; ++og) {
                const uint32_t off = swz((uint32_t)kq * 128 + og * 32 + (t8 >> 1) * 16);
                uint32_t vh[4], vl[4];
                ldsm4t(vh[0], vh[1], vh[2], vh[3], VHI + off);
                ldsm4t(vl[0], vl[1], vl[2], vl[3], VLO + off);
                mma16816h(o[2*og],   pA, vh);
                mma16816h(o[2*og],   pA, vl);
                mma16816h(o[2*og+1], pA, vh + 2);
                mma16816h(o[2*og+1], pA, vl + 2);
            }
        }
        __syncthreads();
    }

    // ---- normalize, write ctx as bf16 hi/lo row-major ----
    const float inv0 = 1.f / l0v;
    const float inv1 = 1.f / l1v;
#pragma unroll
    for (int nf = 0; nf < 8; ++nf) {
        const int dh = nf * 8 + tig * 2;
        {
            const float x = o[nf][0] * inv0, y = o[nf][1] * inv0;
            const __nv_bfloat16 hx = __float2bfloat16(x), hy = __float2bfloat16(y);
            *(__nv_bfloat162*)(g_chi + (size_t)(b * S_ + qrow0) * D_ + h * DH_ + dh) =
                __halves2bfloat162(hx, hy);
            *(__nv_bfloat162*)(g_clo + (size_t)(b * S_ + qrow0) * D_ + h * DH_ + dh) =
                __halves2bfloat162(__float2bfloat16(x - __bfloat162float(hx)),
                                   __float2bfloat16(y - __bfloat162float(hy)));
        }
        {
            const float x = o[nf][2] * inv1, y = o[nf][3] * inv1;
            const __nv_bfloat16 hx = __float2bfloat16(x), hy = __float2bfloat16(y);
            *(__nv_bfloat162*)(g_chi + (size_t)(b * S_ + qrow1) * D_ + h * DH_ + dh) =
                __halves2bfloat162(hx, hy);
            *(__nv_bfloat162*)(g_clo + (size_t)(b * S_ + qrow1) * D_ + h * DH_ + dh) =
                __halves2bfloat162(__float2bfloat16(x - __bfloat162float(hx)),
                                   __float2bfloat16(y - __bfloat162float(hy)));
        }
    }
}

// ---------------------------------------------------------------------------
extern "C" void kernel_launch(void* const* d_in, const int* in_sizes, int n_in,
                              void* d_out, int out_size)
{
    const float* x  = (const float*)d_in[0];
    const float* Wq = (const float*)d_in[1];
    const float* Wk = (const float*)d_in[2];
    const float* Wv = (const float*)d_in[3];
    const float* Wo = (const float*)d_in[4];
    const float* bo = (const float*)d_in[5];
    float* out = (float*)d_out;

    __nv_bfloat16 *xhi, *xlo, *whi, *wlo, *chi, *clo;
    cudaGetSymbolAddress((void**)&xhi, g_xhi);
    cudaGetSymbolAddress((void**)&xlo, g_xlo);
    cudaGetSymbolAddress((void**)&whi, g_whi);
    cudaGetSymbolAddress((void**)&wlo, g_wlo);
    cudaGetSymbolAddress((void**)&chi, g_chi);
    cudaGetSymbolAddress((void**)&clo, g_clo);

    cudaFuncSetAttribute(tgemm<0>, cudaFuncAttributeMaxDynamicSharedMemorySize, TG_SMEM);
    cudaFuncSetAttribute(tgemm<1>, cudaFuncAttributeMaxDynamicSharedMemorySize, TG_SMEM);
    cudaFuncSetAttribute(attn_tc,  cudaFuncAttributeMaxDynamicSharedMemorySize, ATT_SMEM);

    const int nx = M_ * D_;     // 4M
    const int nw = D_ * D_;     // 1M
    split_bf16<<<nx/1024, 256>>>(x, xhi, xlo);
    split4_bf16<<<dim3(nw/1024, 4), 256>>>(Wq, Wk, Wv, Wo, whi, wlo);

    // fused QKV projection: N = 3072 against stacked Wq|Wk|Wv
    tgemm<0><<<dim3(3*D_/256, M_/128), 256, TG_SMEM>>>(xhi, xlo, whi, wlo,
                                                       nullptr, nullptr);

    attn_tc<<<dim3(S_/128, B_*H_), 256, ATT_SMEM>>>();

    tgemm<1><<<dim3(D_/256, M_/128), 256, TG_SMEM>>>(chi, clo,
                                                     whi + 3*(size_t)nw, wlo + 3*(size_t)nw,
                                                     bo, out);
}

// round 9
// speedup vs baseline: 1.4897x; 1.2650x over previous
#include <cuda_runtime.h>
#include <cuda_bf16.h>
#include <cuda_fp16.h>
#include <cstdint>

// Problem constants
#define B_  2
#define S_  2048
#define D_  1024
#define H_  16
#define DH_ 64
#define M_  (B_*S_)          // 4096 rows total

// ---------------------------------------------------------------------------
// Scratch (allocation-free __device__ globals) — all-fp16 pipeline
// ---------------------------------------------------------------------------
__device__ __half g_xh[(size_t)M_*D_];           // x hi/lo
__device__ __half g_xl[(size_t)M_*D_];
__device__ __half g_w16[(size_t)4*D_*D_];        // Wq|Wk|Wv|Wo single fp16
__device__ __half g_qh[(size_t)B_*H_*S_*DH_];    // head-major
__device__ __half g_ql[(size_t)B_*H_*S_*DH_];
__device__ __half g_k1[(size_t)B_*H_*S_*DH_];
__device__ __half g_vh[(size_t)B_*H_*S_*DH_];
__device__ __half g_vl[(size_t)B_*H_*S_*DH_];
__device__ __half g_ch[(size_t)M_*D_];           // ctx hi/lo, row-major
__device__ __half g_cl[(size_t)M_*D_];

// ---------------------------------------------------------------------------
// PTX helpers (plain sm_80-class PTX: valid under compute_103)
// ---------------------------------------------------------------------------
__device__ __forceinline__ uint32_t smem_u32(const void* p) {
    uint32_t a;
    asm("{ .reg .u64 t; cvta.to.shared.u64 t, %1; cvt.u32.u64 %0, t; }"
        : "=r"(a) : "l"(p));
    return a;
}
__device__ __forceinline__ void cp16(uint32_t dst, const void* src) {
    asm volatile("cp.async.cg.shared.global [%0], [%1], 16;"
                 :: "r"(dst), "l"(src) : "memory");
}
__device__ __forceinline__ void cp_commit() {
    asm volatile("cp.async.commit_group;" ::: "memory");
}
__device__ __forceinline__ void cp_wait0() {
    asm volatile("cp.async.wait_group 0;" ::: "memory");
}
__device__ __forceinline__ void cp_wait1() {
    asm volatile("cp.async.wait_group 1;" ::: "memory");
}
__device__ __forceinline__ void cp_wait2() {
    asm volatile("cp.async.wait_group 2;" ::: "memory");
}
__device__ __forceinline__ void ldsm4(uint32_t& r0, uint32_t& r1, uint32_t& r2,
                                      uint32_t& r3, uint32_t addr) {
    asm volatile("ldmatrix.sync.aligned.m8n8.x4.shared.b16 {%0,%1,%2,%3}, [%4];"
                 : "=r"(r0), "=r"(r1), "=r"(r2), "=r"(r3) : "r"(addr));
}
__device__ __forceinline__ void ldsm4t(uint32_t& r0, uint32_t& r1, uint32_t& r2,
                                       uint32_t& r3, uint32_t addr) {
    asm volatile("ldmatrix.sync.aligned.m8n8.x4.trans.shared.b16 {%0,%1,%2,%3}, [%4];"
                 : "=r"(r0), "=r"(r1), "=r"(r2), "=r"(r3) : "r"(addr));
}
// fp16 MMA
__device__ __forceinline__ void mma16816h(float* c, const uint32_t* a, const uint32_t* b) {
    asm volatile(
        "mma.sync.aligned.m16n8k16.row.col.f32.f16.f16.f32 "
        "{%0,%1,%2,%3}, {%4,%5,%6,%7}, {%8,%9}, {%0,%1,%2,%3};"
        : "+f"(c[0]), "+f"(c[1]), "+f"(c[2]), "+f"(c[3])
        : "r"(a[0]), "r"(a[1]), "r"(a[2]), "r"(a[3]), "r"(b[0]), "r"(b[1]));
}
__device__ __forceinline__ float ex2(float x) {
    float y; asm("ex2.approx.ftz.f32 %0, %1;" : "=f"(y) : "f"(x)); return y;
}
// Swizzle<3,4,3>: XOR 16B-column bits [6:4] with row bits [9:7]
__device__ __forceinline__ uint32_t swz(uint32_t off) {
    return off ^ ((off >> 3) & 0x70);
}
__device__ __forceinline__ uint32_t packh(float x, float y) {
    __half2 h = __floats2half2_rn(x, y);
    return *(uint32_t*)&h;
}

// ---------------------------------------------------------------------------
// fp32 -> fp16 hi/lo split (x), fp32 -> fp16 convert (weights)
// ---------------------------------------------------------------------------
__global__ void split_h2(const float* __restrict__ src,
                         __half* __restrict__ hi, __half* __restrict__ lo)
{
    const size_t i = ((size_t)blockIdx.x * blockDim.x + threadIdx.x) * 4;
    float4 v = *(const float4*)(src + i);
    __half h0 = __float2half_rn(v.x), h1 = __float2half_rn(v.y);
    __half h2 = __float2half_rn(v.z), h3 = __float2half_rn(v.w);
    *(__half2*)(hi + i)     = __halves2half2(h0, h1);
    *(__half2*)(hi + i + 2) = __halves2half2(h2, h3);
    *(__half2*)(lo + i) = __halves2half2(
        __float2half_rn(v.x - __half2float(h0)),
        __float2half_rn(v.y - __half2float(h1)));
    *(__half2*)(lo + i + 2) = __halves2half2(
        __float2half_rn(v.z - __half2float(h2)),
        __float2half_rn(v.w - __half2float(h3)));
}

__global__ void conv4_h(const float* __restrict__ a, const float* __restrict__ b,
                        const float* __restrict__ c, const float* __restrict__ d,
                        __half* __restrict__ o)
{
    const int w = blockIdx.y;
    const float* src = (w == 0) ? a : (w == 1) ? b : (w == 2) ? c : d;
    const size_t base = (size_t)w * D_ * D_;
    const size_t i = ((size_t)blockIdx.x * blockDim.x + threadIdx.x) * 4;
    float4 v = *(const float4*)(src + i);
    *(__half2*)(o + base + i)     = __floats2half2_rn(v.x, v.y);
    *(__half2*)(o + base + i + 2) = __floats2half2_rn(v.z, v.w);
}

// ---------------------------------------------------------------------------
// fp16 2-term HMMA GEMM: C = (Ahi+Alo) @ W^T, W single fp16.
// 128x256 CTA tile, BK=64, 2-stage (64 KB/stage), 256 threads,
// 8 warps = 2m x 4n, warp tile 64x64.
// MODE 0: fused-QKV store fp16: Q hi/lo, K single, V hi/lo (head-major)
// MODE 1: store fp32 row-major + bias
// ---------------------------------------------------------------------------
#define A_TB   16384                 // 128 x 128B
#define B_TB   32768                 // 256 x 128B
#define STAGE_B (2*A_TB + B_TB)      // 64 KB
#define TG_SMEM (2*STAGE_B)          // 128 KB
#define NCHUNK  (D_/64)              // 16

template<int MODE>
__global__ __launch_bounds__(256, 1) void tgemm(const __half* __restrict__ Ahi,
                                                const __half* __restrict__ Alo,
                                                const __half* __restrict__ Bw,
                                                const float* __restrict__ bias,
                                                float* __restrict__ outf)
{
    extern __shared__ char smem[];
    const uint32_t sb = smem_u32(smem);
    const int tid  = threadIdx.x;
    const int wid  = tid >> 5;
    const int lane = tid & 31;
    const int wm   = wid >> 2;
    const int wn   = wid & 3;
    const int m0   = blockIdx.y * 128;
    const int n0   = blockIdx.x * 256;

    const char* gA[2] = { (const char*)(Ahi + (size_t)m0 * D_),
                          (const char*)(Alo + (size_t)m0 * D_) };
    const char* gB = (const char*)(Bw + (size_t)n0 * D_);

    auto load_stage = [&](int chunk, uint32_t stage) {
        const uint32_t koff = (uint32_t)chunk * 128;
#pragma unroll
        for (int t = 0; t < 2; ++t) {
            const char* base = gA[t] + koff;
            const uint32_t dstt = stage + t * A_TB;
#pragma unroll
            for (int it = 0; it < 4; ++it) {
                const int c = tid + it * 256;
                const int r = c >> 3, c16 = c & 7;
                cp16(dstt + swz((uint32_t)(r * 128 + c16 * 16)),
                     base + (size_t)r * (D_ * 2) + c16 * 16);
            }
        }
        {
            const char* base = gB + koff;
            const uint32_t dstt = stage + 2 * A_TB;
#pragma unroll
            for (int it = 0; it < 8; ++it) {
                const int c = tid + it * 256;
                const int r = c >> 3, c16 = c & 7;
                cp16(dstt + swz((uint32_t)(r * 128 + c16 * 16)),
                     base + (size_t)r * (D_ * 2) + c16 * 16);
            }
        }
        cp_commit();
    };

    float acc[4][8][4];
#pragma unroll
    for (int i = 0; i < 4; i++)
#pragma unroll
        for (int j = 0; j < 8; j++)
#pragma unroll
            for (int q = 0; q < 4; q++) acc[i][j][q] = 0.f;

    load_stage(0, sb);

    for (int c = 0; c < NCHUNK; ++c) {
        cp_wait0();
        __syncthreads();
        const uint32_t cur = sb + (c & 1) * STAGE_B;
        if (c + 1 < NCHUNK) load_stage(c + 1, sb + ((c + 1) & 1) * STAGE_B);

        const uint32_t aHi = cur;
        const uint32_t aLo = cur + A_TB;
        const uint32_t bB  = cur + 2 * A_TB;

#pragma unroll
        for (int ks = 0; ks < 4; ++ks) {
            uint32_t ahi[4][4], alo[4][4];
            {
                const int rA = wm * 64 + (lane & 15);
                const uint32_t colA = (uint32_t)(ks * 32 + (lane >> 4) * 16);
#pragma unroll
                for (int mf = 0; mf < 4; ++mf) {
                    const uint32_t off = swz((uint32_t)(rA + mf * 16) * 128 + colA);
                    ldsm4(ahi[mf][0], ahi[mf][1], ahi[mf][2], ahi[mf][3], aHi + off);
                    ldsm4(alo[mf][0], alo[mf][1], alo[mf][2], alo[mf][3], aLo + off);
                }
            }
            const int t = lane >> 3;
            const uint32_t colB = (uint32_t)(ks * 32 + (t & 1) * 16);
#pragma unroll
            for (int ng = 0; ng < 4; ++ng) {
                const int rB = wn * 64 + ng * 16 + ((t >> 1) * 8) + (lane & 7);
                const uint32_t off = swz((uint32_t)rB * 128 + colB);
                uint32_t bh[4];
                ldsm4(bh[0], bh[1], bh[2], bh[3], bB + off);
#pragma unroll
                for (int mf = 0; mf < 4; ++mf) {
                    mma16816h(acc[mf][2*ng],   ahi[mf], bh);
                    mma16816h(acc[mf][2*ng],   alo[mf], bh);
                    mma16816h(acc[mf][2*ng+1], ahi[mf], bh + 2);
                    mma16816h(acc[mf][2*ng+1], alo[mf], bh + 2);
                }
            }
        }
        __syncthreads();
    }

    const int gid = lane >> 2, tig = lane & 3;
    __half *dhi = nullptr, *dlo = nullptr;
    if (MODE == 0) {
        const int sel = n0 >> 10;
        dhi = (sel == 0) ? g_qh : (sel == 1) ? g_k1 : g_vh;
        dlo = (sel == 0) ? g_ql : (sel == 1) ? nullptr : g_vl;
    }
#pragma unroll
    for (int mf = 0; mf < 4; ++mf)
#pragma unroll
        for (int nf = 0; nf < 8; ++nf)
#pragma unroll
            for (int half = 0; half < 2; ++half) {
                const int m = m0 + wm * 64 + mf * 16 + gid + half * 8;
                const int n = n0 + wn * 64 + nf * 8 + tig * 2;
                float2 v = make_float2(acc[mf][nf][half*2], acc[mf][nf][half*2+1]);
                if (MODE == 1) {
                    v.x += bias[n]; v.y += bias[n+1];
                    *(float2*)(outf + (size_t)m * D_ + n) = v;
                } else {
                    const int nl = n & (D_ - 1);
                    const int b  = m >> 11;
                    const int s  = m & (S_ - 1);
                    const int h  = nl >> 6;
                    const int dh = nl & (DH_ - 1);
                    const size_t idx = ((size_t)(b * H_ + h) * S_ + s) * DH_ + dh;
                    __half h0 = __float2half_rn(v.x);
                    __half h1 = __float2half_rn(v.y);
                    *(__half2*)(dhi + idx) = __halves2half2(h0, h1);
                    if (dlo)
                        *(__half2*)(dlo + idx) = __halves2half2(
                            __float2half_rn(v.x - __half2float(h0)),
                            __float2half_rn(v.y - __half2float(h1)));
                }
            }
}

// ---------------------------------------------------------------------------
// fp16 HMMA flash attention, causal. BLOCK_M=128, BLOCK_N=64, 256 threads.
// S = (Qhi+Qlo)·K ; O += Pf16·(Vhi+Vlo). 3-stage cp.async KV pipeline.
// ctx written as fp16 hi/lo (row-major) for the out-projection.
// ---------------------------------------------------------------------------
#define SM_Q     0                      // 32 KB (qh 16K + ql 16K)
#define SM_KV    32768
#define KV_STG_B 24576                  // K 8K + Vh 8K + Vl 8K
#define ATT_SMEM (32768 + 3*KV_STG_B)   // 106496 B

__global__ __launch_bounds__(256, 1) void attn_tc()
{
    extern __shared__ char smem[];
    const uint32_t sb = smem_u32(smem);
    const int tid  = threadIdx.x;
    const int w    = tid >> 5;
    const int lane = tid & 31;
    const int gid  = lane >> 2;
    const int tig  = lane & 3;
    const int qt   = (int)(gridDim.x - 1 - blockIdx.x);   // heavy tiles first
    const int bh   = blockIdx.y;
    const int q0   = qt * 128;
    const int b    = bh >> 4;
    const int h    = bh & (H_ - 1);
    const int jmax = 2 * qt + 1;        // 64-key tiles: keys [0, q0+128)

    const size_t headoff = (size_t)bh * S_ * DH_;

    auto load_kv = [&](int j, int stg) {
        const uint32_t base = sb + SM_KV + (uint32_t)stg * KV_STG_B;
        const size_t g = headoff + (size_t)j * 64 * DH_;
        const char* srcs[3] = { (const char*)(g_k1 + g),
                                (const char*)(g_vh + g),
                                (const char*)(g_vl + g) };
#pragma unroll
        for (int t = 0; t < 3; ++t) {
#pragma unroll
            for (int it = 0; it < 2; ++it) {
                const int c = tid + it * 256;       // 0..511
                const int r = c >> 3, c16 = c & 7;
                cp16(base + t * 8192 + swz((uint32_t)(r * 128 + c16 * 16)),
                     srcs[t] + r * 128 + c16 * 16);
            }
        }
        cp_commit();
    };

    // group 0: Q tile (hi/lo) + kv(0)
    {
        const char* qh = (const char*)(g_qh + headoff + (size_t)q0 * DH_);
        const char* ql = (const char*)(g_ql + headoff + (size_t)q0 * DH_);
#pragma unroll
        for (int it = 0; it < 4; ++it) {
            const int c = tid + it * 256;
            const int r = c >> 3, c16 = c & 7;
            const uint32_t off = swz((uint32_t)(r * 128 + c16 * 16));
            cp16(sb + SM_Q + off,         qh + r * 128 + c16 * 16);
            cp16(sb + SM_Q + 16384 + off, ql + r * 128 + c16 * 16);
        }
    }
    load_kv(0, 0);
    if (1 <= jmax) load_kv(1, 1);

    float m0v = -1e30f, m1v = -1e30f, l0v = 0.f, l1v = 0.f;
    float o[8][4];
#pragma unroll
    for (int i = 0; i < 8; i++)
#pragma unroll
        for (int j = 0; j < 4; j++) o[i][j] = 0.f;

    uint32_t qh[4][4], ql[4][4];
    const int qrow0 = q0 + w * 16 + gid;
    const int qrow1 = qrow0 + 8;
    const float SC = 0.18033688011112042f;   // (1/sqrt(64)) * log2(e)
    const int t8 = lane >> 3;

    for (int j = 0; j <= jmax; ++j) {
        if (j + 2 <= jmax) {
            int ns = j + 2; ns = ns - (ns / 3) * 3;
            load_kv(j + 2, ns);
            cp_wait2();
        } else if (j + 1 <= jmax) {
            cp_wait1();
        } else {
            cp_wait0();
        }
        __syncthreads();

        if (j == 0) {   // Q fragments once
            const int rA = w * 16 + (lane & 15);
            const uint32_t colA = (uint32_t)((lane >> 4) * 16);
#pragma unroll
            for (int ks = 0; ks < 4; ++ks) {
                const uint32_t off = swz((uint32_t)rA * 128 + ks * 32 + colA);
                ldsm4(qh[ks][0], qh[ks][1], qh[ks][2], qh[ks][3], sb + SM_Q + off);
                ldsm4(ql[ks][0], ql[ks][1], ql[ks][2], ql[ks][3], sb + SM_Q + 16384 + off);
            }
        }

        int stg = j - (j / 3) * 3;
        const uint32_t cur = sb + SM_KV + (uint32_t)stg * KV_STG_B;
        const uint32_t KK = cur, VHI = cur + 8192, VLO = cur + 16384;
        const int k0 = j * 64;

        // ---- S = Q @ K^T  (2 terms: qh·k + ql·k) ----
        float sacc[8][4];
#pragma unroll
        for (int i = 0; i < 8; i++)
#pragma unroll
            for (int q = 0; q < 4; q++) sacc[i][q] = 0.f;

#pragma unroll
        for (int ks = 0; ks < 4; ++ks) {
            const uint32_t colB = (uint32_t)(ks * 32 + (t8 & 1) * 16);
#pragma unroll
            for (int ng = 0; ng < 4; ++ng) {
                const int rK = ng * 16 + ((t8 >> 1) * 8) + (lane & 7);
                const uint32_t off = swz((uint32_t)rK * 128 + colB);
                uint32_t kk[4];
                ldsm4(kk[0], kk[1], kk[2], kk[3], KK + off);
                mma16816h(sacc[2*ng],   qh[ks], kk);
                mma16816h(sacc[2*ng],   ql[ks], kk);
                mma16816h(sacc[2*ng+1], qh[ks], kk + 2);
                mma16816h(sacc[2*ng+1], ql[ks], kk + 2);
            }
        }

        // ---- scale (+ causal mask on the last two tiles) ----
        if (j >= 2 * qt) {
#pragma unroll
            for (int nf = 0; nf < 8; ++nf) {
                const int col = k0 + nf * 8 + tig * 2;
                sacc[nf][0] = (col     > qrow0) ? -1e30f : sacc[nf][0] * SC;
                sacc[nf][1] = (col + 1 > qrow0) ? -1e30f : sacc[nf][1] * SC;
                sacc[nf][2] = (col     > qrow1) ? -1e30f : sacc[nf][2] * SC;
                sacc[nf][3] = (col + 1 > qrow1) ? -1e30f : sacc[nf][3] * SC;
            }
        } else {
#pragma unroll
            for (int nf = 0; nf < 8; ++nf)
#pragma unroll
                for (int q = 0; q < 4; ++q) sacc[nf][q] *= SC;
        }

        // ---- online softmax ----
        float rm0 = -1e30f, rm1 = -1e30f;
#pragma unroll
        for (int nf = 0; nf < 8; ++nf) {
            rm0 = fmaxf(rm0, fmaxf(sacc[nf][0], sacc[nf][1]));
            rm1 = fmaxf(rm1, fmaxf(sacc[nf][2], sacc[nf][3]));
        }
        rm0 = fmaxf(rm0, __shfl_xor_sync(0xffffffffu, rm0, 1));
        rm0 = fmaxf(rm0, __shfl_xor_sync(0xffffffffu, rm0, 2));
        rm1 = fmaxf(rm1, __shfl_xor_sync(0xffffffffu, rm1, 1));
        rm1 = fmaxf(rm1, __shfl_xor_sync(0xffffffffu, rm1, 2));
        const float mn0 = fmaxf(m0v, rm0);
        const float mn1 = fmaxf(m1v, rm1);
        const float al0 = ex2(m0v - mn0);
        const float al1 = ex2(m1v - mn1);
        float rs0 = 0.f, rs1 = 0.f;
#pragma unroll
        for (int nf = 0; nf < 8; ++nf) {
            sacc[nf][0] = ex2(sacc[nf][0] - mn0);
            sacc[nf][1] = ex2(sacc[nf][1] - mn0);
            sacc[nf][2] = ex2(sacc[nf][2] - mn1);
            sacc[nf][3] = ex2(sacc[nf][3] - mn1);
            rs0 += sacc[nf][0] + sacc[nf][1];
            rs1 += sacc[nf][2] + sacc[nf][3];
        }
        rs0 += __shfl_xor_sync(0xffffffffu, rs0, 1);
        rs0 += __shfl_xor_sync(0xffffffffu, rs0, 2);
        rs1 += __shfl_xor_sync(0xffffffffu, rs1, 1);
        rs1 += __shfl_xor_sync(0xffffffffu, rs1, 2);
        l0v = l0v * al0 + rs0;  m0v = mn0;
        l1v = l1v * al1 + rs1;  m1v = mn1;
#pragma unroll
        for (int nf = 0; nf < 8; ++nf) {
            o[nf][0] *= al0; o[nf][1] *= al0;
            o[nf][2] *= al1; o[nf][3] *= al1;
        }

        // ---- O += P @ V  (P single fp16; V hi/lo via trans-ldmatrix) ----
#pragma unroll
        for (int ks2 = 0; ks2 < 4; ++ks2) {
            uint32_t pA[4];
#pragma unroll
            for (int q = 0; q < 4; ++q) {
                const int nf = 2 * ks2 + (q >> 1);
                const int e  = (q & 1) * 2;
                pA[q] = packh(sacc[nf][e], sacc[nf][e + 1]);
            }
            const int kq = ks2 * 16 + (t8 & 1) * 8 + (lane & 7);
#pragma unroll
            for (int og = 0; og < 4; ++og) {
                const uint32_t off = swz((uint32_t)kq * 128 + og * 32 + (t8 >> 1) * 16);
                uint32_t vh[4], vl[4];
                ldsm4t(vh[0], vh[1], vh[2], vh[3], VHI + off);
                ldsm4t(vl[0], vl[1], vl[2], vl[3], VLO + off);
                mma16816h(o[2*og],   pA, vh);
                mma16816h(o[2*og],   pA, vl);
                mma16816h(o[2*og+1], pA, vh + 2);
                mma16816h(o[2*og+1], pA, vl + 2);
            }
        }
        __syncthreads();
    }

    // ---- normalize, write ctx as fp16 hi/lo row-major ----
    const float inv0 = 1.f / l0v;
    const float inv1 = 1.f / l1v;
#pragma unroll
    for (int nf = 0; nf < 8; ++nf) {
        const int dh = nf * 8 + tig * 2;
        {
            const float x = o[nf][0] * inv0, y = o[nf][1] * inv0;
            const __half hx = __float2half_rn(x), hy = __float2half_rn(y);
            *(__half2*)(g_ch + (size_t)(b * S_ + qrow0) * D_ + h * DH_ + dh) =
                __halves2half2(hx, hy);
            *(__half2*)(g_cl + (size_t)(b * S_ + qrow0) * D_ + h * DH_ + dh) =
                __halves2half2(__float2half_rn(x - __half2float(hx)),
                               __float2half_rn(y - __half2float(hy)));
        }
        {
            const float x = o[nf][2] * inv1, y = o[nf][3] * inv1;
            const __half hx = __float2half_rn(x), hy = __float2half_rn(y);
            *(__half2*)(g_ch + (size_t)(b * S_ + qrow1) * D_ + h * DH_ + dh) =
                __halves2half2(hx, hy);
            *(__half2*)(g_cl + (size_t)(b * S_ + qrow1) * D_ + h * DH_ + dh) =
                __halves2half2(__float2half_rn(x - __half2float(hx)),
                               __float2half_rn(y - __half2float(hy)));
        }
    }
}

// ---------------------------------------------------------------------------
extern "C" void kernel_launch(void* const* d_in, const int* in_sizes, int n_in,
                              void* d_out, int out_size)
{
    const float* x  = (const float*)d_in[0];
    const float* Wq = (const float*)d_in[1];
    const float* Wk = (const float*)d_in[2];
    const float* Wv = (const float*)d_in[3];
    const float* Wo = (const float*)d_in[4];
    const float* bo = (const float*)d_in[5];
    float* out = (float*)d_out;

    __half *xh, *xl, *w16, *ch, *cl;
    cudaGetSymbolAddress((void**)&xh,  g_xh);
    cudaGetSymbolAddress((void**)&xl,  g_xl);
    cudaGetSymbolAddress((void**)&w16, g_w16);
    cudaGetSymbolAddress((void**)&ch,  g_ch);
    cudaGetSymbolAddress((void**)&cl,  g_cl);

    cudaFuncSetAttribute(tgemm<0>, cudaFuncAttributeMaxDynamicSharedMemorySize, TG_SMEM);
    cudaFuncSetAttribute(tgemm<1>, cudaFuncAttributeMaxDynamicSharedMemorySize, TG_SMEM);
    cudaFuncSetAttribute(attn_tc,  cudaFuncAttributeMaxDynamicSharedMemorySize, ATT_SMEM);

    const int nx = M_ * D_;     // 4M
    const int nw = D_ * D_;     // 1M
    split_h2<<<nx/1024, 256>>>(x, xh, xl);
    conv4_h<<<dim3(nw/1024, 4), 256>>>(Wq, Wk, Wv, Wo, w16);

    // fused QKV projection: N = 3072 against stacked Wq|Wk|Wv
    tgemm<0><<<dim3(3*D_/256, M_/128), 256, TG_SMEM>>>(xh, xl, w16, nullptr, nullptr);

    attn_tc<<<dim3(S_/128, B_*H_), 256, ATT_SMEM>>>();

    tgemm<1><<<dim3(D_/256, M_/128), 256, TG_SMEM>>>(ch, cl, w16 + 3*(size_t)nw,
                                                     bo, out);
}

// round 10
// speedup vs baseline: 1.5606x; 1.0476x over previous
#include <cuda_runtime.h>
#include <cuda_bf16.h>
#include <cuda_fp16.h>
#include <cstdint>

// Problem constants
#define B_  2
#define S_  2048
#define D_  1024
#define H_  16
#define DH_ 64
#define M_  (B_*S_)          // 4096 rows total

// ---------------------------------------------------------------------------
// Scratch (allocation-free __device__ globals) — all-fp16 pipeline
// Q single, K single, V hi/lo, ctx hi/lo.
// ---------------------------------------------------------------------------
__device__ __half g_xh[(size_t)M_*D_];           // x hi/lo
__device__ __half g_xl[(size_t)M_*D_];
__device__ __half g_w16[(size_t)4*D_*D_];        // Wq|Wk|Wv|Wo single fp16
__device__ __half g_q1[(size_t)B_*H_*S_*DH_];    // head-major, single
__device__ __half g_k1[(size_t)B_*H_*S_*DH_];    // single
__device__ __half g_vh[(size_t)B_*H_*S_*DH_];    // hi/lo
__device__ __half g_vl[(size_t)B_*H_*S_*DH_];
__device__ __half g_ch[(size_t)M_*D_];           // ctx hi/lo, row-major
__device__ __half g_cl[(size_t)M_*D_];

// ---------------------------------------------------------------------------
// PTX helpers (plain sm_80-class PTX: valid under compute_103)
// ---------------------------------------------------------------------------
__device__ __forceinline__ uint32_t smem_u32(const void* p) {
    uint32_t a;
    asm("{ .reg .u64 t; cvta.to.shared.u64 t, %1; cvt.u32.u64 %0, t; }"
        : "=r"(a) : "l"(p));
    return a;
}
__device__ __forceinline__ void cp16(uint32_t dst, const void* src) {
    asm volatile("cp.async.cg.shared.global [%0], [%1], 16;"
                 :: "r"(dst), "l"(src) : "memory");
}
__device__ __forceinline__ void cp_commit() {
    asm volatile("cp.async.commit_group;" ::: "memory");
}
__device__ __forceinline__ void cp_wait0() {
    asm volatile("cp.async.wait_group 0;" ::: "memory");
}
__device__ __forceinline__ void cp_wait1() {
    asm volatile("cp.async.wait_group 1;" ::: "memory");
}
__device__ __forceinline__ void cp_wait2() {
    asm volatile("cp.async.wait_group 2;" ::: "memory");
}
__device__ __forceinline__ void ldsm4(uint32_t& r0, uint32_t& r1, uint32_t& r2,
                                      uint32_t& r3, uint32_t addr) {
    asm volatile("ldmatrix.sync.aligned.m8n8.x4.shared.b16 {%0,%1,%2,%3}, [%4];"
                 : "=r"(r0), "=r"(r1), "=r"(r2), "=r"(r3) : "r"(addr));
}
__device__ __forceinline__ void ldsm4t(uint32_t& r0, uint32_t& r1, uint32_t& r2,
                                       uint32_t& r3, uint32_t addr) {
    asm volatile("ldmatrix.sync.aligned.m8n8.x4.trans.shared.b16 {%0,%1,%2,%3}, [%4];"
                 : "=r"(r0), "=r"(r1), "=r"(r2), "=r"(r3) : "r"(addr));
}
// fp16 MMA
__device__ __forceinline__ void mma16816h(float* c, const uint32_t* a, const uint32_t* b) {
    asm volatile(
        "mma.sync.aligned.m16n8k16.row.col.f32.f16.f16.f32 "
        "{%0,%1,%2,%3}, {%4,%5,%6,%7}, {%8,%9}, {%0,%1,%2,%3};"
        : "+f"(c[0]), "+f"(c[1]), "+f"(c[2]), "+f"(c[3])
        : "r"(a[0]), "r"(a[1]), "r"(a[2]), "r"(a[3]), "r"(b[0]), "r"(b[1]));
}
__device__ __forceinline__ float ex2(float x) {
    float y; asm("ex2.approx.ftz.f32 %0, %1;" : "=f"(y) : "f"(x)); return y;
}
// Swizzle<3,4,3>: XOR 16B-column bits [6:4] with row bits [9:7]
__device__ __forceinline__ uint32_t swz(uint32_t off) {
    return off ^ ((off >> 3) & 0x70);
}
__device__ __forceinline__ uint32_t packh(float x, float y) {
    __half2 h = __floats2half2_rn(x, y);
    return *(uint32_t*)&h;
}

// ---------------------------------------------------------------------------
// fp32 -> fp16 hi/lo split (x), fp32 -> fp16 convert (weights)
// ---------------------------------------------------------------------------
__global__ void split_h2(const float* __restrict__ src,
                         __half* __restrict__ hi, __half* __restrict__ lo)
{
    const size_t i = ((size_t)blockIdx.x * blockDim.x + threadIdx.x) * 4;
    float4 v = *(const float4*)(src + i);
    __half h0 = __float2half_rn(v.x), h1 = __float2half_rn(v.y);
    __half h2 = __float2half_rn(v.z), h3 = __float2half_rn(v.w);
    *(__half2*)(hi + i)     = __halves2half2(h0, h1);
    *(__half2*)(hi + i + 2) = __halves2half2(h2, h3);
    *(__half2*)(lo + i) = __halves2half2(
        __float2half_rn(v.x - __half2float(h0)),
        __float2half_rn(v.y - __half2float(h1)));
    *(__half2*)(lo + i + 2) = __halves2half2(
        __float2half_rn(v.z - __half2float(h2)),
        __float2half_rn(v.w - __half2float(h3)));
}

__global__ void conv4_h(const float* __restrict__ a, const float* __restrict__ b,
                        const float* __restrict__ c, const float* __restrict__ d,
                        __half* __restrict__ o)
{
    const int w = blockIdx.y;
    const float* src = (w == 0) ? a : (w == 1) ? b : (w == 2) ? c : d;
    const size_t base = (size_t)w * D_ * D_;
    const size_t i = ((size_t)blockIdx.x * blockDim.x + threadIdx.x) * 4;
    float4 v = *(const float4*)(src + i);
    *(__half2*)(o + base + i)     = __floats2half2_rn(v.x, v.y);
    *(__half2*)(o + base + i + 2) = __floats2half2_rn(v.z, v.w);
}

// ---------------------------------------------------------------------------
// fp16 HMMA GEMM: C = (Ahi[+Alo]) @ W^T, W single fp16.
// 128x256 CTA tile, BK=64, 2-stage (64 KB/stage), 256 threads,
// 8 warps = 2m x 4n, warp tile 64x64.
// MODE 0 (fused QKV, N=3072): Q block -> single store, NO lo term;
//                             K block -> single store, NO lo term;
//                             V block -> hi/lo store, lo term kept.
// MODE 1: ctx @ Wo^T + bias -> fp32 out (lo term kept)
// ---------------------------------------------------------------------------
#define A_TB   16384                 // 128 x 128B
#define B_TB   32768                 // 256 x 128B
#define STAGE_B (2*A_TB + B_TB)      // 64 KB
#define TG_SMEM (2*STAGE_B)          // 128 KB
#define NCHUNK  (D_/64)              // 16

template<int MODE>
__global__ __launch_bounds__(256, 1) void tgemm(const __half* __restrict__ Ahi,
                                                const __half* __restrict__ Alo,
                                                const __half* __restrict__ Bw,
                                                const float* __restrict__ bias,
                                                float* __restrict__ outf)
{
    extern __shared__ char smem[];
    const uint32_t sb = smem_u32(smem);
    const int tid  = threadIdx.x;
    const int wid  = tid >> 5;
    const int lane = tid & 31;
    const int wm   = wid >> 2;
    const int wn   = wid & 3;
    const int m0   = blockIdx.y * 128;
    const int n0   = blockIdx.x * 256;
    const int sel  = n0 >> 10;                    // 0=Q, 1=K, 2=V (MODE 0)
    const bool use_lo = (MODE == 1) || (sel == 2);

    const char* gA[2] = { (const char*)(Ahi + (size_t)m0 * D_),
                          (const char*)(Alo + (size_t)m0 * D_) };
    const char* gB = (const char*)(Bw + (size_t)n0 * D_);

    auto load_stage = [&](int chunk, uint32_t stage) {
        const uint32_t koff = (uint32_t)chunk * 128;
        const int nta = use_lo ? 2 : 1;
        for (int t = 0; t < nta; ++t) {
            const char* base = gA[t] + koff;
            const uint32_t dstt = stage + t * A_TB;
#pragma unroll
            for (int it = 0; it < 4; ++it) {
                const int c = tid + it * 256;
                const int r = c >> 3, c16 = c & 7;
                cp16(dstt + swz((uint32_t)(r * 128 + c16 * 16)),
                     base + (size_t)r * (D_ * 2) + c16 * 16);
            }
        }
        {
            const char* base = gB + koff;
            const uint32_t dstt = stage + 2 * A_TB;
#pragma unroll
            for (int it = 0; it < 8; ++it) {
                const int c = tid + it * 256;
                const int r = c >> 3, c16 = c & 7;
                cp16(dstt + swz((uint32_t)(r * 128 + c16 * 16)),
                     base + (size_t)r * (D_ * 2) + c16 * 16);
            }
        }
        cp_commit();
    };

    float acc[4][8][4];
#pragma unroll
    for (int i = 0; i < 4; i++)
#pragma unroll
        for (int j = 0; j < 8; j++)
#pragma unroll
            for (int q = 0; q < 4; q++) acc[i][j][q] = 0.f;

    load_stage(0, sb);

    for (int c = 0; c < NCHUNK; ++c) {
        cp_wait0();
        __syncthreads();
        const uint32_t cur = sb + (c & 1) * STAGE_B;
        if (c + 1 < NCHUNK) load_stage(c + 1, sb + ((c + 1) & 1) * STAGE_B);

        const uint32_t aHi = cur;
        const uint32_t aLo = cur + A_TB;
        const uint32_t bB  = cur + 2 * A_TB;

#pragma unroll
        for (int ks = 0; ks < 4; ++ks) {
            uint32_t ahi[4][4], alo[4][4];
            {
                const int rA = wm * 64 + (lane & 15);
                const uint32_t colA = (uint32_t)(ks * 32 + (lane >> 4) * 16);
#pragma unroll
                for (int mf = 0; mf < 4; ++mf) {
                    const uint32_t off = swz((uint32_t)(rA + mf * 16) * 128 + colA);
                    ldsm4(ahi[mf][0], ahi[mf][1], ahi[mf][2], ahi[mf][3], aHi + off);
                    if (use_lo)
                        ldsm4(alo[mf][0], alo[mf][1], alo[mf][2], alo[mf][3], aLo + off);
                }
            }
            const int t = lane >> 3;
            const uint32_t colB = (uint32_t)(ks * 32 + (t & 1) * 16);
#pragma unroll
            for (int ng = 0; ng < 4; ++ng) {
                const int rB = wn * 64 + ng * 16 + ((t >> 1) * 8) + (lane & 7);
                const uint32_t off = swz((uint32_t)rB * 128 + colB);
                uint32_t bh[4];
                ldsm4(bh[0], bh[1], bh[2], bh[3], bB + off);
#pragma unroll
                for (int mf = 0; mf < 4; ++mf) {
                    mma16816h(acc[mf][2*ng],   ahi[mf], bh);
                    mma16816h(acc[mf][2*ng+1], ahi[mf], bh + 2);
                    if (use_lo) {
                        mma16816h(acc[mf][2*ng],   alo[mf], bh);
                        mma16816h(acc[mf][2*ng+1], alo[mf], bh + 2);
                    }
                }
            }
        }
        __syncthreads();
    }

    const int gid = lane >> 2, tig = lane & 3;
    __half *dhi = nullptr, *dlo = nullptr;
    if (MODE == 0) {
        dhi = (sel == 0) ? g_q1 : (sel == 1) ? g_k1 : g_vh;
        dlo = (sel == 2) ? g_vl : nullptr;
    }
#pragma unroll
    for (int mf = 0; mf < 4; ++mf)
#pragma unroll
        for (int nf = 0; nf < 8; ++nf)
#pragma unroll
            for (int half = 0; half < 2; ++half) {
                const int m = m0 + wm * 64 + mf * 16 + gid + half * 8;
                const int n = n0 + wn * 64 + nf * 8 + tig * 2;
                float2 v = make_float2(acc[mf][nf][half*2], acc[mf][nf][half*2+1]);
                if (MODE == 1) {
                    v.x += bias[n]; v.y += bias[n+1];
                    *(float2*)(outf + (size_t)m * D_ + n) = v;
                } else {
                    const int nl = n & (D_ - 1);
                    const int b  = m >> 11;
                    const int s  = m & (S_ - 1);
                    const int h  = nl >> 6;
                    const int dh = nl & (DH_ - 1);
                    const size_t idx = ((size_t)(b * H_ + h) * S_ + s) * DH_ + dh;
                    __half h0 = __float2half_rn(v.x);
                    __half h1 = __float2half_rn(v.y);
                    *(__half2*)(dhi + idx) = __halves2half2(h0, h1);
                    if (dlo)
                        *(__half2*)(dlo + idx) = __halves2half2(
                            __float2half_rn(v.x - __half2float(h0)),
                            __float2half_rn(v.y - __half2float(h1)));
                }
            }
}

// ---------------------------------------------------------------------------
// fp16 HMMA flash attention, causal. BLOCK_M=128, BLOCK_N=64, 256 threads.
// S = Q·K (single-term) ; O += Pf16·(Vhi+Vlo). 3-stage cp.async KV pipeline.
// ctx written as fp16 hi/lo (row-major) for the out-projection.
// ---------------------------------------------------------------------------
#define SM_Q     0                      // 16 KB (q single)
#define SM_KV    16384
#define KV_STG_B 24576                  // K 8K + Vh 8K + Vl 8K
#define ATT_SMEM (16384 + 3*KV_STG_B)   // 90112 B

__global__ __launch_bounds__(256, 1) void attn_tc()
{
    extern __shared__ char smem[];
    const uint32_t sb = smem_u32(smem);
    const int tid  = threadIdx.x;
    const int w    = tid >> 5;
    const int lane = tid & 31;
    const int gid  = lane >> 2;
    const int tig  = lane & 3;
    const int qt   = (int)(gridDim.x - 1 - blockIdx.x);   // heavy tiles first
    const int bh   = blockIdx.y;
    const int q0   = qt * 128;
    const int b    = bh >> 4;
    const int h    = bh & (H_ - 1);
    const int jmax = 2 * qt + 1;        // 64-key tiles: keys [0, q0+128)

    const size_t headoff = (size_t)bh * S_ * DH_;

    auto load_kv = [&](int j, int stg) {
        const uint32_t base = sb + SM_KV + (uint32_t)stg * KV_STG_B;
        const size_t g = headoff + (size_t)j * 64 * DH_;
        const char* srcs[3] = { (const char*)(g_k1 + g),
                                (const char*)(g_vh + g),
                                (const char*)(g_vl + g) };
#pragma unroll
        for (int t = 0; t < 3; ++t) {
#pragma unroll
            for (int it = 0; it < 2; ++it) {
                const int c = tid + it * 256;       // 0..511
                const int r = c >> 3, c16 = c & 7;
                cp16(base + t * 8192 + swz((uint32_t)(r * 128 + c16 * 16)),
                     srcs[t] + r * 128 + c16 * 16);
            }
        }
        cp_commit();
    };

    // group 0: Q tile (single) + kv(0)
    {
        const char* qsrc = (const char*)(g_q1 + headoff + (size_t)q0 * DH_);
#pragma unroll
        for (int it = 0; it < 4; ++it) {
            const int c = tid + it * 256;
            const int r = c >> 3, c16 = c & 7;
            cp16(sb + SM_Q + swz((uint32_t)(r * 128 + c16 * 16)),
                 qsrc + r * 128 + c16 * 16);
        }
    }
    load_kv(0, 0);
    if (1 <= jmax) load_kv(1, 1);

    float m0v = -1e30f, m1v = -1e30f, l0v = 0.f, l1v = 0.f;
    float o[8][4];
#pragma unroll
    for (int i = 0; i < 8; i++)
#pragma unroll
        for (int j = 0; j < 4; j++) o[i][j] = 0.f;

    uint32_t qA[4][4];
    const int qrow0 = q0 + w * 16 + gid;
    const int qrow1 = qrow0 + 8;
    const float SC = 0.18033688011112042f;   // (1/sqrt(64)) * log2(e)
    const int t8 = lane >> 3;

    for (int j = 0; j <= jmax; ++j) {
        if (j + 2 <= jmax) {
            int ns = j + 2; ns = ns - (ns / 3) * 3;
            load_kv(j + 2, ns);
            cp_wait2();
        } else if (j + 1 <= jmax) {
            cp_wait1();
        } else {
            cp_wait0();
        }
        __syncthreads();

        if (j == 0) {   // Q fragments once
            const int rA = w * 16 + (lane & 15);
            const uint32_t colA = (uint32_t)((lane >> 4) * 16);
#pragma unroll
            for (int ks = 0; ks < 4; ++ks) {
                const uint32_t off = swz((uint32_t)rA * 128 + ks * 32 + colA);
                ldsm4(qA[ks][0], qA[ks][1], qA[ks][2], qA[ks][3], sb + SM_Q + off);
            }
        }

        int stg = j - (j / 3) * 3;
        const uint32_t cur = sb + SM_KV + (uint32_t)stg * KV_STG_B;
        const uint32_t KK = cur, VHI = cur + 8192, VLO = cur + 16384;
        const int k0 = j * 64;

        // ---- S = Q @ K^T  (single term) ----
        float sacc[8][4];
#pragma unroll
        for (int i = 0; i < 8; i++)
#pragma unroll
            for (int q = 0; q < 4; q++) sacc[i][q] = 0.f;

#pragma unroll
        for (int ks = 0; ks < 4; ++ks) {
            const uint32_t colB = (uint32_t)(ks * 32 + (t8 & 1) * 16);
#pragma unroll
            for (int ng = 0; ng < 4; ++ng) {
                const int rK = ng * 16 + ((t8 >> 1) * 8) + (lane & 7);
                const uint32_t off = swz((uint32_t)rK * 128 + colB);
                uint32_t kk[4];
                ldsm4(kk[0], kk[1], kk[2], kk[3], KK + off);
                mma16816h(sacc[2*ng],   qA[ks], kk);
                mma16816h(sacc[2*ng+1], qA[ks], kk + 2);
            }
        }

        // ---- scale (+ causal mask on the last two tiles) ----
        if (j >= 2 * qt) {
#pragma unroll
            for (int nf = 0; nf < 8; ++nf) {
                const int col = k0 + nf * 8 + tig * 2;
                sacc[nf][0] = (col     > qrow0) ? -1e30f : sacc[nf][0] * SC;
                sacc[nf][1] = (col + 1 > qrow0) ? -1e30f : sacc[nf][1] * SC;
                sacc[nf][2] = (col     > qrow1) ? -1e30f : sacc[nf][2] * SC;
                sacc[nf][3] = (col + 1 > qrow1) ? -1e30f : sacc[nf][3] * SC;
            }
        } else {
#pragma unroll
            for (int nf = 0; nf < 8; ++nf)
#pragma unroll
                for (int q = 0; q < 4; ++q) sacc[nf][q] *= SC;
        }

        // ---- online softmax ----
        float rm0 = -1e30f, rm1 = -1e30f;
#pragma unroll
        for (int nf = 0; nf < 8; ++nf) {
            rm0 = fmaxf(rm0, fmaxf(sacc[nf][0], sacc[nf][1]));
            rm1 = fmaxf(rm1, fmaxf(sacc[nf][2], sacc[nf][3]));
        }
        rm0 = fmaxf(rm0, __shfl_xor_sync(0xffffffffu, rm0, 1));
        rm0 = fmaxf(rm0, __shfl_xor_sync(0xffffffffu, rm0, 2));
        rm1 = fmaxf(rm1, __shfl_xor_sync(0xffffffffu, rm1, 1));
        rm1 = fmaxf(rm1, __shfl_xor_sync(0xffffffffu, rm1, 2));
        const float mn0 = fmaxf(m0v, rm0);
        const float mn1 = fmaxf(m1v, rm1);
        const float al0 = ex2(m0v - mn0);
        const float al1 = ex2(m1v - mn1);
        float rs0 = 0.f, rs1 = 0.f;
#pragma unroll
        for (int nf = 0; nf < 8; ++nf) {
            sacc[nf][0] = ex2(sacc[nf][0] - mn0);
            sacc[nf][1] = ex2(sacc[nf][1] - mn0);
            sacc[nf][2] = ex2(sacc[nf][2] - mn1);
            sacc[nf][3] = ex2(sacc[nf][3] - mn1);
            rs0 += sacc[nf][0] + sacc[nf][1];
            rs1 += sacc[nf][2] + sacc[nf][3];
        }
        rs0 += __shfl_xor_sync(0xffffffffu, rs0, 1);
        rs0 += __shfl_xor_sync(0xffffffffu, rs0, 2);
        rs1 += __shfl_xor_sync(0xffffffffu, rs1, 1);
        rs1 += __shfl_xor_sync(0xffffffffu, rs1, 2);
        l0v = l0v * al0 + rs0;  m0v = mn0;
        l1v = l1v * al1 + rs1;  m1v = mn1;
#pragma unroll
        for (int nf = 0; nf < 8; ++nf) {
            o[nf][0] *= al0; o[nf][1] *= al0;
            o[nf][2] *= al1; o[nf][3] *= al1;
        }

        // ---- O += P @ V  (P single fp16; V hi/lo via trans-ldmatrix) ----
#pragma unroll
        for (int ks2 = 0; ks2 < 4; ++ks2) {
            uint32_t pA[4];
#pragma unroll
            for (int q = 0; q < 4; ++q) {
                const int nf = 2 * ks2 + (q >> 1);
                const int e  = (q & 1) * 2;
                pA[q] = packh(sacc[nf][e], sacc[nf][e + 1]);
            }
            const int kq = ks2 * 16 + (t8 & 1) * 8 + (lane & 7);
#pragma unroll
            for (int og = 0; og < 4; ++og) {
                const uint32_t off = swz((uint32_t)kq * 128 + og * 32 + (t8 >> 1) * 16);
                uint32_t vh[4], vl[4];
                ldsm4t(vh[0], vh[1], vh[2], vh[3], VHI + off);
                ldsm4t(vl[0], vl[1], vl[2], vl[3], VLO + off);
                mma16816h(o[2*og],   pA, vh);
                mma16816h(o[2*og],   pA, vl);
                mma16816h(o[2*og+1], pA, vh + 2);
                mma16816h(o[2*og+1], pA, vl + 2);
            }
        }
        __syncthreads();
    }

    // ---- normalize, write ctx as fp16 hi/lo row-major ----
    const float inv0 = 1.f / l0v;
    const float inv1 = 1.f / l1v;
#pragma unroll
    for (int nf = 0; nf < 8; ++nf) {
        const int dh = nf * 8 + tig * 2;
        {
            const float x = o[nf][0] * inv0, y = o[nf][1] * inv0;
            const __half hx = __float2half_rn(x), hy = __float2half_rn(y);
            *(__half2*)(g_ch + (size_t)(b * S_ + qrow0) * D_ + h * DH_ + dh) =
                __halves2half2(hx, hy);
            *(__half2*)(g_cl + (size_t)(b * S_ + qrow0) * D_ + h * DH_ + dh) =
                __halves2half2(__float2half_rn(x - __half2float(hx)),
                               __float2half_rn(y - __half2float(hy)));
        }
        {
            const float x = o[nf][2] * inv1, y = o[nf][3] * inv1;
            const __half hx = __float2half_rn(x), hy = __float2half_rn(y);
            *(__half2*)(g_ch + (size_t)(b * S_ + qrow1) * D_ + h * DH_ + dh) =
                __halves2half2(hx, hy);
            *(__half2*)(g_cl + (size_t)(b * S_ + qrow1) * D_ + h * DH_ + dh) =
                __halves2half2(__float2half_rn(x - __half2float(hx)),
                               __float2half_rn(y - __half2float(hy)));
        }
    }
}

// ---------------------------------------------------------------------------
extern "C" void kernel_launch(void* const* d_in, const int* in_sizes, int n_in,
                              void* d_out, int out_size)
{
    const float* x  = (const float*)d_in[0];
    const float* Wq = (const float*)d_in[1];
    const float* Wk = (const float*)d_in[2];
    const float* Wv = (const float*)d_in[3];
    const float* Wo = (const float*)d_in[4];
    const float* bo = (const float*)d_in[5];
    float* out = (float*)d_out;

    __half *xh, *xl, *w16, *ch, *cl;
    cudaGetSymbolAddress((void**)&xh,  g_xh);
    cudaGetSymbolAddress((void**)&xl,  g_xl);
    cudaGetSymbolAddress((void**)&w16, g_w16);
    cudaGetSymbolAddress((void**)&ch,  g_ch);
    cudaGetSymbolAddress((void**)&cl,  g_cl);

    cudaFuncSetAttribute(tgemm<0>, cudaFuncAttributeMaxDynamicSharedMemorySize, TG_SMEM);
    cudaFuncSetAttribute(tgemm<1>, cudaFuncAttributeMaxDynamicSharedMemorySize, TG_SMEM);
    cudaFuncSetAttribute(attn_tc,  cudaFuncAttributeMaxDynamicSharedMemorySize, ATT_SMEM);

    const int nx = M_ * D_;     // 4M
    const int nw = D_ * D_;     // 1M
    split_h2<<<nx/1024, 256>>>(x, xh, xl);
    conv4_h<<<dim3(nw/1024, 4), 256>>>(Wq, Wk, Wv, Wo, w16);

    // fused QKV projection: N = 3072 against stacked Wq|Wk|Wv
    tgemm<0><<<dim3(3*D_/256, M_/128), 256, TG_SMEM>>>(xh, xl, w16, nullptr, nullptr);

    attn_tc<<<dim3(S_/128, B_*H_), 256, ATT_SMEM>>>();

    tgemm<1><<<dim3(D_/256, M_/128), 256, TG_SMEM>>>(ch, cl, w16 + 3*(size_t)nw,
                                                     bo, out);
}

// round 11
// speedup vs baseline: 2.0931x; 1.3413x over previous
#include <cuda_runtime.h>
#include <cuda_bf16.h>
#include <cuda_fp16.h>
#include <cstdint>

// Problem constants
#define B_  2
#define S_  2048
#define D_  1024
#define H_  16
#define DH_ 64
#define M_  (B_*S_)          // 4096 rows total

// ---------------------------------------------------------------------------
// Scratch (allocation-free __device__ globals) — fp16 pipeline
// x single, W single, Q/K/V single, ctx hi/lo (out-proj keeps compensation).
// ---------------------------------------------------------------------------
__device__ __half g_x16[(size_t)M_*D_];
__device__ __half g_w16[(size_t)4*D_*D_];        // Wq|Wk|Wv|Wo
__device__ __half g_q1[(size_t)B_*H_*S_*DH_];    // head-major
__device__ __half g_k1[(size_t)B_*H_*S_*DH_];
__device__ __half g_v1[(size_t)B_*H_*S_*DH_];
__device__ __half g_ch[(size_t)M_*D_];           // ctx hi/lo, row-major
__device__ __half g_cl[(size_t)M_*D_];

// ---------------------------------------------------------------------------
// PTX helpers (plain sm_80-class PTX: valid under compute_103)
// ---------------------------------------------------------------------------
__device__ __forceinline__ uint32_t smem_u32(const void* p) {
    uint32_t a;
    asm("{ .reg .u64 t; cvta.to.shared.u64 t, %1; cvt.u32.u64 %0, t; }"
        : "=r"(a) : "l"(p));
    return a;
}
__device__ __forceinline__ void cp16(uint32_t dst, const void* src) {
    asm volatile("cp.async.cg.shared.global [%0], [%1], 16;"
                 :: "r"(dst), "l"(src) : "memory");
}
__device__ __forceinline__ void cp_commit() {
    asm volatile("cp.async.commit_group;" ::: "memory");
}
__device__ __forceinline__ void cp_wait0() {
    asm volatile("cp.async.wait_group 0;" ::: "memory");
}
__device__ __forceinline__ void cp_wait1() {
    asm volatile("cp.async.wait_group 1;" ::: "memory");
}
__device__ __forceinline__ void cp_wait2() {
    asm volatile("cp.async.wait_group 2;" ::: "memory");
}
__device__ __forceinline__ void ldsm4(uint32_t& r0, uint32_t& r1, uint32_t& r2,
                                      uint32_t& r3, uint32_t addr) {
    asm volatile("ldmatrix.sync.aligned.m8n8.x4.shared.b16 {%0,%1,%2,%3}, [%4];"
                 : "=r"(r0), "=r"(r1), "=r"(r2), "=r"(r3) : "r"(addr));
}
__device__ __forceinline__ void ldsm4t(uint32_t& r0, uint32_t& r1, uint32_t& r2,
                                       uint32_t& r3, uint32_t addr) {
    asm volatile("ldmatrix.sync.aligned.m8n8.x4.trans.shared.b16 {%0,%1,%2,%3}, [%4];"
                 : "=r"(r0), "=r"(r1), "=r"(r2), "=r"(r3) : "r"(addr));
}
// fp16 MMA
__device__ __forceinline__ void mma16816h(float* c, const uint32_t* a, const uint32_t* b) {
    asm volatile(
        "mma.sync.aligned.m16n8k16.row.col.f32.f16.f16.f32 "
        "{%0,%1,%2,%3}, {%4,%5,%6,%7}, {%8,%9}, {%0,%1,%2,%3};"
        : "+f"(c[0]), "+f"(c[1]), "+f"(c[2]), "+f"(c[3])
        : "r"(a[0]), "r"(a[1]), "r"(a[2]), "r"(a[3]), "r"(b[0]), "r"(b[1]));
}
__device__ __forceinline__ float ex2(float x) {
    float y; asm("ex2.approx.ftz.f32 %0, %1;" : "=f"(y) : "f"(x)); return y;
}
// Swizzle<3,4,3>: XOR 16B-column bits [6:4] with row bits [9:7]
__device__ __forceinline__ uint32_t swz(uint32_t off) {
    return off ^ ((off >> 3) & 0x70);
}
__device__ __forceinline__ uint32_t packh(float x, float y) {
    __half2 h = __floats2half2_rn(x, y);
    return *(uint32_t*)&h;
}

// ---------------------------------------------------------------------------
// converts: x -> fp16, 4 weight matrices -> fp16
// ---------------------------------------------------------------------------
__global__ void conv_h(const float* __restrict__ src, __half* __restrict__ o)
{
    const size_t i = ((size_t)blockIdx.x * blockDim.x + threadIdx.x) * 4;
    float4 v = *(const float4*)(src + i);
    *(__half2*)(o + i)     = __floats2half2_rn(v.x, v.y);
    *(__half2*)(o + i + 2) = __floats2half2_rn(v.z, v.w);
}

__global__ void conv4_h(const float* __restrict__ a, const float* __restrict__ b,
                        const float* __restrict__ c, const float* __restrict__ d,
                        __half* __restrict__ o)
{
    const int w = blockIdx.y;
    const float* src = (w == 0) ? a : (w == 1) ? b : (w == 2) ? c : d;
    const size_t base = (size_t)w * D_ * D_;
    const size_t i = ((size_t)blockIdx.x * blockDim.x + threadIdx.x) * 4;
    float4 v = *(const float4*)(src + i);
    *(__half2*)(o + base + i)     = __floats2half2_rn(v.x, v.y);
    *(__half2*)(o + base + i + 2) = __floats2half2_rn(v.z, v.w);
}

// ---------------------------------------------------------------------------
// fp16 HMMA GEMM: 128x256 CTA tile, BK=64, 2-stage, 256 threads,
// 8 warps = 2m x 4n, warp tile 64x64.
// MODE 0 (fused QKV, N=3072): A = x16 single, single MMA term;
//                             stores single fp16 head-major to q/k/v.
// MODE 1 (out-proj): A = ctx hi/lo, 2 MMA terms; fp32 out + bias.
// ---------------------------------------------------------------------------
#define A_TB   16384                 // 128 x 128B
#define B_TB   32768                 // 256 x 128B
#define NCHUNK  (D_/64)              // 16
// stage sizes per mode
#define STAGE0 (A_TB + B_TB)         // 48 KB
#define STAGE1 (2*A_TB + B_TB)       // 64 KB
#define TG_SMEM0 (2*STAGE0)          // 96 KB
#define TG_SMEM1 (2*STAGE1)          // 128 KB

template<int MODE>
__global__ __launch_bounds__(256, 1) void tgemm(const __half* __restrict__ Ahi,
                                                const __half* __restrict__ Alo,
                                                const __half* __restrict__ Bw,
                                                const float* __restrict__ bias,
                                                float* __restrict__ outf)
{
    constexpr int N_A = (MODE == 1) ? 2 : 1;
    constexpr uint32_t STG = N_A * A_TB + B_TB;

    extern __shared__ char smem[];
    const uint32_t sb = smem_u32(smem);
    const int tid  = threadIdx.x;
    const int wid  = tid >> 5;
    const int lane = tid & 31;
    const int wm   = wid >> 2;
    const int wn   = wid & 3;
    const int m0   = blockIdx.y * 128;
    const int n0   = blockIdx.x * 256;
    const int sel  = n0 >> 10;                    // 0=Q, 1=K, 2=V (MODE 0)

    const char* gA[2] = { (const char*)(Ahi + (size_t)m0 * D_),
                          (const char*)(Alo + (size_t)m0 * D_) };
    const char* gB = (const char*)(Bw + (size_t)n0 * D_);

    auto load_stage = [&](int chunk, uint32_t stage) {
        const uint32_t koff = (uint32_t)chunk * 128;
#pragma unroll
        for (int t = 0; t < N_A; ++t) {
            const char* base = gA[t] + koff;
            const uint32_t dstt = stage + t * A_TB;
#pragma unroll
            for (int it = 0; it < 4; ++it) {
                const int c = tid + it * 256;
                const int r = c >> 3, c16 = c & 7;
                cp16(dstt + swz((uint32_t)(r * 128 + c16 * 16)),
                     base + (size_t)r * (D_ * 2) + c16 * 16);
            }
        }
        {
            const char* base = gB + koff;
            const uint32_t dstt = stage + N_A * A_TB;
#pragma unroll
            for (int it = 0; it < 8; ++it) {
                const int c = tid + it * 256;
                const int r = c >> 3, c16 = c & 7;
                cp16(dstt + swz((uint32_t)(r * 128 + c16 * 16)),
                     base + (size_t)r * (D_ * 2) + c16 * 16);
            }
        }
        cp_commit();
    };

    float acc[4][8][4];
#pragma unroll
    for (int i = 0; i < 4; i++)
#pragma unroll
        for (int j = 0; j < 8; j++)
#pragma unroll
            for (int q = 0; q < 4; q++) acc[i][j][q] = 0.f;

    load_stage(0, sb);

    for (int c = 0; c < NCHUNK; ++c) {
        cp_wait0();
        __syncthreads();
        const uint32_t cur = sb + (c & 1) * STG;
        if (c + 1 < NCHUNK) load_stage(c + 1, sb + ((c + 1) & 1) * STG);

        const uint32_t aHi = cur;
        const uint32_t aLo = cur + A_TB;
        const uint32_t bB  = cur + N_A * A_TB;

#pragma unroll
        for (int ks = 0; ks < 4; ++ks) {
            uint32_t ahi[4][4], alo[4][4];
            {
                const int rA = wm * 64 + (lane & 15);
                const uint32_t colA = (uint32_t)(ks * 32 + (lane >> 4) * 16);
#pragma unroll
                for (int mf = 0; mf < 4; ++mf) {
                    const uint32_t off = swz((uint32_t)(rA + mf * 16) * 128 + colA);
                    ldsm4(ahi[mf][0], ahi[mf][1], ahi[mf][2], ahi[mf][3], aHi + off);
                    if (MODE == 1)
                        ldsm4(alo[mf][0], alo[mf][1], alo[mf][2], alo[mf][3], aLo + off);
                }
            }
            const int t = lane >> 3;
            const uint32_t colB = (uint32_t)(ks * 32 + (t & 1) * 16);
#pragma unroll
            for (int ng = 0; ng < 4; ++ng) {
                const int rB = wn * 64 + ng * 16 + ((t >> 1) * 8) + (lane & 7);
                const uint32_t off = swz((uint32_t)rB * 128 + colB);
                uint32_t bh[4];
                ldsm4(bh[0], bh[1], bh[2], bh[3], bB + off);
#pragma unroll
                for (int mf = 0; mf < 4; ++mf) {
                    mma16816h(acc[mf][2*ng],   ahi[mf], bh);
                    mma16816h(acc[mf][2*ng+1], ahi[mf], bh + 2);
                    if (MODE == 1) {
                        mma16816h(acc[mf][2*ng],   alo[mf], bh);
                        mma16816h(acc[mf][2*ng+1], alo[mf], bh + 2);
                    }
                }
            }
        }
        __syncthreads();
    }

    const int gid = lane >> 2, tig = lane & 3;
    __half* dhi = nullptr;
    if (MODE == 0)
        dhi = (sel == 0) ? g_q1 : (sel == 1) ? g_k1 : g_v1;
#pragma unroll
    for (int mf = 0; mf < 4; ++mf)
#pragma unroll
        for (int nf = 0; nf < 8; ++nf)
#pragma unroll
            for (int half = 0; half < 2; ++half) {
                const int m = m0 + wm * 64 + mf * 16 + gid + half * 8;
                const int n = n0 + wn * 64 + nf * 8 + tig * 2;
                float2 v = make_float2(acc[mf][nf][half*2], acc[mf][nf][half*2+1]);
                if (MODE == 1) {
                    v.x += bias[n]; v.y += bias[n+1];
                    *(float2*)(outf + (size_t)m * D_ + n) = v;
                } else {
                    const int nl = n & (D_ - 1);
                    const int b  = m >> 11;
                    const int s  = m & (S_ - 1);
                    const int h  = nl >> 6;
                    const int dh = nl & (DH_ - 1);
                    const size_t idx = ((size_t)(b * H_ + h) * S_ + s) * DH_ + dh;
                    *(__half2*)(dhi + idx) = __floats2half2_rn(v.x, v.y);
                }
            }
}

// ---------------------------------------------------------------------------
// fp16 HMMA flash attention, causal. BLOCK_M=128, BLOCK_N=64, 256 threads.
// S = Q·K (single) ; O += Pf16·V (single). 3-stage cp.async KV pipeline.
// ctx written as fp16 hi/lo (row-major) for the compensated out-projection.
// ---------------------------------------------------------------------------
#define SM_Q     0                      // 16 KB (q single)
#define SM_KV    16384
#define KV_STG_B 16384                  // K 8K + V 8K
#define ATT_SMEM (16384 + 3*KV_STG_B)   // 65536 B

__global__ __launch_bounds__(256, 1) void attn_tc()
{
    extern __shared__ char smem[];
    const uint32_t sb = smem_u32(smem);
    const int tid  = threadIdx.x;
    const int w    = tid >> 5;
    const int lane = tid & 31;
    const int gid  = lane >> 2;
    const int tig  = lane & 3;
    const int qt   = (int)(gridDim.x - 1 - blockIdx.x);   // heavy tiles first
    const int bh   = blockIdx.y;
    const int q0   = qt * 128;
    const int b    = bh >> 4;
    const int h    = bh & (H_ - 1);
    const int jmax = 2 * qt + 1;        // 64-key tiles: keys [0, q0+128)

    const size_t headoff = (size_t)bh * S_ * DH_;

    auto load_kv = [&](int j, int stg) {
        const uint32_t base = sb + SM_KV + (uint32_t)stg * KV_STG_B;
        const size_t g = headoff + (size_t)j * 64 * DH_;
        const char* srcs[2] = { (const char*)(g_k1 + g),
                                (const char*)(g_v1 + g) };
#pragma unroll
        for (int t = 0; t < 2; ++t) {
#pragma unroll
            for (int it = 0; it < 2; ++it) {
                const int c = tid + it * 256;       // 0..511
                const int r = c >> 3, c16 = c & 7;
                cp16(base + t * 8192 + swz((uint32_t)(r * 128 + c16 * 16)),
                     srcs[t] + r * 128 + c16 * 16);
            }
        }
        cp_commit();
    };

    // group 0: Q tile (single) + kv(0)
    {
        const char* qsrc = (const char*)(g_q1 + headoff + (size_t)q0 * DH_);
#pragma unroll
        for (int it = 0; it < 4; ++it) {
            const int c = tid + it * 256;
            const int r = c >> 3, c16 = c & 7;
            cp16(sb + SM_Q + swz((uint32_t)(r * 128 + c16 * 16)),
                 qsrc + r * 128 + c16 * 16);
        }
    }
    load_kv(0, 0);
    if (1 <= jmax) load_kv(1, 1);

    float m0v = -1e30f, m1v = -1e30f, l0v = 0.f, l1v = 0.f;
    float o[8][4];
#pragma unroll
    for (int i = 0; i < 8; i++)
#pragma unroll
        for (int j = 0; j < 4; j++) o[i][j] = 0.f;

    uint32_t qA[4][4];
    const int qrow0 = q0 + w * 16 + gid;
    const int qrow1 = qrow0 + 8;
    const float SC = 0.18033688011112042f;   // (1/sqrt(64)) * log2(e)
    const int t8 = lane >> 3;

    for (int j = 0; j <= jmax; ++j) {
        if (j + 2 <= jmax) {
            int ns = j + 2; ns = ns - (ns / 3) * 3;
            load_kv(j + 2, ns);
            cp_wait2();
        } else if (j + 1 <= jmax) {
            cp_wait1();
        } else {
            cp_wait0();
        }
        __syncthreads();

        if (j == 0) {   // Q fragments once
            const int rA = w * 16 + (lane & 15);
            const uint32_t colA = (uint32_t)((lane >> 4) * 16);
#pragma unroll
            for (int ks = 0; ks < 4; ++ks) {
                const uint32_t off = swz((uint32_t)rA * 128 + ks * 32 + colA);
                ldsm4(qA[ks][0], qA[ks][1], qA[ks][2], qA[ks][3], sb + SM_Q + off);
            }
        }

        int stg = j - (j / 3) * 3;
        const uint32_t cur = sb + SM_KV + (uint32_t)stg * KV_STG_B;
        const uint32_t KK = cur, VV = cur + 8192;
        const int k0 = j * 64;

        // ---- S = Q @ K^T  (single term) ----
        float sacc[8][4];
#pragma unroll
        for (int i = 0; i < 8; i++)
#pragma unroll
            for (int q = 0; q < 4; q++) sacc[i][q] = 0.f;

#pragma unroll
        for (int ks = 0; ks < 4; ++ks) {
            const uint32_t colB = (uint32_t)(ks * 32 + (t8 & 1) * 16);
#pragma unroll
            for (int ng = 0; ng < 4; ++ng) {
                const int rK = ng * 16 + ((t8 >> 1) * 8) + (lane & 7);
                const uint32_t off = swz((uint32_t)rK * 128 + colB);
                uint32_t kk[4];
                ldsm4(kk[0], kk[1], kk[2], kk[3], KK + off);
                mma16816h(sacc[2*ng],   qA[ks], kk);
                mma16816h(sacc[2*ng+1], qA[ks], kk + 2);
            }
        }

        // ---- scale (+ causal mask on the last two tiles) ----
        if (j >= 2 * qt) {
#pragma unroll
            for (int nf = 0; nf < 8; ++nf) {
                const int col = k0 + nf * 8 + tig * 2;
                sacc[nf][0] = (col     > qrow0) ? -1e30f : sacc[nf][0] * SC;
                sacc[nf][1] = (col + 1 > qrow0) ? -1e30f : sacc[nf][1] * SC;
                sacc[nf][2] = (col     > qrow1) ? -1e30f : sacc[nf][2] * SC;
                sacc[nf][3] = (col + 1 > qrow1) ? -1e30f : sacc[nf][3] * SC;
            }
        } else {
#pragma unroll
            for (int nf = 0; nf < 8; ++nf)
#pragma unroll
                for (int q = 0; q < 4; ++q) sacc[nf][q] *= SC;
        }

        // ---- online softmax ----
        float rm0 = -1e30f, rm1 = -1e30f;
#pragma unroll
        for (int nf = 0; nf < 8; ++nf) {
            rm0 = fmaxf(rm0, fmaxf(sacc[nf][0], sacc[nf][1]));
            rm1 = fmaxf(rm1, fmaxf(sacc[nf][2], sacc[nf][3]));
        }
        rm0 = fmaxf(rm0, __shfl_xor_sync(0xffffffffu, rm0, 1));
        rm0 = fmaxf(rm0, __shfl_xor_sync(0xffffffffu, rm0, 2));
        rm1 = fmaxf(rm1, __shfl_xor_sync(0xffffffffu, rm1, 1));
        rm1 = fmaxf(rm1, __shfl_xor_sync(0xffffffffu, rm1, 2));
        const float mn0 = fmaxf(m0v, rm0);
        const float mn1 = fmaxf(m1v, rm1);
        const float al0 = ex2(m0v - mn0);
        const float al1 = ex2(m1v - mn1);
        float rs0 = 0.f, rs1 = 0.f;
#pragma unroll
        for (int nf = 0; nf < 8; ++nf) {
            sacc[nf][0] = ex2(sacc[nf][0] - mn0);
            sacc[nf][1] = ex2(sacc[nf][1] - mn0);
            sacc[nf][2] = ex2(sacc[nf][2] - mn1);
            sacc[nf][3] = ex2(sacc[nf][3] - mn1);
            rs0 += sacc[nf][0] + sacc[nf][1];
            rs1 += sacc[nf][2] + sacc[nf][3];
        }
        rs0 += __shfl_xor_sync(0xffffffffu, rs0, 1);
        rs0 += __shfl_xor_sync(0xffffffffu, rs0, 2);
        rs1 += __shfl_xor_sync(0xffffffffu, rs1, 1);
        rs1 += __shfl_xor_sync(0xffffffffu, rs1, 2);
        l0v = l0v * al0 + rs0;  m0v = mn0;
        l1v = l1v * al1 + rs1;  m1v = mn1;
#pragma unroll
        for (int nf = 0; nf < 8; ++nf) {
            o[nf][0] *= al0; o[nf][1] *= al0;
            o[nf][2] *= al1; o[nf][3] *= al1;
        }

        // ---- O += P @ V  (P single fp16; V single via trans-ldmatrix) ----
#pragma unroll
        for (int ks2 = 0; ks2 < 4; ++ks2) {
            uint32_t pA[4];
#pragma unroll
            for (int q = 0; q < 4; ++q) {
                const int nf = 2 * ks2 + (q >> 1);
                const int e  = (q & 1) * 2;
                pA[q] = packh(sacc[nf][e], sacc[nf][e + 1]);
            }
            const int kq = ks2 * 16 + (t8 & 1) * 8 + (lane & 7);
#pragma unroll
            for (int og = 0; og < 4; ++og) {
                const uint32_t off = swz((uint32_t)kq * 128 + og * 32 + (t8 >> 1) * 16);
                uint32_t vv[4];
                ldsm4t(vv[0], vv[1], vv[2], vv[3], VV + off);
                mma16816h(o[2*og],   pA, vv);
                mma16816h(o[2*og+1], pA, vv + 2);
            }
        }
        __syncthreads();
    }

    // ---- normalize, write ctx as fp16 hi/lo row-major ----
    const float inv0 = 1.f / l0v;
    const float inv1 = 1.f / l1v;
#pragma unroll
    for (int nf = 0; nf < 8; ++nf) {
        const int dh = nf * 8 + tig * 2;
        {
            const float x = o[nf][0] * inv0, y = o[nf][1] * inv0;
            const __half hx = __float2half_rn(x), hy = __float2half_rn(y);
            *(__half2*)(g_ch + (size_t)(b * S_ + qrow0) * D_ + h * DH_ + dh) =
                __halves2half2(hx, hy);
            *(__half2*)(g_cl + (size_t)(b * S_ + qrow0) * D_ + h * DH_ + dh) =
                __halves2half2(__float2half_rn(x - __half2float(hx)),
                               __float2half_rn(y - __half2float(hy)));
        }
        {
            const float x = o[nf][2] * inv1, y = o[nf][3] * inv1;
            const __half hx = __float2half_rn(x), hy = __float2half_rn(y);
            *(__half2*)(g_ch + (size_t)(b * S_ + qrow1) * D_ + h * DH_ + dh) =
                __halves2half2(hx, hy);
            *(__half2*)(g_cl + (size_t)(b * S_ + qrow1) * D_ + h * DH_ + dh) =
                __halves2half2(__float2half_rn(x - __half2float(hx)),
                               __float2half_rn(y - __half2float(hy)));
        }
    }
}

// ---------------------------------------------------------------------------
extern "C" void kernel_launch(void* const* d_in, const int* in_sizes, int n_in,
                              void* d_out, int out_size)
{
    const float* x  = (const float*)d_in[0];
    const float* Wq = (const float*)d_in[1];
    const float* Wk = (const float*)d_in[2];
    const float* Wv = (const float*)d_in[3];
    const float* Wo = (const float*)d_in[4];
    const float* bo = (const float*)d_in[5];
    float* out = (float*)d_out;

    __half *x16, *w16, *ch, *cl;
    cudaGetSymbolAddress((void**)&x16, g_x16);
    cudaGetSymbolAddress((void**)&w16, g_w16);
    cudaGetSymbolAddress((void**)&ch,  g_ch);
    cudaGetSymbolAddress((void**)&cl,  g_cl);

    cudaFuncSetAttribute(tgemm<0>, cudaFuncAttributeMaxDynamicSharedMemorySize, TG_SMEM0);
    cudaFuncSetAttribute(tgemm<1>, cudaFuncAttributeMaxDynamicSharedMemorySize, TG_SMEM1);
    cudaFuncSetAttribute(attn_tc,  cudaFuncAttributeMaxDynamicSharedMemorySize, ATT_SMEM);

    const int nx = M_ * D_;     // 4M
    const int nw = D_ * D_;     // 1M
    conv_h<<<nx/1024, 256>>>(x, x16);
    conv4_h<<<dim3(nw/1024, 4), 256>>>(Wq, Wk, Wv, Wo, w16);

    // fused QKV projection: N = 3072 against stacked Wq|Wk|Wv (single-term)
    tgemm<0><<<dim3(3*D_/256, M_/128), 256, TG_SMEM0>>>(x16, nullptr, w16,
                                                        nullptr, nullptr);

    attn_tc<<<dim3(S_/128, B_*H_), 256, ATT_SMEM>>>();

    // out-projection: ctx hi/lo, 2-term compensated
    tgemm<1><<<dim3(D_/256, M_/128), 256, TG_SMEM1>>>(ch, cl, w16 + 3*(size_t)nw,
                                                      bo, out);
}

// round 12
// speedup vs baseline: 2.2646x; 1.0819x over previous
#include <cuda_runtime.h>
#include <cuda_bf16.h>
#include <cuda_fp16.h>
#include <cstdint>

// Problem constants
#define B_  2
#define S_  2048
#define D_  1024
#define H_  16
#define DH_ 64
#define M_  (B_*S_)          // 4096 rows total

// ---------------------------------------------------------------------------
// Scratch (allocation-free __device__ globals) — fp16 single everywhere;
// accumulation is always fp32 (MMA C), final out-proj output fp32.
// ---------------------------------------------------------------------------
__device__ __half g_x16[(size_t)M_*D_];
__device__ __half g_w16[(size_t)4*D_*D_];        // Wq|Wk|Wv|Wo
__device__ __half g_q1[(size_t)B_*H_*S_*DH_];    // head-major
__device__ __half g_k1[(size_t)B_*H_*S_*DH_];
__device__ __half g_v1[(size_t)B_*H_*S_*DH_];
__device__ __half g_c1[(size_t)M_*D_];           // ctx, row-major

// ---------------------------------------------------------------------------
// PTX helpers (plain sm_80-class PTX: valid under compute_103)
// ---------------------------------------------------------------------------
__device__ __forceinline__ uint32_t smem_u32(const void* p) {
    uint32_t a;
    asm("{ .reg .u64 t; cvta.to.shared.u64 t, %1; cvt.u32.u64 %0, t; }"
        : "=r"(a) : "l"(p));
    return a;
}
__device__ __forceinline__ void cp16(uint32_t dst, const void* src) {
    asm volatile("cp.async.cg.shared.global [%0], [%1], 16;"
                 :: "r"(dst), "l"(src) : "memory");
}
__device__ __forceinline__ void cp_commit() {
    asm volatile("cp.async.commit_group;" ::: "memory");
}
__device__ __forceinline__ void cp_wait0() {
    asm volatile("cp.async.wait_group 0;" ::: "memory");
}
__device__ __forceinline__ void cp_wait1() {
    asm volatile("cp.async.wait_group 1;" ::: "memory");
}
__device__ __forceinline__ void cp_wait2() {
    asm volatile("cp.async.wait_group 2;" ::: "memory");
}
__device__ __forceinline__ void ldsm4(uint32_t& r0, uint32_t& r1, uint32_t& r2,
                                      uint32_t& r3, uint32_t addr) {
    asm volatile("ldmatrix.sync.aligned.m8n8.x4.shared.b16 {%0,%1,%2,%3}, [%4];"
                 : "=r"(r0), "=r"(r1), "=r"(r2), "=r"(r3) : "r"(addr));
}
__device__ __forceinline__ void ldsm4t(uint32_t& r0, uint32_t& r1, uint32_t& r2,
                                       uint32_t& r3, uint32_t addr) {
    asm volatile("ldmatrix.sync.aligned.m8n8.x4.trans.shared.b16 {%0,%1,%2,%3}, [%4];"
                 : "=r"(r0), "=r"(r1), "=r"(r2), "=r"(r3) : "r"(addr));
}
// fp16 MMA
__device__ __forceinline__ void mma16816h(float* c, const uint32_t* a, const uint32_t* b) {
    asm volatile(
        "mma.sync.aligned.m16n8k16.row.col.f32.f16.f16.f32 "
        "{%0,%1,%2,%3}, {%4,%5,%6,%7}, {%8,%9}, {%0,%1,%2,%3};"
        : "+f"(c[0]), "+f"(c[1]), "+f"(c[2]), "+f"(c[3])
        : "r"(a[0]), "r"(a[1]), "r"(a[2]), "r"(a[3]), "r"(b[0]), "r"(b[1]));
}
__device__ __forceinline__ float ex2(float x) {
    float y; asm("ex2.approx.ftz.f32 %0, %1;" : "=f"(y) : "f"(x)); return y;
}
// Swizzle<3,4,3>: XOR 16B-column bits [6:4] with row bits [9:7]
__device__ __forceinline__ uint32_t swz(uint32_t off) {
    return off ^ ((off >> 3) & 0x70);
}
__device__ __forceinline__ uint32_t packh(float x, float y) {
    __half2 h = __floats2half2_rn(x, y);
    return *(uint32_t*)&h;
}

// ---------------------------------------------------------------------------
// converts: x -> fp16, 4 weight matrices -> fp16
// ---------------------------------------------------------------------------
__global__ void conv_h(const float* __restrict__ src, __half* __restrict__ o)
{
    const size_t i = ((size_t)blockIdx.x * blockDim.x + threadIdx.x) * 4;
    float4 v = *(const float4*)(src + i);
    *(__half2*)(o + i)     = __floats2half2_rn(v.x, v.y);
    *(__half2*)(o + i + 2) = __floats2half2_rn(v.z, v.w);
}

__global__ void conv4_h(const float* __restrict__ a, const float* __restrict__ b,
                        const float* __restrict__ c, const float* __restrict__ d,
                        __half* __restrict__ o)
{
    const int w = blockIdx.y;
    const float* src = (w == 0) ? a : (w == 1) ? b : (w == 2) ? c : d;
    const size_t base = (size_t)w * D_ * D_;
    const size_t i = ((size_t)blockIdx.x * blockDim.x + threadIdx.x) * 4;
    float4 v = *(const float4*)(src + i);
    *(__half2*)(o + base + i)     = __floats2half2_rn(v.x, v.y);
    *(__half2*)(o + base + i + 2) = __floats2half2_rn(v.z, v.w);
}

// ---------------------------------------------------------------------------
// fp16 HMMA GEMM (single-term): 128x256 CTA tile, BK=64, 2-stage, 256 thr,
// 8 warps = 2m x 4n, warp tile 64x64.
// MODE 0 (fused QKV, N=3072): stores single fp16 head-major to q/k/v.
// MODE 1 (out-proj): fp32 out + bias, row-major.
// ---------------------------------------------------------------------------
#define A_TB   16384                 // 128 x 128B
#define B_TB   32768                 // 256 x 128B
#define STAGE  (A_TB + B_TB)         // 48 KB
#define TG_SMEM (2*STAGE)            // 96 KB
#define NCHUNK  (D_/64)              // 16

template<int MODE>
__global__ __launch_bounds__(256, 1) void tgemm(const __half* __restrict__ Ax,
                                                const __half* __restrict__ Bw,
                                                const float* __restrict__ bias,
                                                float* __restrict__ outf)
{
    extern __shared__ char smem[];
    const uint32_t sb = smem_u32(smem);
    const int tid  = threadIdx.x;
    const int wid  = tid >> 5;
    const int lane = tid & 31;
    const int wm   = wid >> 2;
    const int wn   = wid & 3;
    const int m0   = blockIdx.y * 128;
    const int n0   = blockIdx.x * 256;
    const int sel  = n0 >> 10;                    // 0=Q, 1=K, 2=V (MODE 0)

    const char* gA = (const char*)(Ax + (size_t)m0 * D_);
    const char* gB = (const char*)(Bw + (size_t)n0 * D_);

    auto load_stage = [&](int chunk, uint32_t stage) {
        const uint32_t koff = (uint32_t)chunk * 128;
        {
            const char* base = gA + koff;
#pragma unroll
            for (int it = 0; it < 4; ++it) {
                const int c = tid + it * 256;
                const int r = c >> 3, c16 = c & 7;
                cp16(stage + swz((uint32_t)(r * 128 + c16 * 16)),
                     base + (size_t)r * (D_ * 2) + c16 * 16);
            }
        }
        {
            const char* base = gB + koff;
            const uint32_t dstt = stage + A_TB;
#pragma unroll
            for (int it = 0; it < 8; ++it) {
                const int c = tid + it * 256;
                const int r = c >> 3, c16 = c & 7;
                cp16(dstt + swz((uint32_t)(r * 128 + c16 * 16)),
                     base + (size_t)r * (D_ * 2) + c16 * 16);
            }
        }
        cp_commit();
    };

    float acc[4][8][4];
#pragma unroll
    for (int i = 0; i < 4; i++)
#pragma unroll
        for (int j = 0; j < 8; j++)
#pragma unroll
            for (int q = 0; q < 4; q++) acc[i][j][q] = 0.f;

    load_stage(0, sb);

    for (int c = 0; c < NCHUNK; ++c) {
        cp_wait0();
        __syncthreads();
        const uint32_t cur = sb + (c & 1) * STAGE;
        if (c + 1 < NCHUNK) load_stage(c + 1, sb + ((c + 1) & 1) * STAGE);

        const uint32_t aA = cur;
        const uint32_t bB = cur + A_TB;

#pragma unroll
        for (int ks = 0; ks < 4; ++ks) {
            uint32_t af[4][4];
            {
                const int rA = wm * 64 + (lane & 15);
                const uint32_t colA = (uint32_t)(ks * 32 + (lane >> 4) * 16);
#pragma unroll
                for (int mf = 0; mf < 4; ++mf) {
                    const uint32_t off = swz((uint32_t)(rA + mf * 16) * 128 + colA);
                    ldsm4(af[mf][0], af[mf][1], af[mf][2], af[mf][3], aA + off);
                }
            }
            const int t = lane >> 3;
            const uint32_t colB = (uint32_t)(ks * 32 + (t & 1) * 16);
#pragma unroll
            for (int ng = 0; ng < 4; ++ng) {
                const int rB = wn * 64 + ng * 16 + ((t >> 1) * 8) + (lane & 7);
                const uint32_t off = swz((uint32_t)rB * 128 + colB);
                uint32_t bh[4];
                ldsm4(bh[0], bh[1], bh[2], bh[3], bB + off);
#pragma unroll
                for (int mf = 0; mf < 4; ++mf) {
                    mma16816h(acc[mf][2*ng],   af[mf], bh);
                    mma16816h(acc[mf][2*ng+1], af[mf], bh + 2);
                }
            }
        }
        __syncthreads();
    }

    const int gid = lane >> 2, tig = lane & 3;
    __half* dhi = nullptr;
    if (MODE == 0)
        dhi = (sel == 0) ? g_q1 : (sel == 1) ? g_k1 : g_v1;
#pragma unroll
    for (int mf = 0; mf < 4; ++mf)
#pragma unroll
        for (int nf = 0; nf < 8; ++nf)
#pragma unroll
            for (int half = 0; half < 2; ++half) {
                const int m = m0 + wm * 64 + mf * 16 + gid + half * 8;
                const int n = n0 + wn * 64 + nf * 8 + tig * 2;
                float2 v = make_float2(acc[mf][nf][half*2], acc[mf][nf][half*2+1]);
                if (MODE == 1) {
                    v.x += bias[n]; v.y += bias[n+1];
                    *(float2*)(outf + (size_t)m * D_ + n) = v;
                } else {
                    const int nl = n & (D_ - 1);
                    const int b  = m >> 11;
                    const int s  = m & (S_ - 1);
                    const int h  = nl >> 6;
                    const int dh = nl & (DH_ - 1);
                    const size_t idx = ((size_t)(b * H_ + h) * S_ + s) * DH_ + dh;
                    *(__half2*)(dhi + idx) = __floats2half2_rn(v.x, v.y);
                }
            }
}

// ---------------------------------------------------------------------------
// fp16 HMMA flash attention, causal. BLOCK_M=128, BLOCK_N=64, 256 threads,
// 2 CTAs/SM (128-reg cap). S = Q·K ; O += Pf16·V. 3-stage cp.async pipeline.
// ctx written single fp16 row-major.
// ---------------------------------------------------------------------------
#define SM_Q     0                      // 16 KB (q single)
#define SM_KV    16384
#define KV_STG_B 16384                  // K 8K + V 8K
#define ATT_SMEM (16384 + 3*KV_STG_B)   // 65536 B

__global__ __launch_bounds__(256, 2) void attn_tc()
{
    extern __shared__ char smem[];
    const uint32_t sb = smem_u32(smem);
    const int tid  = threadIdx.x;
    const int w    = tid >> 5;
    const int lane = tid & 31;
    const int gid  = lane >> 2;
    const int tig  = lane & 3;
    const int qt   = (int)(gridDim.x - 1 - blockIdx.x);   // heavy tiles first
    const int bh   = blockIdx.y;
    const int q0   = qt * 128;
    const int b    = bh >> 4;
    const int h    = bh & (H_ - 1);
    const int jmax = 2 * qt + 1;        // 64-key tiles: keys [0, q0+128)

    const size_t headoff = (size_t)bh * S_ * DH_;

    auto load_kv = [&](int j, int stg) {
        const uint32_t base = sb + SM_KV + (uint32_t)stg * KV_STG_B;
        const size_t g = headoff + (size_t)j * 64 * DH_;
        const char* srcs[2] = { (const char*)(g_k1 + g),
                                (const char*)(g_v1 + g) };
#pragma unroll
        for (int t = 0; t < 2; ++t) {
#pragma unroll
            for (int it = 0; it < 2; ++it) {
                const int c = tid + it * 256;       // 0..511
                const int r = c >> 3, c16 = c & 7;
                cp16(base + t * 8192 + swz((uint32_t)(r * 128 + c16 * 16)),
                     srcs[t] + r * 128 + c16 * 16);
            }
        }
        cp_commit();
    };

    // group 0: Q tile (single) + kv(0)
    {
        const char* qsrc = (const char*)(g_q1 + headoff + (size_t)q0 * DH_);
#pragma unroll
        for (int it = 0; it < 4; ++it) {
            const int c = tid + it * 256;
            const int r = c >> 3, c16 = c & 7;
            cp16(sb + SM_Q + swz((uint32_t)(r * 128 + c16 * 16)),
                 qsrc + r * 128 + c16 * 16);
        }
    }
    load_kv(0, 0);
    if (1 <= jmax) load_kv(1, 1);

    float m0v = -1e30f, m1v = -1e30f, l0v = 0.f, l1v = 0.f;
    float o[8][4];
#pragma unroll
    for (int i = 0; i < 8; i++)
#pragma unroll
        for (int j = 0; j < 4; j++) o[i][j] = 0.f;

    uint32_t qA[4][4];
    const int qrow0 = q0 + w * 16 + gid;
    const int qrow1 = qrow0 + 8;
    const float SC = 0.18033688011112042f;   // (1/sqrt(64)) * log2(e)
    const int t8 = lane >> 3;

    for (int j = 0; j <= jmax; ++j) {
        if (j + 2 <= jmax) {
            int ns = j + 2; ns = ns - (ns / 3) * 3;
            load_kv(j + 2, ns);
            cp_wait2();
        } else if (j + 1 <= jmax) {
            cp_wait1();
        } else {
            cp_wait0();
        }
        __syncthreads();

        if (j == 0) {   // Q fragments once
            const int rA = w * 16 + (lane & 15);
            const uint32_t colA = (uint32_t)((lane >> 4) * 16);
#pragma unroll
            for (int ks = 0; ks < 4; ++ks) {
                const uint32_t off = swz((uint32_t)rA * 128 + ks * 32 + colA);
                ldsm4(qA[ks][0], qA[ks][1], qA[ks][2], qA[ks][3], sb + SM_Q + off);
            }
        }

        int stg = j - (j / 3) * 3;
        const uint32_t cur = sb + SM_KV + (uint32_t)stg * KV_STG_B;
        const uint32_t KK = cur, VV = cur + 8192;
        const int k0 = j * 64;

        // ---- S = Q @ K^T  (single term) ----
        float sacc[8][4];
#pragma unroll
        for (int i = 0; i < 8; i++)
#pragma unroll
            for (int q = 0; q < 4; q++) sacc[i][q] = 0.f;

#pragma unroll
        for (int ks = 0; ks < 4; ++ks) {
            const uint32_t colB = (uint32_t)(ks * 32 + (t8 & 1) * 16);
#pragma unroll
            for (int ng = 0; ng < 4; ++ng) {
                const int rK = ng * 16 + ((t8 >> 1) * 8) + (lane & 7);
                const uint32_t off = swz((uint32_t)rK * 128 + colB);
                uint32_t kk[4];
                ldsm4(kk[0], kk[1], kk[2], kk[3], KK + off);
                mma16816h(sacc[2*ng],   qA[ks], kk);
                mma16816h(sacc[2*ng+1], qA[ks], kk + 2);
            }
        }

        // ---- scale (+ causal mask on the last two tiles) ----
        if (j >= 2 * qt) {
#pragma unroll
            for (int nf = 0; nf < 8; ++nf) {
                const int col = k0 + nf * 8 + tig * 2;
                sacc[nf][0] = (col     > qrow0) ? -1e30f : sacc[nf][0] * SC;
                sacc[nf][1] = (col + 1 > qrow0) ? -1e30f : sacc[nf][1] * SC;
                sacc[nf][2] = (col     > qrow1) ? -1e30f : sacc[nf][2] * SC;
                sacc[nf][3] = (col + 1 > qrow1) ? -1e30f : sacc[nf][3] * SC;
            }
        } else {
#pragma unroll
            for (int nf = 0; nf < 8; ++nf)
#pragma unroll
                for (int q = 0; q < 4; ++q) sacc[nf][q] *= SC;
        }

        // ---- online softmax ----
        float rm0 = -1e30f, rm1 = -1e30f;
#pragma unroll
        for (int nf = 0; nf < 8; ++nf) {
            rm0 = fmaxf(rm0, fmaxf(sacc[nf][0], sacc[nf][1]));
            rm1 = fmaxf(rm1, fmaxf(sacc[nf][2], sacc[nf][3]));
        }
        rm0 = fmaxf(rm0, __shfl_xor_sync(0xffffffffu, rm0, 1));
        rm0 = fmaxf(rm0, __shfl_xor_sync(0xffffffffu, rm0, 2));
        rm1 = fmaxf(rm1, __shfl_xor_sync(0xffffffffu, rm1, 1));
        rm1 = fmaxf(rm1, __shfl_xor_sync(0xffffffffu, rm1, 2));
        const float mn0 = fmaxf(m0v, rm0);
        const float mn1 = fmaxf(m1v, rm1);
        const float al0 = ex2(m0v - mn0);
        const float al1 = ex2(m1v - mn1);
        float rs0 = 0.f, rs1 = 0.f;
#pragma unroll
        for (int nf = 0; nf < 8; ++nf) {
            sacc[nf][0] = ex2(sacc[nf][0] - mn0);
            sacc[nf][1] = ex2(sacc[nf][1] - mn0);
            sacc[nf][2] = ex2(sacc[nf][2] - mn1);
            sacc[nf][3] = ex2(sacc[nf][3] - mn1);
            rs0 += sacc[nf][0] + sacc[nf][1];
            rs1 += sacc[nf][2] + sacc[nf][3];
        }
        rs0 += __shfl_xor_sync(0xffffffffu, rs0, 1);
        rs0 += __shfl_xor_sync(0xffffffffu, rs0, 2);
        rs1 += __shfl_xor_sync(0xffffffffu, rs1, 1);
        rs1 += __shfl_xor_sync(0xffffffffu, rs1, 2);
        l0v = l0v * al0 + rs0;  m0v = mn0;
        l1v = l1v * al1 + rs1;  m1v = mn1;
#pragma unroll
        for (int nf = 0; nf < 8; ++nf) {
            o[nf][0] *= al0; o[nf][1] *= al0;
            o[nf][2] *= al1; o[nf][3] *= al1;
        }

        // ---- O += P @ V  (P single fp16; V single via trans-ldmatrix) ----
#pragma unroll
        for (int ks2 = 0; ks2 < 4; ++ks2) {
            uint32_t pA[4];
#pragma unroll
            for (int q = 0; q < 4; ++q) {
                const int nf = 2 * ks2 + (q >> 1);
                const int e  = (q & 1) * 2;
                pA[q] = packh(sacc[nf][e], sacc[nf][e + 1]);
            }
            const int kq = ks2 * 16 + (t8 & 1) * 8 + (lane & 7);
#pragma unroll
            for (int og = 0; og < 4; ++og) {
                const uint32_t off = swz((uint32_t)kq * 128 + og * 32 + (t8 >> 1) * 16);
                uint32_t vv[4];
                ldsm4t(vv[0], vv[1], vv[2], vv[3], VV + off);
                mma16816h(o[2*og],   pA, vv);
                mma16816h(o[2*og+1], pA, vv + 2);
            }
        }
        __syncthreads();
    }

    // ---- normalize, write ctx single fp16 row-major ----
    const float inv0 = 1.f / l0v;
    const float inv1 = 1.f / l1v;
#pragma unroll
    for (int nf = 0; nf < 8; ++nf) {
        const int dh = nf * 8 + tig * 2;
        *(__half2*)(g_c1 + (size_t)(b * S_ + qrow0) * D_ + h * DH_ + dh) =
            __floats2half2_rn(o[nf][0] * inv0, o[nf][1] * inv0);
        *(__half2*)(g_c1 + (size_t)(b * S_ + qrow1) * D_ + h * DH_ + dh) =
            __floats2half2_rn(o[nf][2] * inv1, o[nf][3] * inv1);
    }
}

// ---------------------------------------------------------------------------
extern "C" void kernel_launch(void* const* d_in, const int* in_sizes, int n_in,
                              void* d_out, int out_size)
{
    const float* x  = (const float*)d_in[0];
    const float* Wq = (const float*)d_in[1];
    const float* Wk = (const float*)d_in[2];
    const float* Wv = (const float*)d_in[3];
    const float* Wo = (const float*)d_in[4];
    const float* bo = (const float*)d_in[5];
    float* out = (float*)d_out;

    __half *x16, *w16, *c1;
    cudaGetSymbolAddress((void**)&x16, g_x16);
    cudaGetSymbolAddress((void**)&w16, g_w16);
    cudaGetSymbolAddress((void**)&c1,  g_c1);

    cudaFuncSetAttribute(tgemm<0>, cudaFuncAttributeMaxDynamicSharedMemorySize, TG_SMEM);
    cudaFuncSetAttribute(tgemm<1>, cudaFuncAttributeMaxDynamicSharedMemorySize, TG_SMEM);
    cudaFuncSetAttribute(attn_tc,  cudaFuncAttributeMaxDynamicSharedMemorySize, ATT_SMEM);

    const int nx = M_ * D_;     // 4M
    const int nw = D_ * D_;     // 1M
    conv_h<<<nx/1024, 256>>>(x, x16);
    conv4_h<<<dim3(nw/1024, 4), 256>>>(Wq, Wk, Wv, Wo, w16);

    // fused QKV projection: N = 3072 against stacked Wq|Wk|Wv (single-term)
    tgemm<0><<<dim3(3*D_/256, M_/128), 256, TG_SMEM>>>(x16, w16, nullptr, nullptr);

    attn_tc<<<dim3(S_/128, B_*H_), 256, ATT_SMEM>>>();

    // out-projection (single-term): ctx @ Wo^T + bias
    tgemm<1><<<dim3(D_/256, M_/128), 256, TG_SMEM>>>(c1, w16 + 3*(size_t)nw,
                                                     bo, out);
}

// round 13
// speedup vs baseline: 2.2874x; 1.0101x over previous
#include <cuda_runtime.h>
#include <cuda_bf16.h>
#include <cuda_fp16.h>
#include <cstdint>

// Problem constants
#define B_  2
#define S_  2048
#define D_  1024
#define H_  16
#define DH_ 64
#define M_  (B_*S_)          // 4096 rows total

// ---------------------------------------------------------------------------
// Scratch (allocation-free __device__ globals) — fp16 single everywhere;
// accumulation is always fp32 (MMA C), final out-proj output fp32.
// Q is stored PRE-SCALED by (1/sqrt(DH))*log2(e).
// ---------------------------------------------------------------------------
__device__ __half g_x16[(size_t)M_*D_];
__device__ __half g_w16[(size_t)4*D_*D_];        // Wq|Wk|Wv|Wo
__device__ __half g_q1[(size_t)B_*H_*S_*DH_];    // head-major, pre-scaled
__device__ __half g_k1[(size_t)B_*H_*S_*DH_];
__device__ __half g_v1[(size_t)B_*H_*S_*DH_];
__device__ __half g_c1[(size_t)M_*D_];           // ctx, row-major

// ---------------------------------------------------------------------------
// PTX helpers (plain sm_80-class PTX: valid under compute_103)
// ---------------------------------------------------------------------------
__device__ __forceinline__ uint32_t smem_u32(const void* p) {
    uint32_t a;
    asm("{ .reg .u64 t; cvta.to.shared.u64 t, %1; cvt.u32.u64 %0, t; }"
        : "=r"(a) : "l"(p));
    return a;
}
__device__ __forceinline__ void cp16(uint32_t dst, const void* src) {
    asm volatile("cp.async.cg.shared.global [%0], [%1], 16;"
                 :: "r"(dst), "l"(src) : "memory");
}
__device__ __forceinline__ void cp_commit() {
    asm volatile("cp.async.commit_group;" ::: "memory");
}
__device__ __forceinline__ void cp_wait0() {
    asm volatile("cp.async.wait_group 0;" ::: "memory");
}
__device__ __forceinline__ void cp_wait1() {
    asm volatile("cp.async.wait_group 1;" ::: "memory");
}
__device__ __forceinline__ void cp_wait2() {
    asm volatile("cp.async.wait_group 2;" ::: "memory");
}
__device__ __forceinline__ void ldsm4(uint32_t& r0, uint32_t& r1, uint32_t& r2,
                                      uint32_t& r3, uint32_t addr) {
    asm volatile("ldmatrix.sync.aligned.m8n8.x4.shared.b16 {%0,%1,%2,%3}, [%4];"
                 : "=r"(r0), "=r"(r1), "=r"(r2), "=r"(r3) : "r"(addr));
}
__device__ __forceinline__ void ldsm4t(uint32_t& r0, uint32_t& r1, uint32_t& r2,
                                       uint32_t& r3, uint32_t addr) {
    asm volatile("ldmatrix.sync.aligned.m8n8.x4.trans.shared.b16 {%0,%1,%2,%3}, [%4];"
                 : "=r"(r0), "=r"(r1), "=r"(r2), "=r"(r3) : "r"(addr));
}
// fp16 MMA
__device__ __forceinline__ void mma16816h(float* c, const uint32_t* a, const uint32_t* b) {
    asm volatile(
        "mma.sync.aligned.m16n8k16.row.col.f32.f16.f16.f32 "
        "{%0,%1,%2,%3}, {%4,%5,%6,%7}, {%8,%9}, {%0,%1,%2,%3};"
        : "+f"(c[0]), "+f"(c[1]), "+f"(c[2]), "+f"(c[3])
        : "r"(a[0]), "r"(a[1]), "r"(a[2]), "r"(a[3]), "r"(b[0]), "r"(b[1]));
}
__device__ __forceinline__ float ex2(float x) {
    float y; asm("ex2.approx.ftz.f32 %0, %1;" : "=f"(y) : "f"(x)); return y;
}
// Swizzle<3,4,3>: XOR 16B-column bits [6:4] with row bits [9:7]
__device__ __forceinline__ uint32_t swz(uint32_t off) {
    return off ^ ((off >> 3) & 0x70);
}
__device__ __forceinline__ uint32_t packh(float x, float y) {
    __half2 h = __floats2half2_rn(x, y);
    return *(uint32_t*)&h;
}

// ---------------------------------------------------------------------------
// single merged convert: y<4 -> weight y; y>=4 -> x quarter (y-4). 1M elems each.
// ---------------------------------------------------------------------------
__global__ void convall(const float* __restrict__ x,
                        const float* __restrict__ a, const float* __restrict__ b,
                        const float* __restrict__ c, const float* __restrict__ d,
                        __half* __restrict__ x16, __half* __restrict__ w16)
{
    const int y = blockIdx.y;
    const size_t off = ((size_t)blockIdx.x * blockDim.x + threadIdx.x) * 4;
    const float* src;
    __half* dst;
    size_t base;
    if (y < 4) {
        src = (y == 0) ? a : (y == 1) ? b : (y == 2) ? c : d;
        dst = w16; base = (size_t)y * D_ * D_;
        float4 v = *(const float4*)(src + off);
        *(__half2*)(dst + base + off)     = __floats2half2_rn(v.x, v.y);
        *(__half2*)(dst + base + off + 2) = __floats2half2_rn(v.z, v.w);
    } else {
        base = (size_t)(y - 4) * D_ * D_;
        float4 v = *(const float4*)(x + base + off);
        *(__half2*)(x16 + base + off)     = __floats2half2_rn(v.x, v.y);
        *(__half2*)(x16 + base + off + 2) = __floats2half2_rn(v.z, v.w);
    }
}

// ---------------------------------------------------------------------------
// fp16 HMMA GEMM (single-term): 128x256 CTA tile, BK=64, 2-stage, 256 thr,
// 8 warps = 2m x 4n, warp tile 64x64.
// MODE 0 (fused QKV, N=3072): stores single fp16 head-major to q/k/v;
//                             Q block pre-scaled by (1/8)*log2(e).
// MODE 1 (out-proj): fp32 out + bias, row-major.
// ---------------------------------------------------------------------------
#define A_TB   16384                 // 128 x 128B
#define B_TB   32768                 // 256 x 128B
#define STAGE  (A_TB + B_TB)         // 48 KB
#define TG_SMEM (2*STAGE)            // 96 KB
#define NCHUNK  (D_/64)              // 16

template<int MODE>
__global__ __launch_bounds__(256, 1) void tgemm(const __half* __restrict__ Ax,
                                                const __half* __restrict__ Bw,
                                                const float* __restrict__ bias,
                                                float* __restrict__ outf)
{
    extern __shared__ char smem[];
    const uint32_t sb = smem_u32(smem);
    const int tid  = threadIdx.x;
    const int wid  = tid >> 5;
    const int lane = tid & 31;
    const int wm   = wid >> 2;
    const int wn   = wid & 3;
    const int m0   = blockIdx.y * 128;
    const int n0   = blockIdx.x * 256;
    const int sel  = n0 >> 10;                    // 0=Q, 1=K, 2=V (MODE 0)

    const char* gA = (const char*)(Ax + (size_t)m0 * D_);
    const char* gB = (const char*)(Bw + (size_t)n0 * D_);

    auto load_stage = [&](int chunk, uint32_t stage) {
        const uint32_t koff = (uint32_t)chunk * 128;
        {
            const char* base = gA + koff;
#pragma unroll
            for (int it = 0; it < 4; ++it) {
                const int c = tid + it * 256;
                const int r = c >> 3, c16 = c & 7;
                cp16(stage + swz((uint32_t)(r * 128 + c16 * 16)),
                     base + (size_t)r * (D_ * 2) + c16 * 16);
            }
        }
        {
            const char* base = gB + koff;
            const uint32_t dstt = stage + A_TB;
#pragma unroll
            for (int it = 0; it < 8; ++it) {
                const int c = tid + it * 256;
                const int r = c >> 3, c16 = c & 7;
                cp16(dstt + swz((uint32_t)(r * 128 + c16 * 16)),
                     base + (size_t)r * (D_ * 2) + c16 * 16);
            }
        }
        cp_commit();
    };

    float acc[4][8][4];
#pragma unroll
    for (int i = 0; i < 4; i++)
#pragma unroll
        for (int j = 0; j < 8; j++)
#pragma unroll
            for (int q = 0; q < 4; q++) acc[i][j][q] = 0.f;

    load_stage(0, sb);

    for (int c = 0; c < NCHUNK; ++c) {
        cp_wait0();
        __syncthreads();
        const uint32_t cur = sb + (c & 1) * STAGE;
        if (c + 1 < NCHUNK) load_stage(c + 1, sb + ((c + 1) & 1) * STAGE);

        const uint32_t aA = cur;
        const uint32_t bB = cur + A_TB;

#pragma unroll
        for (int ks = 0; ks < 4; ++ks) {
            uint32_t af[4][4];
            {
                const int rA = wm * 64 + (lane & 15);
                const uint32_t colA = (uint32_t)(ks * 32 + (lane >> 4) * 16);
#pragma unroll
                for (int mf = 0; mf < 4; ++mf) {
                    const uint32_t off = swz((uint32_t)(rA + mf * 16) * 128 + colA);
                    ldsm4(af[mf][0], af[mf][1], af[mf][2], af[mf][3], aA + off);
                }
            }
            const int t = lane >> 3;
            const uint32_t colB = (uint32_t)(ks * 32 + (t & 1) * 16);
#pragma unroll
            for (int ng = 0; ng < 4; ++ng) {
                const int rB = wn * 64 + ng * 16 + ((t >> 1) * 8) + (lane & 7);
                const uint32_t off = swz((uint32_t)rB * 128 + colB);
                uint32_t bh[4];
                ldsm4(bh[0], bh[1], bh[2], bh[3], bB + off);
#pragma unroll
                for (int mf = 0; mf < 4; ++mf) {
                    mma16816h(acc[mf][2*ng],   af[mf], bh);
                    mma16816h(acc[mf][2*ng+1], af[mf], bh + 2);
                }
            }
        }
        __syncthreads();
    }

    const int gid = lane >> 2, tig = lane & 3;
    __half* dhi = nullptr;
    float sq = 1.f;
    if (MODE == 0) {
        dhi = (sel == 0) ? g_q1 : (sel == 1) ? g_k1 : g_v1;
        if (sel == 0) sq = 0.18033688011112042f;   // (1/sqrt(64)) * log2(e)
    }
#pragma unroll
    for (int mf = 0; mf < 4; ++mf)
#pragma unroll
        for (int nf = 0; nf < 8; ++nf)
#pragma unroll
            for (int half = 0; half < 2; ++half) {
                const int m = m0 + wm * 64 + mf * 16 + gid + half * 8;
                const int n = n0 + wn * 64 + nf * 8 + tig * 2;
                float2 v = make_float2(acc[mf][nf][half*2], acc[mf][nf][half*2+1]);
                if (MODE == 1) {
                    v.x += bias[n]; v.y += bias[n+1];
                    *(float2*)(outf + (size_t)m * D_ + n) = v;
                } else {
                    const int nl = n & (D_ - 1);
                    const int b  = m >> 11;
                    const int s  = m & (S_ - 1);
                    const int h  = nl >> 6;
                    const int dh = nl & (DH_ - 1);
                    const size_t idx = ((size_t)(b * H_ + h) * S_ + s) * DH_ + dh;
                    *(__half2*)(dhi + idx) = __floats2half2_rn(v.x * sq, v.y * sq);
                }
            }
}

// ---------------------------------------------------------------------------
// fp16 HMMA flash attention, causal. BLOCK_M=128, BLOCK_N=64, 256 threads,
// 2 CTAs/SM. Q pre-scaled (no per-tile scale pass); o-rescale skipped when
// the running max is unchanged (exact). 3-stage cp.async KV pipeline.
// ---------------------------------------------------------------------------
#define SM_Q     0                      // 16 KB (q single)
#define SM_KV    16384
#define KV_STG_B 16384                  // K 8K + V 8K
#define ATT_SMEM (16384 + 3*KV_STG_B)   // 65536 B

__global__ __launch_bounds__(256, 2) void attn_tc()
{
    extern __shared__ char smem[];
    const uint32_t sb = smem_u32(smem);
    const int tid  = threadIdx.x;
    const int w    = tid >> 5;
    const int lane = tid & 31;
    const int gid  = lane >> 2;
    const int tig  = lane & 3;
    const int qt   = (int)(gridDim.x - 1 - blockIdx.x);   // heavy tiles first
    const int bh   = blockIdx.y;
    const int q0   = qt * 128;
    const int b    = bh >> 4;
    const int h    = bh & (H_ - 1);
    const int jmax = 2 * qt + 1;        // 64-key tiles: keys [0, q0+128)

    const size_t headoff = (size_t)bh * S_ * DH_;

    auto load_kv = [&](int j, int stg) {
        const uint32_t base = sb + SM_KV + (uint32_t)stg * KV_STG_B;
        const size_t g = headoff + (size_t)j * 64 * DH_;
        const char* srcs[2] = { (const char*)(g_k1 + g),
                                (const char*)(g_v1 + g) };
#pragma unroll
        for (int t = 0; t < 2; ++t) {
#pragma unroll
            for (int it = 0; it < 2; ++it) {
                const int c = tid + it * 256;       // 0..511
                const int r = c >> 3, c16 = c & 7;
                cp16(base + t * 8192 + swz((uint32_t)(r * 128 + c16 * 16)),
                     srcs[t] + r * 128 + c16 * 16);
            }
        }
        cp_commit();
    };

    // group 0: Q tile (single, pre-scaled) + kv(0)
    {
        const char* qsrc = (const char*)(g_q1 + headoff + (size_t)q0 * DH_);
#pragma unroll
        for (int it = 0; it < 4; ++it) {
            const int c = tid + it * 256;
            const int r = c >> 3, c16 = c & 7;
            cp16(sb + SM_Q + swz((uint32_t)(r * 128 + c16 * 16)),
                 qsrc + r * 128 + c16 * 16);
        }
    }
    load_kv(0, 0);
    if (1 <= jmax) load_kv(1, 1);

    float m0v = -1e30f, m1v = -1e30f, l0v = 0.f, l1v = 0.f;
    float o[8][4];
#pragma unroll
    for (int i = 0; i < 8; i++)
#pragma unroll
        for (int j = 0; j < 4; j++) o[i][j] = 0.f;

    uint32_t qA[4][4];
    const int qrow0 = q0 + w * 16 + gid;
    const int qrow1 = qrow0 + 8;
    const int t8 = lane >> 3;

    for (int j = 0; j <= jmax; ++j) {
        if (j + 2 <= jmax) {
            int ns = j + 2; ns = ns - (ns / 3) * 3;
            load_kv(j + 2, ns);
            cp_wait2();
        } else if (j + 1 <= jmax) {
            cp_wait1();
        } else {
            cp_wait0();
        }
        __syncthreads();

        if (j == 0) {   // Q fragments once
            const int rA = w * 16 + (lane & 15);
            const uint32_t colA = (uint32_t)((lane >> 4) * 16);
#pragma unroll
            for (int ks = 0; ks < 4; ++ks) {
                const uint32_t off = swz((uint32_t)rA * 128 + ks * 32 + colA);
                ldsm4(qA[ks][0], qA[ks][1], qA[ks][2], qA[ks][3], sb + SM_Q + off);
            }
        }

        int stg = j - (j / 3) * 3;
        const uint32_t cur = sb + SM_KV + (uint32_t)stg * KV_STG_B;
        const uint32_t KK = cur, VV = cur + 8192;
        const int k0 = j * 64;

        // ---- S = Q @ K^T  (already in log2 domain; Q pre-scaled) ----
        float sacc[8][4];
#pragma unroll
        for (int i = 0; i < 8; i++)
#pragma unroll
            for (int q = 0; q < 4; q++) sacc[i][q] = 0.f;

#pragma unroll
        for (int ks = 0; ks < 4; ++ks) {
            const uint32_t colB = (uint32_t)(ks * 32 + (t8 & 1) * 16);
#pragma unroll
            for (int ng = 0; ng < 4; ++ng) {
                const int rK = ng * 16 + ((t8 >> 1) * 8) + (lane & 7);
                const uint32_t off = swz((uint32_t)rK * 128 + colB);
                uint32_t kk[4];
                ldsm4(kk[0], kk[1], kk[2], kk[3], KK + off);
                mma16816h(sacc[2*ng],   qA[ks], kk);
                mma16816h(sacc[2*ng+1], qA[ks], kk + 2);
            }
        }

        // ---- causal mask (only the last two tiles touch the diagonal) ----
        if (j >= 2 * qt) {
#pragma unroll
            for (int nf = 0; nf < 8; ++nf) {
                const int col = k0 + nf * 8 + tig * 2;
                if (col     > qrow0) sacc[nf][0] = -1e30f;
                if (col + 1 > qrow0) sacc[nf][1] = -1e30f;
                if (col     > qrow1) sacc[nf][2] = -1e30f;
                if (col + 1 > qrow1) sacc[nf][3] = -1e30f;
            }
        }

        // ---- online softmax ----
        float rm0 = -1e30f, rm1 = -1e30f;
#pragma unroll
        for (int nf = 0; nf < 8; ++nf) {
            rm0 = fmaxf(rm0, fmaxf(sacc[nf][0], sacc[nf][1]));
            rm1 = fmaxf(rm1, fmaxf(sacc[nf][2], sacc[nf][3]));
        }
        rm0 = fmaxf(rm0, __shfl_xor_sync(0xffffffffu, rm0, 1));
        rm0 = fmaxf(rm0, __shfl_xor_sync(0xffffffffu, rm0, 2));
        rm1 = fmaxf(rm1, __shfl_xor_sync(0xffffffffu, rm1, 1));
        rm1 = fmaxf(rm1, __shfl_xor_sync(0xffffffffu, rm1, 2));
        const float mn0 = fmaxf(m0v, rm0);
        const float mn1 = fmaxf(m1v, rm1);
        const bool up0 = (mn0 > m0v);
        const bool up1 = (mn1 > m1v);
        const float al0 = up0 ? ex2(m0v - mn0) : 1.f;
        const float al1 = up1 ? ex2(m1v - mn1) : 1.f;
        float rs0 = 0.f, rs1 = 0.f;
#pragma unroll
        for (int nf = 0; nf < 8; ++nf) {
            sacc[nf][0] = ex2(sacc[nf][0] - mn0);
            sacc[nf][1] = ex2(sacc[nf][1] - mn0);
            sacc[nf][2] = ex2(sacc[nf][2] - mn1);
            sacc[nf][3] = ex2(sacc[nf][3] - mn1);
            rs0 += sacc[nf][0] + sacc[nf][1];
            rs1 += sacc[nf][2] + sacc[nf][3];
        }
        rs0 += __shfl_xor_sync(0xffffffffu, rs0, 1);
        rs0 += __shfl_xor_sync(0xffffffffu, rs0, 2);
        rs1 += __shfl_xor_sync(0xffffffffu, rs1, 1);
        rs1 += __shfl_xor_sync(0xffffffffu, rs1, 2);
        l0v = l0v * al0 + rs0;  m0v = mn0;
        l1v = l1v * al1 + rs1;  m1v = mn1;
        if (up0) {
#pragma unroll
            for (int nf = 0; nf < 8; ++nf) { o[nf][0] *= al0; o[nf][1] *= al0; }
        }
        if (up1) {
#pragma unroll
            for (int nf = 0; nf < 8; ++nf) { o[nf][2] *= al1; o[nf][3] *= al1; }
        }

        // ---- O += P @ V  (P single fp16; V single via trans-ldmatrix) ----
#pragma unroll
        for (int ks2 = 0; ks2 < 4; ++ks2) {
            uint32_t pA[4];
#pragma unroll
            for (int q = 0; q < 4; ++q) {
                const int nf = 2 * ks2 + (q >> 1);
                const int e  = (q & 1) * 2;
                pA[q] = packh(sacc[nf][e], sacc[nf][e + 1]);
            }
            const int kq = ks2 * 16 + (t8 & 1) * 8 + (lane & 7);
#pragma unroll
            for (int og = 0; og < 4; ++og) {
                const uint32_t off = swz((uint32_t)kq * 128 + og * 32 + (t8 >> 1) * 16);
                uint32_t vv[4];
                ldsm4t(vv[0], vv[1], vv[2], vv[3], VV + off);
                mma16816h(o[2*og],   pA, vv);
                mma16816h(o[2*og+1], pA, vv + 2);
            }
        }
        __syncthreads();
    }

    // ---- normalize, write ctx single fp16 row-major ----
    const float inv0 = 1.f / l0v;
    const float inv1 = 1.f / l1v;
#pragma unroll
    for (int nf = 0; nf < 8; ++nf) {
        const int dh = nf * 8 + tig * 2;
        *(__half2*)(g_c1 + (size_t)(b * S_ + qrow0) * D_ + h * DH_ + dh) =
            __floats2half2_rn(o[nf][0] * inv0, o[nf][1] * inv0);
        *(__half2*)(g_c1 + (size_t)(b * S_ + qrow1) * D_ + h * DH_ + dh) =
            __floats2half2_rn(o[nf][2] * inv1, o[nf][3] * inv1);
    }
}

// ---------------------------------------------------------------------------
extern "C" void kernel_launch(void* const* d_in, const int* in_sizes, int n_in,
                              void* d_out, int out_size)
{
    const float* x  = (const float*)d_in[0];
    const float* Wq = (const float*)d_in[1];
    const float* Wk = (const float*)d_in[2];
    const float* Wv = (const float*)d_in[3];
    const float* Wo = (const float*)d_in[4];
    const float* bo = (const float*)d_in[5];
    float* out = (float*)d_out;

    __half *x16, *w16, *c1;
    cudaGetSymbolAddress((void**)&x16, g_x16);
    cudaGetSymbolAddress((void**)&w16, g_w16);
    cudaGetSymbolAddress((void**)&c1,  g_c1);

    cudaFuncSetAttribute(tgemm<0>, cudaFuncAttributeMaxDynamicSharedMemorySize, TG_SMEM);
    cudaFuncSetAttribute(tgemm<1>, cudaFuncAttributeMaxDynamicSharedMemorySize, TG_SMEM);
    cudaFuncSetAttribute(attn_tc,  cudaFuncAttributeMaxDynamicSharedMemorySize, ATT_SMEM);

    const int n1m = D_ * D_;    // 1M elems
    convall<<<dim3(n1m/1024, 8), 256>>>(x, Wq, Wk, Wv, Wo, x16, w16);

    // fused QKV projection: N = 3072 against stacked Wq|Wk|Wv (single-term)
    tgemm<0><<<dim3(3*D_/256, M_/128), 256, TG_SMEM>>>(x16, w16, nullptr, nullptr);

    attn_tc<<<dim3(S_/128, B_*H_), 256, ATT_SMEM>>>();

    // out-projection (single-term): ctx @ Wo^T + bias
    tgemm<1><<<dim3(D_/256, M_/128), 256, TG_SMEM>>>(c1, w16 + 3*(size_t)n1m,
                                                     bo, out);
}

// round 15
// speedup vs baseline: 2.3619x; 1.0326x over previous
#include <cuda_runtime.h>
#include <cuda_bf16.h>
#include <cuda_fp16.h>
#include <cstdint>

// Problem constants
#define B_  2
#define S_  2048
#define D_  1024
#define H_  16
#define DH_ 64
#define M_  (B_*S_)          // 4096 rows total

// ---------------------------------------------------------------------------
// Scratch (allocation-free __device__ globals) — fp16 single everywhere;
// accumulation is always fp32 (MMA C), final out-proj output fp32.
// Q is stored PRE-SCALED by (1/sqrt(DH))*log2(e).
// ---------------------------------------------------------------------------
__device__ __half g_x16[(size_t)M_*D_];
__device__ __half g_w16[(size_t)4*D_*D_];        // Wq|Wk|Wv|Wo
__device__ __half g_q1[(size_t)B_*H_*S_*DH_];    // head-major, pre-scaled
__device__ __half g_k1[(size_t)B_*H_*S_*DH_];
__device__ __half g_v1[(size_t)B_*H_*S_*DH_];
__device__ __half g_c1[(size_t)M_*D_];           // ctx, row-major

// ---------------------------------------------------------------------------
// PTX helpers (plain sm_80-class PTX: valid under compute_103)
// ---------------------------------------------------------------------------
__device__ __forceinline__ uint32_t smem_u32(const void* p) {
    uint32_t a;
    asm("{ .reg .u64 t; cvta.to.shared.u64 t, %1; cvt.u32.u64 %0, t; }"
        : "=r"(a) : "l"(p));
    return a;
}
__device__ __forceinline__ void cp16(uint32_t dst, const void* src) {
    asm volatile("cp.async.cg.shared.global [%0], [%1], 16;"
                 :: "r"(dst), "l"(src) : "memory");
}
__device__ __forceinline__ void cp_commit() {
    asm volatile("cp.async.commit_group;" ::: "memory");
}
__device__ __forceinline__ void cp_wait0() {
    asm volatile("cp.async.wait_group 0;" ::: "memory");
}
__device__ __forceinline__ void cp_wait1() {
    asm volatile("cp.async.wait_group 1;" ::: "memory");
}
__device__ __forceinline__ void cp_wait2() {
    asm volatile("cp.async.wait_group 2;" ::: "memory");
}
__device__ __forceinline__ void ldsm4(uint32_t& r0, uint32_t& r1, uint32_t& r2,
                                      uint32_t& r3, uint32_t addr) {
    asm volatile("ldmatrix.sync.aligned.m8n8.x4.shared.b16 {%0,%1,%2,%3}, [%4];"
                 : "=r"(r0), "=r"(r1), "=r"(r2), "=r"(r3) : "r"(addr));
}
__device__ __forceinline__ void ldsm4t(uint32_t& r0, uint32_t& r1, uint32_t& r2,
                                       uint32_t& r3, uint32_t addr) {
    asm volatile("ldmatrix.sync.aligned.m8n8.x4.trans.shared.b16 {%0,%1,%2,%3}, [%4];"
                 : "=r"(r0), "=r"(r1), "=r"(r2), "=r"(r3) : "r"(addr));
}
// fp16 MMA
__device__ __forceinline__ void mma16816h(float* c, const uint32_t* a, const uint32_t* b) {
    asm volatile(
        "mma.sync.aligned.m16n8k16.row.col.f32.f16.f16.f32 "
        "{%0,%1,%2,%3}, {%4,%5,%6,%7}, {%8,%9}, {%0,%1,%2,%3};"
        : "+f"(c[0]), "+f"(c[1]), "+f"(c[2]), "+f"(c[3])
        : "r"(a[0]), "r"(a[1]), "r"(a[2]), "r"(a[3]), "r"(b[0]), "r"(b[1]));
}
__device__ __forceinline__ float ex2(float x) {
    float y; asm("ex2.approx.ftz.f32 %0, %1;" : "=f"(y) : "f"(x)); return y;
}
// Swizzle<3,4,3>: XOR 16B-column bits [6:4] with row bits [9:7]
__device__ __forceinline__ uint32_t swz(uint32_t off) {
    return off ^ ((off >> 3) & 0x70);
}
__device__ __forceinline__ uint32_t packh(float x, float y) {
    __half2 h = __floats2half2_rn(x, y);
    return *(uint32_t*)&h;
}

// ---------------------------------------------------------------------------
// single merged convert: y<4 -> weight y; y>=4 -> x quarter (y-4). 1M elems each.
// ---------------------------------------------------------------------------
__global__ void convall(const float* __restrict__ x,
                        const float* __restrict__ a, const float* __restrict__ b,
                        const float* __restrict__ c, const float* __restrict__ d,
                        __half* __restrict__ x16, __half* __restrict__ w16)
{
    const int y = blockIdx.y;
    const size_t off = ((size_t)blockIdx.x * blockDim.x + threadIdx.x) * 4;
    size_t base;
    if (y < 4) {
        const float* src = (y == 0) ? a : (y == 1) ? b : (y == 2) ? c : d;
        base = (size_t)y * D_ * D_;
        float4 v = *(const float4*)(src + off);
        *(__half2*)(w16 + base + off)     = __floats2half2_rn(v.x, v.y);
        *(__half2*)(w16 + base + off + 2) = __floats2half2_rn(v.z, v.w);
    } else {
        base = (size_t)(y - 4) * D_ * D_;
        float4 v = *(const float4*)(x + base + off);
        *(__half2*)(x16 + base + off)     = __floats2half2_rn(v.x, v.y);
        *(__half2*)(x16 + base + off + 2) = __floats2half2_rn(v.z, v.w);
    }
}

// ---------------------------------------------------------------------------
// fp16 HMMA GEMM (single-term): 128x128 CTA tile, BK=64, 2-stage, 256 thr,
// 2 CTAs/SM. 8 warps = 2m x 4n, warp tile 64x32 (acc 64 regs -> no spills).
// MODE 0 (fused QKV, N=3072): stores single fp16 head-major to q/k/v;
//                             Q block pre-scaled by (1/8)*log2(e).
// MODE 1 (out-proj): fp32 out + bias, row-major.
// ---------------------------------------------------------------------------
#define A_TB   16384                 // 128 x 128B
#define STAGE  (2*A_TB)              // A 16K + B 16K = 32 KB
#define TG_SMEM (2*STAGE)            // 64 KB
#define NCHUNK  (D_/64)              // 16

template<int MODE>
__global__ __launch_bounds__(256, 2) void tgemm(const __half* __restrict__ Ax,
                                                const __half* __restrict__ Bw,
                                                const float* __restrict__ bias,
                                                float* __restrict__ outf)
{
    extern __shared__ char smem[];
    const uint32_t sb = smem_u32(smem);
    const int tid  = threadIdx.x;
    const int wid  = tid >> 5;
    const int lane = tid & 31;
    const int wm   = wid >> 2;          // 0..1  (64-row slab)
    const int wn   = wid & 3;           // 0..3  (32-col slab)
    const int m0   = blockIdx.y * 128;
    const int n0   = blockIdx.x * 128;
    const int sel  = n0 >> 10;          // 0=Q, 1=K, 2=V (MODE 0)

    const char* gA = (const char*)(Ax + (size_t)m0 * D_);
    const char* gB = (const char*)(Bw + (size_t)n0 * D_);

    auto load_stage = [&](int chunk, uint32_t stage) {
        const uint32_t koff = (uint32_t)chunk * 128;
        {
            const char* base = gA + koff;
#pragma unroll
            for (int it = 0; it < 4; ++it) {
                const int c = tid + it * 256;
                const int r = c >> 3, c16 = c & 7;
                cp16(stage + swz((uint32_t)(r * 128 + c16 * 16)),
                     base + (size_t)r * (D_ * 2) + c16 * 16);
            }
        }
        {
            const char* base = gB + koff;
            const uint32_t dstt = stage + A_TB;
#pragma unroll
            for (int it = 0; it < 4; ++it) {
                const int c = tid + it * 256;
                const int r = c >> 3, c16 = c & 7;
                cp16(dstt + swz((uint32_t)(r * 128 + c16 * 16)),
                     base + (size_t)r * (D_ * 2) + c16 * 16);
            }
        }
        cp_commit();
    };

    float acc[4][4][4];
#pragma unroll
    for (int i = 0; i < 4; i++)
#pragma unroll
        for (int j = 0; j < 4; j++)
#pragma unroll
            for (int q = 0; q < 4; q++) acc[i][j][q] = 0.f;

    load_stage(0, sb);

    for (int c = 0; c < NCHUNK; ++c) {
        cp_wait0();
        __syncthreads();
        const uint32_t cur = sb + (c & 1) * STAGE;
        if (c + 1 < NCHUNK) load_stage(c + 1, sb + ((c + 1) & 1) * STAGE);

        const uint32_t aA = cur;
        const uint32_t bB = cur + A_TB;

#pragma unroll
        for (int ks = 0; ks < 4; ++ks) {
            uint32_t af[4][4];
            {
                const int rA = wm * 64 + (lane & 15);
                const uint32_t colA = (uint32_t)(ks * 32 + (lane >> 4) * 16);
#pragma unroll
                for (int mf = 0; mf < 4; ++mf) {
                    const uint32_t off = swz((uint32_t)(rA + mf * 16) * 128 + colA);
                    ldsm4(af[mf][0], af[mf][1], af[mf][2], af[mf][3], aA + off);
                }
            }
            const int t = lane >> 3;
            const uint32_t colB = (uint32_t)(ks * 32 + (t & 1) * 16);
#pragma unroll
            for (int ng = 0; ng < 2; ++ng) {
                const int rB = wn * 32 + ng * 16 + ((t >> 1) * 8) + (lane & 7);
                const uint32_t off = swz((uint32_t)rB * 128 + colB);
                uint32_t bh[4];
                ldsm4(bh[0], bh[1], bh[2], bh[3], bB + off);
#pragma unroll
                for (int mf = 0; mf < 4; ++mf) {
                    mma16816h(acc[mf][2*ng],   af[mf], bh);
                    mma16816h(acc[mf][2*ng+1], af[mf], bh + 2);
                }
            }
        }
        __syncthreads();
    }

    const int gid = lane >> 2, tig = lane & 3;
    __half* dhi = nullptr;
    float sq = 1.f;
    if (MODE == 0) {
        dhi = (sel == 0) ? g_q1 : (sel == 1) ? g_k1 : g_v1;
        if (sel == 0) sq = 0.18033688011112042f;   // (1/sqrt(64)) * log2(e)
    }
#pragma unroll
    for (int mf = 0; mf < 4; ++mf)
#pragma unroll
        for (int nf = 0; nf < 4; ++nf)
#pragma unroll
            for (int half = 0; half < 2; ++half) {
                const int m = m0 + wm * 64 + mf * 16 + gid + half * 8;
                const int n = n0 + wn * 32 + nf * 8 + tig * 2;
                float2 v = make_float2(acc[mf][nf][half*2], acc[mf][nf][half*2+1]);
                if (MODE == 1) {
                    v.x += bias[n]; v.y += bias[n+1];
                    *(float2*)(outf + (size_t)m * D_ + n) = v;
                } else {
                    const int nl = n & (D_ - 1);
                    const int b  = m >> 11;
                    const int s  = m & (S_ - 1);
                    const int h  = nl >> 6;
                    const int dh = nl & (DH_ - 1);
                    const size_t idx = ((size_t)(b * H_ + h) * S_ + s) * DH_ + dh;
                    *(__half2*)(dhi + idx) = __floats2half2_rn(v.x * sq, v.y * sq);
                }
            }
}

// ---------------------------------------------------------------------------
// fp16 HMMA flash attention, causal. BLOCK_M=128, BLOCK_N=64, 256 threads,
// 2 CTAs/SM. Q pre-scaled (no per-tile scale pass); o-rescale skipped when
// the running max is unchanged (exact). 3-stage cp.async KV pipeline.
// (unchanged from R13)
// ---------------------------------------------------------------------------
#define SM_Q     0                      // 16 KB (q single)
#define SM_KV    16384
#define KV_STG_B 16384                  // K 8K + V 8K
#define ATT_SMEM (16384 + 3*KV_STG_B)   // 65536 B

__global__ __launch_bounds__(256, 2) void attn_tc()
{
    extern __shared__ char smem[];
    const uint32_t sb = smem_u32(smem);
    const int tid  = threadIdx.x;
    const int w    = tid >> 5;
    const int lane = tid & 31;
    const int gid  = lane >> 2;
    const int tig  = lane & 3;
    const int qt   = (int)(gridDim.x - 1 - blockIdx.x);   // heavy tiles first
    const int bh   = blockIdx.y;
    const int q0   = qt * 128;
    const int b    = bh >> 4;
    const int h    = bh & (H_ - 1);
    const int jmax = 2 * qt + 1;        // 64-key tiles: keys [0, q0+128)

    const size_t headoff = (size_t)bh * S_ * DH_;

    auto load_kv = [&](int j, int stg) {
        const uint32_t base = sb + SM_KV + (uint32_t)stg * KV_STG_B;
        const size_t g = headoff + (size_t)j * 64 * DH_;
        const char* srcs[2] = { (const char*)(g_k1 + g),
                                (const char*)(g_v1 + g) };
#pragma unroll
        for (int t = 0; t < 2; ++t) {
#pragma unroll
            for (int it = 0; it < 2; ++it) {
                const int c = tid + it * 256;       // 0..511
                const int r = c >> 3, c16 = c & 7;
                cp16(base + t * 8192 + swz((uint32_t)(r * 128 + c16 * 16)),
                     srcs[t] + r * 128 + c16 * 16);
            }
        }
        cp_commit();
    };

    // group 0: Q tile (single, pre-scaled) + kv(0)
    {
        const char* qsrc = (const char*)(g_q1 + headoff + (size_t)q0 * DH_);
#pragma unroll
        for (int it = 0; it < 4; ++it) {
            const int c = tid + it * 256;
            const int r = c >> 3, c16 = c & 7;
            cp16(sb + SM_Q + swz((uint32_t)(r * 128 + c16 * 16)),
                 qsrc + r * 128 + c16 * 16);
        }
    }
    load_kv(0, 0);
    if (1 <= jmax) load_kv(1, 1);

    float m0v = -1e30f, m1v = -1e30f, l0v = 0.f, l1v = 0.f;
    float o[8][4];
#pragma unroll
    for (int i = 0; i < 8; i++)
#pragma unroll
        for (int j = 0; j < 4; j++) o[i][j] = 0.f;

    uint32_t qA[4][4];
    const int qrow0 = q0 + w * 16 + gid;
    const int qrow1 = qrow0 + 8;
    const int t8 = lane >> 3;

    for (int j = 0; j <= jmax; ++j) {
        if (j + 2 <= jmax) {
            int ns = j + 2; ns = ns - (ns / 3) * 3;
            load_kv(j + 2, ns);
            cp_wait2();
        } else if (j + 1 <= jmax) {
            cp_wait1();
        } else {
            cp_wait0();
        }
        __syncthreads();

        if (j == 0) {   // Q fragments once
            const int rA = w * 16 + (lane & 15);
            const uint32_t colA = (uint32_t)((lane >> 4) * 16);
#pragma unroll
            for (int ks = 0; ks < 4; ++ks) {
                const uint32_t off = swz((uint32_t)rA * 128 + ks * 32 + colA);
                ldsm4(qA[ks][0], qA[ks][1], qA[ks][2], qA[ks][3], sb + SM_Q + off);
            }
        }

        int stg = j - (j / 3) * 3;
        const uint32_t cur = sb + SM_KV + (uint32_t)stg * KV_STG_B;
        const uint32_t KK = cur, VV = cur + 8192;
        const int k0 = j * 64;

        // ---- S = Q @ K^T  (log2 domain; Q pre-scaled) ----
        float sacc[8][4];
#pragma unroll
        for (int i = 0; i < 8; i++)
#pragma unroll
            for (int q = 0; q < 4; q++) sacc[i][q] = 0.f;

#pragma unroll
        for (int ks = 0; ks < 4; ++ks) {
            const uint32_t colB = (uint32_t)(ks * 32 + (t8 & 1) * 16);
#pragma unroll
            for (int ng = 0; ng < 4; ++ng) {
                const int rK = ng * 16 + ((t8 >> 1) * 8) + (lane & 7);
                const uint32_t off = swz((uint32_t)rK * 128 + colB);
                uint32_t kk[4];
                ldsm4(kk[0], kk[1], kk[2], kk[3], KK + off);
                mma16816h(sacc[2*ng],   qA[ks], kk);
                mma16816h(sacc[2*ng+1], qA[ks], kk + 2);
            }
        }

        // ---- causal mask (only the last two tiles touch the diagonal) ----
        if (j >= 2 * qt) {
#pragma unroll
            for (int nf = 0; nf < 8; ++nf) {
                const int col = k0 + nf * 8 + tig * 2;
                if (col     > qrow0) sacc[nf][0] = -1e30f;
                if (col + 1 > qrow0) sacc[nf][1] = -1e30f;
                if (col     > qrow1) sacc[nf][2] = -1e30f;
                if (col + 1 > qrow1) sacc[nf][3] = -1e30f;
            }
        }

        // ---- online softmax ----
        float rm0 = -1e30f, rm1 = -1e30f;
#pragma unroll
        for (int nf = 0; nf < 8; ++nf) {
            rm0 = fmaxf(rm0, fmaxf(sacc[nf][0], sacc[nf][1]));
            rm1 = fmaxf(rm1, fmaxf(sacc[nf][2], sacc[nf][3]));
        }
        rm0 = fmaxf(rm0, __shfl_xor_sync(0xffffffffu, rm0, 1));
        rm0 = fmaxf(rm0, __shfl_xor_sync(0xffffffffu, rm0, 2));
        rm1 = fmaxf(rm1, __shfl_xor_sync(0xffffffffu, rm1, 1));
        rm1 = fmaxf(rm1, __shfl_xor_sync(0xffffffffu, rm1, 2));
        const float mn0 = fmaxf(m0v, rm0);
        const float mn1 = fmaxf(m1v, rm1);
        const bool up0 = (mn0 > m0v);
        const bool up1 = (mn1 > m1v);
        const float al0 = up0 ? ex2(m0v - mn0) : 1.f;
        const float al1 = up1 ? ex2(m1v - mn1) : 1.f;
        float rs0 = 0.f, rs1 = 0.f;
#pragma unroll
        for (int nf = 0; nf < 8; ++nf) {
            sacc[nf][0] = ex2(sacc[nf][0] - mn0);
            sacc[nf][1] = ex2(sacc[nf][1] - mn0);
            sacc[nf][2] = ex2(sacc[nf][2] - mn1);
            sacc[nf][3] = ex2(sacc[nf][3] - mn1);
            rs0 += sacc[nf][0] + sacc[nf][1];
            rs1 += sacc[nf][2] + sacc[nf][3];
        }
        rs0 += __shfl_xor_sync(0xffffffffu, rs0, 1);
        rs0 += __shfl_xor_sync(0xffffffffu, rs0, 2);
        rs1 += __shfl_xor_sync(0xffffffffu, rs1, 1);
        rs1 += __shfl_xor_sync(0xffffffffu, rs1, 2);
        l0v = l0v * al0 + rs0;  m0v = mn0;
        l1v = l1v * al1 + rs1;  m1v = mn1;
        if (up0) {
#pragma unroll
            for (int nf = 0; nf < 8; ++nf) { o[nf][0] *= al0; o[nf][1] *= al0; }
        }
        if (up1) {
#pragma unroll
            for (int nf = 0; nf < 8; ++nf) { o[nf][2] *= al1; o[nf][3] *= al1; }
        }

        // ---- O += P @ V  (P single fp16; V single via trans-ldmatrix) ----
#pragma unroll
        for (int ks2 = 0; ks2 < 4; ++ks2) {
            uint32_t pA[4];
#pragma unroll
            for (int q = 0; q < 4; ++q) {
                const int nf = 2 * ks2 + (q >> 1);
                const int e  = (q & 1) * 2;
                pA[q] = packh(sacc[nf][e], sacc[nf][e + 1]);
            }
            const int kq = ks2 * 16 + (t8 & 1) * 8 + (lane & 7);
#pragma unroll
            for (int og = 0; og < 4; ++og) {
                const uint32_t off = swz((uint32_t)kq * 128 + og * 32 + (t8 >> 1) * 16);
                uint32_t vv[4];
                ldsm4t(vv[0], vv[1], vv[2], vv[3], VV + off);
                mma16816h(o[2*og],   pA, vv);
                mma16816h(o[2*og+1], pA, vv + 2);
            }
        }
        __syncthreads();
    }

    // ---- normalize, write ctx single fp16 row-major ----
    const float inv0 = 1.f / l0v;
    const float inv1 = 1.f / l1v;
#pragma unroll
    for (int nf = 0; nf < 8; ++nf) {
        const int dh = nf * 8 + tig * 2;
        *(__half2*)(g_c1 + (size_t)(b * S_ + qrow0) * D_ + h * DH_ + dh) =
            __floats2half2_rn(o[nf][0] * inv0, o[nf][1] * inv0);
        *(__half2*)(g_c1 + (size_t)(b * S_ + qrow1) * D_ + h * DH_ + dh) =
            __floats2half2_rn(o[nf][2] * inv1, o[nf][3] * inv1);
    }
}

// ---------------------------------------------------------------------------
extern "C" void kernel_launch(void* const* d_in, const int* in_sizes, int n_in,
                              void* d_out, int out_size)
{
    const float* x  = (const float*)d_in[0];
    const float* Wq = (const float*)d_in[1];
    const float* Wk = (const float*)d_in[2];
    const float* Wv = (const float*)d_in[3];
    const float* Wo = (const float*)d_in[4];
    const float* bo = (const float*)d_in[5];
    float* out = (float*)d_out;

    __half *x16, *w16, *c1;
    cudaGetSymbolAddress((void**)&x16, g_x16);
    cudaGetSymbolAddress((void**)&w16, g_w16);
    cudaGetSymbolAddress((void**)&c1,  g_c1);

    cudaFuncSetAttribute(tgemm<0>, cudaFuncAttributeMaxDynamicSharedMemorySize, TG_SMEM);
    cudaFuncSetAttribute(tgemm<1>, cudaFuncAttributeMaxDynamicSharedMemorySize, TG_SMEM);
    cudaFuncSetAttribute(attn_tc,  cudaFuncAttributeMaxDynamicSharedMemorySize, ATT_SMEM);

    const int n1m = D_ * D_;    // 1M elems
    convall<<<dim3(n1m/1024, 8), 256>>>(x, Wq, Wk, Wv, Wo, x16, w16);

    // fused QKV projection: N = 3072 against stacked Wq|Wk|Wv (single-term)
    tgemm<0><<<dim3(3*D_/128, M_/128), 256, TG_SMEM>>>(x16, w16, nullptr, nullptr);

    attn_tc<<<dim3(S_/128, B_*H_), 256, ATT_SMEM>>>();

    // out-projection (single-term): ctx @ Wo^T + bias
    tgemm<1><<<dim3(D_/128, M_/128), 256, TG_SMEM>>>(c1, w16 + 3*(size_t)n1m,
                                                     bo, out);
}

// round 16
// speedup vs baseline: 2.4322x; 1.0298x over previous
#include <cuda_runtime.h>
#include <cuda_bf16.h>
#include <cuda_fp16.h>
#include <cstdint>

// Problem constants
#define B_  2
#define S_  2048
#define D_  1024
#define H_  16
#define DH_ 64
#define M_  (B_*S_)          // 4096 rows total

// ---------------------------------------------------------------------------
// Scratch (allocation-free __device__ globals) — fp16 single everywhere;
// accumulation is always fp32 (MMA C), final out-proj output fp32.
// Q is stored PRE-SCALED by (1/sqrt(DH))*log2(e).
// ---------------------------------------------------------------------------
__device__ __half g_x16[(size_t)M_*D_];
__device__ __half g_w16[(size_t)4*D_*D_];        // Wq|Wk|Wv|Wo
__device__ __half g_q1[(size_t)B_*H_*S_*DH_];    // head-major, pre-scaled
__device__ __half g_k1[(size_t)B_*H_*S_*DH_];
__device__ __half g_v1[(size_t)B_*H_*S_*DH_];
__device__ __half g_c1[(size_t)M_*D_];           // ctx, row-major

// ---------------------------------------------------------------------------
// PTX helpers (plain sm_80-class PTX: valid under compute_103)
// ---------------------------------------------------------------------------
__device__ __forceinline__ uint32_t smem_u32(const void* p) {
    uint32_t a;
    asm("{ .reg .u64 t; cvta.to.shared.u64 t, %1; cvt.u32.u64 %0, t; }"
        : "=r"(a) : "l"(p));
    return a;
}
__device__ __forceinline__ void cp16(uint32_t dst, const void* src) {
    asm volatile("cp.async.cg.shared.global [%0], [%1], 16;"
                 :: "r"(dst), "l"(src) : "memory");
}
__device__ __forceinline__ void cp_commit() {
    asm volatile("cp.async.commit_group;" ::: "memory");
}
__device__ __forceinline__ void cp_wait0() {
    asm volatile("cp.async.wait_group 0;" ::: "memory");
}
__device__ __forceinline__ void cp_wait1() {
    asm volatile("cp.async.wait_group 1;" ::: "memory");
}
__device__ __forceinline__ void ldsm4(uint32_t& r0, uint32_t& r1, uint32_t& r2,
                                      uint32_t& r3, uint32_t addr) {
    asm volatile("ldmatrix.sync.aligned.m8n8.x4.shared.b16 {%0,%1,%2,%3}, [%4];"
                 : "=r"(r0), "=r"(r1), "=r"(r2), "=r"(r3) : "r"(addr));
}
__device__ __forceinline__ void ldsm4t(uint32_t& r0, uint32_t& r1, uint32_t& r2,
                                       uint32_t& r3, uint32_t addr) {
    asm volatile("ldmatrix.sync.aligned.m8n8.x4.trans.shared.b16 {%0,%1,%2,%3}, [%4];"
                 : "=r"(r0), "=r"(r1), "=r"(r2), "=r"(r3) : "r"(addr));
}
// fp16 MMA
__device__ __forceinline__ void mma16816h(float* c, const uint32_t* a, const uint32_t* b) {
    asm volatile(
        "mma.sync.aligned.m16n8k16.row.col.f32.f16.f16.f32 "
        "{%0,%1,%2,%3}, {%4,%5,%6,%7}, {%8,%9}, {%0,%1,%2,%3};"
        : "+f"(c[0]), "+f"(c[1]), "+f"(c[2]), "+f"(c[3])
        : "r"(a[0]), "r"(a[1]), "r"(a[2]), "r"(a[3]), "r"(b[0]), "r"(b[1]));
}
__device__ __forceinline__ float ex2(float x) {
    float y; asm("ex2.approx.ftz.f32 %0, %1;" : "=f"(y) : "f"(x)); return y;
}
__device__ __forceinline__ uint32_t ex2_h2(uint32_t x) {
    uint32_t y; asm("ex2.approx.f16x2 %0, %1;" : "=r"(y) : "r"(x)); return y;
}
__device__ __forceinline__ uint32_t hadd2(uint32_t a, uint32_t b) {
    uint32_t y; asm("add.rn.f16x2 %0, %1, %2;" : "=r"(y) : "r"(a), "r"(b)); return y;
}
// Swizzle<3,4,3>: XOR 16B-column bits [6:4] with row bits [9:7]
__device__ __forceinline__ uint32_t swz(uint32_t off) {
    return off ^ ((off >> 3) & 0x70);
}
__device__ __forceinline__ uint32_t packh(float x, float y) {
    __half2 h = __floats2half2_rn(x, y);
    return *(uint32_t*)&h;
}

// ---------------------------------------------------------------------------
// single merged convert: y<4 -> weight y; y>=4 -> x quarter (y-4). 1M elems each.
// ---------------------------------------------------------------------------
__global__ void convall(const float* __restrict__ x,
                        const float* __restrict__ a, const float* __restrict__ b,
                        const float* __restrict__ c, const float* __restrict__ d,
                        __half* __restrict__ x16, __half* __restrict__ w16)
{
    const int y = blockIdx.y;
    const size_t off = ((size_t)blockIdx.x * blockDim.x + threadIdx.x) * 4;
    size_t base;
    if (y < 4) {
        const float* src = (y == 0) ? a : (y == 1) ? b : (y == 2) ? c : d;
        base = (size_t)y * D_ * D_;
        float4 v = *(const float4*)(src + off);
        *(__half2*)(w16 + base + off)     = __floats2half2_rn(v.x, v.y);
        *(__half2*)(w16 + base + off + 2) = __floats2half2_rn(v.z, v.w);
    } else {
        base = (size_t)(y - 4) * D_ * D_;
        float4 v = *(const float4*)(x + base + off);
        *(__half2*)(x16 + base + off)     = __floats2half2_rn(v.x, v.y);
        *(__half2*)(x16 + base + off + 2) = __floats2half2_rn(v.z, v.w);
    }
}

// ---------------------------------------------------------------------------
// fp16 HMMA GEMM (single-term): 128x128 CTA tile, BK=64, THREE-stage,
// 256 thr, 2 CTAs/SM, one barrier per chunk. Warp tile 64x32.
// MODE 0 (fused QKV, N=3072): stores single fp16 head-major to q/k/v;
//                             Q block pre-scaled by (1/8)*log2(e).
// MODE 1 (out-proj): fp32 out + bias, row-major.
// ---------------------------------------------------------------------------
#define A_TB   16384                 // 128 x 128B
#define STAGE  (2*A_TB)              // A 16K + B 16K = 32 KB
#define TG_SMEM (3*STAGE)            // 96 KB
#define NCHUNK  (D_/64)              // 16

template<int MODE>
__global__ __launch_bounds__(256, 2) void tgemm(const __half* __restrict__ Ax,
                                                const __half* __restrict__ Bw,
                                                const float* __restrict__ bias,
                                                float* __restrict__ outf)
{
    extern __shared__ char smem[];
    const uint32_t sb = smem_u32(smem);
    const int tid  = threadIdx.x;
    const int wid  = tid >> 5;
    const int lane = tid & 31;
    const int wm   = wid >> 2;          // 0..1  (64-row slab)
    const int wn   = wid & 3;           // 0..3  (32-col slab)
    const int m0   = blockIdx.y * 128;
    const int n0   = blockIdx.x * 128;
    const int sel  = n0 >> 10;          // 0=Q, 1=K, 2=V (MODE 0)

    const char* gA = (const char*)(Ax + (size_t)m0 * D_);
    const char* gB = (const char*)(Bw + (size_t)n0 * D_);

    auto load_stage = [&](int chunk, uint32_t stage) {
        const uint32_t koff = (uint32_t)chunk * 128;
        {
            const char* base = gA + koff;
#pragma unroll
            for (int it = 0; it < 4; ++it) {
                const int c = tid + it * 256;
                const int r = c >> 3, c16 = c & 7;
                cp16(stage + swz((uint32_t)(r * 128 + c16 * 16)),
                     base + (size_t)r * (D_ * 2) + c16 * 16);
            }
        }
        {
            const char* base = gB + koff;
            const uint32_t dstt = stage + A_TB;
#pragma unroll
            for (int it = 0; it < 4; ++it) {
                const int c = tid + it * 256;
                const int r = c >> 3, c16 = c & 7;
                cp16(dstt + swz((uint32_t)(r * 128 + c16 * 16)),
                     base + (size_t)r * (D_ * 2) + c16 * 16);
            }
        }
        cp_commit();
    };

    float acc[4][4][4];
#pragma unroll
    for (int i = 0; i < 4; i++)
#pragma unroll
        for (int j = 0; j < 4; j++)
#pragma unroll
            for (int q = 0; q < 4; q++) acc[i][j][q] = 0.f;

    load_stage(0, sb);
    load_stage(1, sb + STAGE);

    int stg = 0;
    for (int c = 0; c < NCHUNK; ++c) {
        if (c + 1 < NCHUNK) cp_wait1(); else cp_wait0();
        __syncthreads();
        if (c + 2 < NCHUNK) {
            int ns = stg + 2; if (ns >= 3) ns -= 3;
            load_stage(c + 2, sb + (uint32_t)ns * STAGE);
        }
        const uint32_t cur = sb + (uint32_t)stg * STAGE;
        const uint32_t aA = cur;
        const uint32_t bB = cur + A_TB;

#pragma unroll
        for (int ks = 0; ks < 4; ++ks) {
            uint32_t af[4][4];
            {
                const int rA = wm * 64 + (lane & 15);
                const uint32_t colA = (uint32_t)(ks * 32 + (lane >> 4) * 16);
#pragma unroll
                for (int mf = 0; mf < 4; ++mf) {
                    const uint32_t off = swz((uint32_t)(rA + mf * 16) * 128 + colA);
                    ldsm4(af[mf][0], af[mf][1], af[mf][2], af[mf][3], aA + off);
                }
            }
            const int t = lane >> 3;
            const uint32_t colB = (uint32_t)(ks * 32 + (t & 1) * 16);
#pragma unroll
            for (int ng = 0; ng < 2; ++ng) {
                const int rB = wn * 32 + ng * 16 + ((t >> 1) * 8) + (lane & 7);
                const uint32_t off = swz((uint32_t)rB * 128 + colB);
                uint32_t bh[4];
                ldsm4(bh[0], bh[1], bh[2], bh[3], bB + off);
#pragma unroll
                for (int mf = 0; mf < 4; ++mf) {
                    mma16816h(acc[mf][2*ng],   af[mf], bh);
                    mma16816h(acc[mf][2*ng+1], af[mf], bh + 2);
                }
            }
        }
        if (++stg == 3) stg = 0;
    }

    const int gid = lane >> 2, tig = lane & 3;
    __half* dhi = nullptr;
    float sq = 1.f;
    if (MODE == 0) {
        dhi = (sel == 0) ? g_q1 : (sel == 1) ? g_k1 : g_v1;
        if (sel == 0) sq = 0.18033688011112042f;   // (1/sqrt(64)) * log2(e)
    }
#pragma unroll
    for (int mf = 0; mf < 4; ++mf)
#pragma unroll
        for (int nf = 0; nf < 4; ++nf)
#pragma unroll
            for (int half = 0; half < 2; ++half) {
                const int m = m0 + wm * 64 + mf * 16 + gid + half * 8;
                const int n = n0 + wn * 32 + nf * 8 + tig * 2;
                float2 v = make_float2(acc[mf][nf][half*2], acc[mf][nf][half*2+1]);
                if (MODE == 1) {
                    v.x += bias[n]; v.y += bias[n+1];
                    *(float2*)(outf + (size_t)m * D_ + n) = v;
                } else {
                    const int nl = n & (D_ - 1);
                    const int b  = m >> 11;
                    const int s  = m & (S_ - 1);
                    const int h  = nl >> 6;
                    const int dh = nl & (DH_ - 1);
                    const size_t idx = ((size_t)(b * H_ + h) * S_ + s) * DH_ + dh;
                    *(__half2*)(dhi + idx) = __floats2half2_rn(v.x * sq, v.y * sq);
                }
            }
}

// ---------------------------------------------------------------------------
// fp16 HMMA flash attention, causal. BLOCK_M=128, BLOCK_N=64, 256 threads,
// 2 CTAs/SM. Q pre-scaled; o-rescale skipped when max unchanged (exact).
// f16x2 exponentials (P emerges pre-packed as MMA A-frags); one barrier/tile.
// 3-stage cp.async KV pipeline.
// ---------------------------------------------------------------------------
#define SM_Q     0                      // 16 KB (q single)
#define SM_KV    16384
#define KV_STG_B 16384                  // K 8K + V 8K
#define ATT_SMEM (16384 + 3*KV_STG_B)   // 65536 B

__global__ __launch_bounds__(256, 2) void attn_tc()
{
    extern __shared__ char smem[];
    const uint32_t sb = smem_u32(smem);
    const int tid  = threadIdx.x;
    const int w    = tid >> 5;
    const int lane = tid & 31;
    const int gid  = lane >> 2;
    const int tig  = lane & 3;
    const int qt   = (int)(gridDim.x - 1 - blockIdx.x);   // heavy tiles first
    const int bh   = blockIdx.y;
    const int q0   = qt * 128;
    const int b    = bh >> 4;
    const int h    = bh & (H_ - 1);
    const int jmax = 2 * qt + 1;        // 64-key tiles: keys [0, q0+128)

    const size_t headoff = (size_t)bh * S_ * DH_;

    auto load_kv = [&](int j, int stg) {
        const uint32_t base = sb + SM_KV + (uint32_t)stg * KV_STG_B;
        const size_t g = headoff + (size_t)j * 64 * DH_;
        const char* srcs[2] = { (const char*)(g_k1 + g),
                                (const char*)(g_v1 + g) };
#pragma unroll
        for (int t = 0; t < 2; ++t) {
#pragma unroll
            for (int it = 0; it < 2; ++it) {
                const int c = tid + it * 256;       // 0..511
                const int r = c >> 3, c16 = c & 7;
                cp16(base + t * 8192 + swz((uint32_t)(r * 128 + c16 * 16)),
                     srcs[t] + r * 128 + c16 * 16);
            }
        }
        cp_commit();
    };

    // group 0: Q tile (single, pre-scaled) + kv(0)
    {
        const char* qsrc = (const char*)(g_q1 + headoff + (size_t)q0 * DH_);
#pragma unroll
        for (int it = 0; it < 4; ++it) {
            const int c = tid + it * 256;
            const int r = c >> 3, c16 = c & 7;
            cp16(sb + SM_Q + swz((uint32_t)(r * 128 + c16 * 16)),
                 qsrc + r * 128 + c16 * 16);
        }
    }
    load_kv(0, 0);
    if (1 <= jmax) load_kv(1, 1);

    float m0v = -1e30f, m1v = -1e30f, l0v = 0.f, l1v = 0.f;
    float o[8][4];
#pragma unroll
    for (int i = 0; i < 8; i++)
#pragma unroll
        for (int j = 0; j < 4; j++) o[i][j] = 0.f;

    uint32_t qA[4][4];
    const int qrow0 = q0 + w * 16 + gid;
    const int qrow1 = qrow0 + 8;
    const int t8 = lane >> 3;

    for (int j = 0; j <= jmax; ++j) {
        if (j < jmax) cp_wait1(); else cp_wait0();
        __syncthreads();
        if (j + 2 <= jmax) {
            int ns = j + 2; ns = ns - (ns / 3) * 3;   // (j+2) % 3
            load_kv(j + 2, ns);
        }

        if (j == 0) {   // Q fragments once
            const int rA = w * 16 + (lane & 15);
            const uint32_t colA = (uint32_t)((lane >> 4) * 16);
#pragma unroll
            for (int ks = 0; ks < 4; ++ks) {
                const uint32_t off = swz((uint32_t)rA * 128 + ks * 32 + colA);
                ldsm4(qA[ks][0], qA[ks][1], qA[ks][2], qA[ks][3], sb + SM_Q + off);
            }
        }

        int stg = j - (j / 3) * 3;
        const uint32_t cur = sb + SM_KV + (uint32_t)stg * KV_STG_B;
        const uint32_t KK = cur, VV = cur + 8192;
        const int k0 = j * 64;

        // ---- S = Q @ K^T  (log2 domain; Q pre-scaled) ----
        float sacc[8][4];
#pragma unroll
        for (int i = 0; i < 8; i++)
#pragma unroll
            for (int q = 0; q < 4; q++) sacc[i][q] = 0.f;

#pragma unroll
        for (int ks = 0; ks < 4; ++ks) {
            const uint32_t colB = (uint32_t)(ks * 32 + (t8 & 1) * 16);
#pragma unroll
            for (int ng = 0; ng < 4; ++ng) {
                const int rK = ng * 16 + ((t8 >> 1) * 8) + (lane & 7);
                const uint32_t off = swz((uint32_t)rK * 128 + colB);
                uint32_t kk[4];
                ldsm4(kk[0], kk[1], kk[2], kk[3], KK + off);
                mma16816h(sacc[2*ng],   qA[ks], kk);
                mma16816h(sacc[2*ng+1], qA[ks], kk + 2);
            }
        }

        // ---- causal mask (only the last two tiles touch the diagonal) ----
        if (j >= 2 * qt) {
#pragma unroll
            for (int nf = 0; nf < 8; ++nf) {
                const int col = k0 + nf * 8 + tig * 2;
                if (col     > qrow0) sacc[nf][0] = -1e30f;
                if (col + 1 > qrow0) sacc[nf][1] = -1e30f;
                if (col     > qrow1) sacc[nf][2] = -1e30f;
                if (col + 1 > qrow1) sacc[nf][3] = -1e30f;
            }
        }

        // ---- online softmax (f16x2 exponentials) ----
        float rm0 = -1e30f, rm1 = -1e30f;
#pragma unroll
        for (int nf = 0; nf < 8; ++nf) {
            rm0 = fmaxf(rm0, fmaxf(sacc[nf][0], sacc[nf][1]));
            rm1 = fmaxf(rm1, fmaxf(sacc[nf][2], sacc[nf][3]));
        }
        rm0 = fmaxf(rm0, __shfl_xor_sync(0xffffffffu, rm0, 1));
        rm0 = fmaxf(rm0, __shfl_xor_sync(0xffffffffu, rm0, 2));
        rm1 = fmaxf(rm1, __shfl_xor_sync(0xffffffffu, rm1, 1));
        rm1 = fmaxf(rm1, __shfl_xor_sync(0xffffffffu, rm1, 2));
        const float mn0 = fmaxf(m0v, rm0);
        const float mn1 = fmaxf(m1v, rm1);
        const bool up0 = (mn0 > m0v);
        const bool up1 = (mn1 > m1v);
        const float al0 = up0 ? ex2(m0v - mn0) : 1.f;
        const float al1 = up1 ? ex2(m1v - mn1) : 1.f;

        uint32_t pP[4][4];
        uint32_t racc0 = 0u, racc1 = 0u;    // half2 accumulators (zero)
#pragma unroll
        for (int nf = 0; nf < 8; ++nf) {
            uint32_t p01 = ex2_h2(packh(sacc[nf][0] - mn0, sacc[nf][1] - mn0));
            uint32_t p23 = ex2_h2(packh(sacc[nf][2] - mn1, sacc[nf][3] - mn1));
            pP[nf >> 1][(nf & 1) * 2 + 0] = p01;
            pP[nf >> 1][(nf & 1) * 2 + 1] = p23;
            racc0 = hadd2(racc0, p01);
            racc1 = hadd2(racc1, p23);
        }
        float2 f0 = __half22float2(*(__half2*)&racc0);
        float2 f1 = __half22float2(*(__half2*)&racc1);
        float rs0 = f0.x + f0.y;
        float rs1 = f1.x + f1.y;
        rs0 += __shfl_xor_sync(0xffffffffu, rs0, 1);
        rs0 += __shfl_xor_sync(0xffffffffu, rs0, 2);
        rs1 += __shfl_xor_sync(0xffffffffu, rs1, 1);
        rs1 += __shfl_xor_sync(0xffffffffu, rs1, 2);
        l0v = l0v * al0 + rs0;  m0v = mn0;
        l1v = l1v * al1 + rs1;  m1v = mn1;
        if (up0) {
#pragma unroll
            for (int nf = 0; nf < 8; ++nf) { o[nf][0] *= al0; o[nf][1] *= al0; }
        }
        if (up1) {
#pragma unroll
            for (int nf = 0; nf < 8; ++nf) { o[nf][2] *= al1; o[nf][3] *= al1; }
        }

        // ---- O += P @ V  (P pre-packed; V single via trans-ldmatrix) ----
#pragma unroll
        for (int ks2 = 0; ks2 < 4; ++ks2) {
            const int kq = ks2 * 16 + (t8 & 1) * 8 + (lane & 7);
#pragma unroll
            for (int og = 0; og < 4; ++og) {
                const uint32_t off = swz((uint32_t)kq * 128 + og * 32 + (t8 >> 1) * 16);
                uint32_t vv[4];
                ldsm4t(vv[0], vv[1], vv[2], vv[3], VV + off);
                mma16816h(o[2*og],   pP[ks2], vv);
                mma16816h(o[2*og+1], pP[ks2], vv + 2);
            }
        }
    }

    // ---- normalize, write ctx single fp16 row-major ----
    const float inv0 = 1.f / l0v;
    const float inv1 = 1.f / l1v;
#pragma unroll
    for (int nf = 0; nf < 8; ++nf) {
        const int dh = nf * 8 + tig * 2;
        *(__half2*)(g_c1 + (size_t)(b * S_ + qrow0) * D_ + h * DH_ + dh) =
            __floats2half2_rn(o[nf][0] * inv0, o[nf][1] * inv0);
        *(__half2*)(g_c1 + (size_t)(b * S_ + qrow1) * D_ + h * DH_ + dh) =
            __floats2half2_rn(o[nf][2] * inv1, o[nf][3] * inv1);
    }
}

// ---------------------------------------------------------------------------
extern "C" void kernel_launch(void* const* d_in, const int* in_sizes, int n_in,
                              void* d_out, int out_size)
{
    const float* x  = (const float*)d_in[0];
    const float* Wq = (const float*)d_in[1];
    const float* Wk = (const float*)d_in[2];
    const float* Wv = (const float*)d_in[3];
    const float* Wo = (const float*)d_in[4];
    const float* bo = (const float*)d_in[5];
    float* out = (float*)d_out;

    __half *x16, *w16, *c1;
    cudaGetSymbolAddress((void**)&x16, g_x16);
    cudaGetSymbolAddress((void**)&w16, g_w16);
    cudaGetSymbolAddress((void**)&c1,  g_c1);

    cudaFuncSetAttribute(tgemm<0>, cudaFuncAttributeMaxDynamicSharedMemorySize, TG_SMEM);
    cudaFuncSetAttribute(tgemm<1>, cudaFuncAttributeMaxDynamicSharedMemorySize, TG_SMEM);
    cudaFuncSetAttribute(attn_tc,  cudaFuncAttributeMaxDynamicSharedMemorySize, ATT_SMEM);

    const int n1m = D_ * D_;    // 1M elems
    convall<<<dim3(n1m/1024, 8), 256>>>(x, Wq, Wk, Wv, Wo, x16, w16);

    // fused QKV projection: N = 3072 against stacked Wq|Wk|Wv (single-term)
    tgemm<0><<<dim3(3*D_/128, M_/128), 256, TG_SMEM>>>(x16, w16, nullptr, nullptr);

    attn_tc<<<dim3(S_/128, B_*H_), 256, ATT_SMEM>>>();

    // out-projection (single-term): ctx @ Wo^T + bias
    tgemm<1><<<dim3(D_/128, M_/128), 256, TG_SMEM>>>(c1, w16 + 3*(size_t)n1m,
                                                     bo, out);
}

// round 17
// speedup vs baseline: 2.4837x; 1.0212x over previous
#include <cuda_runtime.h>
#include <cuda_bf16.h>
#include <cuda_fp16.h>
#include <cstdint>

// Problem constants
#define B_  2
#define S_  2048
#define D_  1024
#define H_  16
#define DH_ 64
#define M_  (B_*S_)          // 4096 rows total

// ---------------------------------------------------------------------------
// Scratch (allocation-free __device__ globals) — fp16 single everywhere;
// accumulation is always fp32 (MMA C), final out-proj output fp32.
// Q is stored PRE-SCALED by (1/sqrt(DH))*log2(e).
// ---------------------------------------------------------------------------
__device__ __half g_x16[(size_t)M_*D_];
__device__ __half g_w16[(size_t)4*D_*D_];        // Wq|Wk|Wv|Wo
__device__ __half g_q1[(size_t)B_*H_*S_*DH_];    // head-major, pre-scaled
__device__ __half g_k1[(size_t)B_*H_*S_*DH_];
__device__ __half g_v1[(size_t)B_*H_*S_*DH_];
__device__ __half g_c1[(size_t)M_*D_];           // ctx, row-major

// ---------------------------------------------------------------------------
// PTX helpers (plain sm_80-class PTX: valid under compute_103)
// ---------------------------------------------------------------------------
__device__ __forceinline__ uint32_t smem_u32(const void* p) {
    uint32_t a;
    asm("{ .reg .u64 t; cvta.to.shared.u64 t, %1; cvt.u32.u64 %0, t; }"
        : "=r"(a) : "l"(p));
    return a;
}
__device__ __forceinline__ void cp16(uint32_t dst, const void* src) {
    asm volatile("cp.async.cg.shared.global [%0], [%1], 16;"
                 :: "r"(dst), "l"(src) : "memory");
}
__device__ __forceinline__ void cp_commit() {
    asm volatile("cp.async.commit_group;" ::: "memory");
}
__device__ __forceinline__ void cp_wait0() {
    asm volatile("cp.async.wait_group 0;" ::: "memory");
}
__device__ __forceinline__ void cp_wait1() {
    asm volatile("cp.async.wait_group 1;" ::: "memory");
}
__device__ __forceinline__ void ldsm4(uint32_t& r0, uint32_t& r1, uint32_t& r2,
                                      uint32_t& r3, uint32_t addr) {
    asm volatile("ldmatrix.sync.aligned.m8n8.x4.shared.b16 {%0,%1,%2,%3}, [%4];"
                 : "=r"(r0), "=r"(r1), "=r"(r2), "=r"(r3) : "r"(addr));
}
__device__ __forceinline__ void ldsm4t(uint32_t& r0, uint32_t& r1, uint32_t& r2,
                                       uint32_t& r3, uint32_t addr) {
    asm volatile("ldmatrix.sync.aligned.m8n8.x4.trans.shared.b16 {%0,%1,%2,%3}, [%4];"
                 : "=r"(r0), "=r"(r1), "=r"(r2), "=r"(r3) : "r"(addr));
}
// fp16 MMA
__device__ __forceinline__ void mma16816h(float* c, const uint32_t* a, const uint32_t* b) {
    asm volatile(
        "mma.sync.aligned.m16n8k16.row.col.f32.f16.f16.f32 "
        "{%0,%1,%2,%3}, {%4,%5,%6,%7}, {%8,%9}, {%0,%1,%2,%3};"
        : "+f"(c[0]), "+f"(c[1]), "+f"(c[2]), "+f"(c[3])
        : "r"(a[0]), "r"(a[1]), "r"(a[2]), "r"(a[3]), "r"(b[0]), "r"(b[1]));
}
__device__ __forceinline__ float ex2(float x) {
    float y; asm("ex2.approx.ftz.f32 %0, %1;" : "=f"(y) : "f"(x)); return y;
}
__device__ __forceinline__ uint32_t ex2_h2(uint32_t x) {
    uint32_t y; asm("ex2.approx.f16x2 %0, %1;" : "=r"(y) : "r"(x)); return y;
}
__device__ __forceinline__ uint32_t hadd2(uint32_t a, uint32_t b) {
    uint32_t y; asm("add.rn.f16x2 %0, %1, %2;" : "=r"(y) : "r"(a), "r"(b)); return y;
}
// Swizzle<3,4,3>: XOR 16B-column bits [6:4] with row bits [9:7]
__device__ __forceinline__ uint32_t swz(uint32_t off) {
    return off ^ ((off >> 3) & 0x70);
}
__device__ __forceinline__ uint32_t packh(float x, float y) {
    __half2 h = __floats2half2_rn(x, y);
    return *(uint32_t*)&h;
}

// ---------------------------------------------------------------------------
// single merged convert: y<4 -> weight y; y>=4 -> x quarter (y-4). 1M elems each.
// ---------------------------------------------------------------------------
__global__ void convall(const float* __restrict__ x,
                        const float* __restrict__ a, const float* __restrict__ b,
                        const float* __restrict__ c, const float* __restrict__ d,
                        __half* __restrict__ x16, __half* __restrict__ w16)
{
    const int y = blockIdx.y;
    const size_t off = ((size_t)blockIdx.x * blockDim.x + threadIdx.x) * 4;
    size_t base;
    if (y < 4) {
        const float* src = (y == 0) ? a : (y == 1) ? b : (y == 2) ? c : d;
        base = (size_t)y * D_ * D_;
        float4 v = *(const float4*)(src + off);
        *(__half2*)(w16 + base + off)     = __floats2half2_rn(v.x, v.y);
        *(__half2*)(w16 + base + off + 2) = __floats2half2_rn(v.z, v.w);
    } else {
        base = (size_t)(y - 4) * D_ * D_;
        float4 v = *(const float4*)(x + base + off);
        *(__half2*)(x16 + base + off)     = __floats2half2_rn(v.x, v.y);
        *(__half2*)(x16 + base + off + 2) = __floats2half2_rn(v.z, v.w);
    }
}

// ---------------------------------------------------------------------------
// fp16 HMMA GEMM (single-term): 128x128 CTA tile, BK=64, TWO-stage (R15 cfg),
// 256 thr, 2 CTAs/SM. Warp tile 64x32.
// MODE 0 (fused QKV, N=3072): stores single fp16 head-major to q/k/v;
//                             Q block pre-scaled by (1/8)*log2(e).
// MODE 1 (out-proj): fp32 out + bias, row-major.
// ---------------------------------------------------------------------------
#define A_TB   16384                 // 128 x 128B
#define STAGE  (2*A_TB)              // A 16K + B 16K = 32 KB
#define TG_SMEM (2*STAGE)            // 64 KB
#define NCHUNK  (D_/64)              // 16

template<int MODE>
__global__ __launch_bounds__(256, 2) void tgemm(const __half* __restrict__ Ax,
                                                const __half* __restrict__ Bw,
                                                const float* __restrict__ bias,
                                                float* __restrict__ outf)
{
    extern __shared__ char smem[];
    const uint32_t sb = smem_u32(smem);
    const int tid  = threadIdx.x;
    const int wid  = tid >> 5;
    const int lane = tid & 31;
    const int wm   = wid >> 2;          // 0..1  (64-row slab)
    const int wn   = wid & 3;           // 0..3  (32-col slab)
    const int m0   = blockIdx.y * 128;
    const int n0   = blockIdx.x * 128;
    const int sel  = n0 >> 10;          // 0=Q, 1=K, 2=V (MODE 0)

    const char* gA = (const char*)(Ax + (size_t)m0 * D_);
    const char* gB = (const char*)(Bw + (size_t)n0 * D_);

    auto load_stage = [&](int chunk, uint32_t stage) {
        const uint32_t koff = (uint32_t)chunk * 128;
        {
            const char* base = gA + koff;
#pragma unroll
            for (int it = 0; it < 4; ++it) {
                const int c = tid + it * 256;
                const int r = c >> 3, c16 = c & 7;
                cp16(stage + swz((uint32_t)(r * 128 + c16 * 16)),
                     base + (size_t)r * (D_ * 2) + c16 * 16);
            }
        }
        {
            const char* base = gB + koff;
            const uint32_t dstt = stage + A_TB;
#pragma unroll
            for (int it = 0; it < 4; ++it) {
                const int c = tid + it * 256;
                const int r = c >> 3, c16 = c & 7;
                cp16(dstt + swz((uint32_t)(r * 128 + c16 * 16)),
                     base + (size_t)r * (D_ * 2) + c16 * 16);
            }
        }
        cp_commit();
    };

    float acc[4][4][4];
#pragma unroll
    for (int i = 0; i < 4; i++)
#pragma unroll
        for (int j = 0; j < 4; j++)
#pragma unroll
            for (int q = 0; q < 4; q++) acc[i][j][q] = 0.f;

    load_stage(0, sb);

    for (int c = 0; c < NCHUNK; ++c) {
        cp_wait0();
        __syncthreads();
        const uint32_t cur = sb + (c & 1) * STAGE;
        if (c + 1 < NCHUNK) load_stage(c + 1, sb + ((c + 1) & 1) * STAGE);

        const uint32_t aA = cur;
        const uint32_t bB = cur + A_TB;

#pragma unroll
        for (int ks = 0; ks < 4; ++ks) {
            uint32_t af[4][4];
            {
                const int rA = wm * 64 + (lane & 15);
                const uint32_t colA = (uint32_t)(ks * 32 + (lane >> 4) * 16);
#pragma unroll
                for (int mf = 0; mf < 4; ++mf) {
                    const uint32_t off = swz((uint32_t)(rA + mf * 16) * 128 + colA);
                    ldsm4(af[mf][0], af[mf][1], af[mf][2], af[mf][3], aA + off);
                }
            }
            const int t = lane >> 3;
            const uint32_t colB = (uint32_t)(ks * 32 + (t & 1) * 16);
#pragma unroll
            for (int ng = 0; ng < 2; ++ng) {
                const int rB = wn * 32 + ng * 16 + ((t >> 1) * 8) + (lane & 7);
                const uint32_t off = swz((uint32_t)rB * 128 + colB);
                uint32_t bh[4];
                ldsm4(bh[0], bh[1], bh[2], bh[3], bB + off);
#pragma unroll
                for (int mf = 0; mf < 4; ++mf) {
                    mma16816h(acc[mf][2*ng],   af[mf], bh);
                    mma16816h(acc[mf][2*ng+1], af[mf], bh + 2);
                }
            }
        }
        __syncthreads();
    }

    const int gid = lane >> 2, tig = lane & 3;
    __half* dhi = nullptr;
    float sq = 1.f;
    if (MODE == 0) {
        dhi = (sel == 0) ? g_q1 : (sel == 1) ? g_k1 : g_v1;
        if (sel == 0) sq = 0.18033688011112042f;   // (1/sqrt(64)) * log2(e)
    }
#pragma unroll
    for (int mf = 0; mf < 4; ++mf)
#pragma unroll
        for (int nf = 0; nf < 4; ++nf)
#pragma unroll
            for (int half = 0; half < 2; ++half) {
                const int m = m0 + wm * 64 + mf * 16 + gid + half * 8;
                const int n = n0 + wn * 32 + nf * 8 + tig * 2;
                float2 v = make_float2(acc[mf][nf][half*2], acc[mf][nf][half*2+1]);
                if (MODE == 1) {
                    v.x += bias[n]; v.y += bias[n+1];
                    *(float2*)(outf + (size_t)m * D_ + n) = v;
                } else {
                    const int nl = n & (D_ - 1);
                    const int b  = m >> 11;
                    const int s  = m & (S_ - 1);
                    const int h  = nl >> 6;
                    const int dh = nl & (DH_ - 1);
                    const size_t idx = ((size_t)(b * H_ + h) * S_ + s) * DH_ + dh;
                    *(__half2*)(dhi + idx) = __floats2half2_rn(v.x * sq, v.y * sq);
                }
            }
}

// ---------------------------------------------------------------------------
// fp16 HMMA flash attention, causal. BLOCK_M=128, 64-key sub-tiles processed
// in PAIRS per barrier (tile count is always even = 2qt+2). 4-stage cp.async
// KV ring; one wait+sync per pair. 256 threads, 2 CTAs/SM. Q pre-scaled;
// o-rescale skipped when max unchanged; f16x2 exponentials.
// ---------------------------------------------------------------------------
#define SM_Q     0                      // 16 KB (q single)
#define SM_KV    16384
#define KV_STG_B 16384                  // K 8K + V 8K
#define ATT_SMEM (16384 + 4*KV_STG_B)   // 81920 B

__global__ __launch_bounds__(256, 2) void attn_tc()
{
    extern __shared__ char smem[];
    const uint32_t sb = smem_u32(smem);
    const int tid  = threadIdx.x;
    const int w    = tid >> 5;
    const int lane = tid & 31;
    const int gid  = lane >> 2;
    const int tig  = lane & 3;
    const int qt   = (int)(gridDim.x - 1 - blockIdx.x);   // heavy tiles first
    const int bh   = blockIdx.y;
    const int q0   = qt * 128;
    const int b    = bh >> 4;
    const int h    = bh & (H_ - 1);
    const int jmax = 2 * qt + 1;        // tiles 0..jmax (count even)

    const size_t headoff = (size_t)bh * S_ * DH_;

    auto load_kv = [&](int j) {
        const uint32_t base = sb + SM_KV + (uint32_t)(j & 3) * KV_STG_B;
        const size_t g = headoff + (size_t)j * 64 * DH_;
        const char* srcs[2] = { (const char*)(g_k1 + g),
                                (const char*)(g_v1 + g) };
#pragma unroll
        for (int t = 0; t < 2; ++t) {
#pragma unroll
            for (int it = 0; it < 2; ++it) {
                const int c = tid + it * 256;       // 0..511
                const int r = c >> 3, c16 = c & 7;
                cp16(base + t * 8192 + swz((uint32_t)(r * 128 + c16 * 16)),
                     srcs[t] + r * 128 + c16 * 16);
            }
        }
        cp_commit();
    };

    // initial: Q tile + kv(0) in one group; kv(1) second group
    {
        const char* qsrc = (const char*)(g_q1 + headoff + (size_t)q0 * DH_);
#pragma unroll
        for (int it = 0; it < 4; ++it) {
            const int c = tid + it * 256;
            const int r = c >> 3, c16 = c & 7;
            cp16(sb + SM_Q + swz((uint32_t)(r * 128 + c16 * 16)),
                 qsrc + r * 128 + c16 * 16);
        }
    }
    load_kv(0);
    load_kv(1);

    float m0v = -1e30f, m1v = -1e30f, l0v = 0.f, l1v = 0.f;
    float o[8][4];
#pragma unroll
    for (int i = 0; i < 8; i++)
#pragma unroll
        for (int j = 0; j < 4; j++) o[i][j] = 0.f;

    uint32_t qA[4][4];
    const int qrow0 = q0 + w * 16 + gid;
    const int qrow1 = qrow0 + 8;
    const int t8 = lane >> 3;
    bool qloaded = false;

    for (int jp = 0; jp <= jmax; jp += 2) {
        cp_wait0();                 // tiles jp, jp+1 resident
        __syncthreads();            // all warps done with stages being reloaded
        if (jp + 2 <= jmax) {       // prefetch next pair (overwrites pair jp-2)
            load_kv(jp + 2);
            load_kv(jp + 3);
        }

        if (!qloaded) {             // Q fragments once
            qloaded = true;
            const int rA = w * 16 + (lane & 15);
            const uint32_t colA = (uint32_t)((lane >> 4) * 16);
#pragma unroll
            for (int ks = 0; ks < 4; ++ks) {
                const uint32_t off = swz((uint32_t)rA * 128 + ks * 32 + colA);
                ldsm4(qA[ks][0], qA[ks][1], qA[ks][2], qA[ks][3], sb + SM_Q + off);
            }
        }

#pragma unroll
        for (int sub = 0; sub < 2; ++sub) {
            const int j = jp + sub;
            const uint32_t cur = sb + SM_KV + (uint32_t)(j & 3) * KV_STG_B;
            const uint32_t KK = cur, VV = cur + 8192;
            const int k0 = j * 64;

            // ---- S = Q @ K^T  (log2 domain; Q pre-scaled) ----
            float sacc[8][4];
#pragma unroll
            for (int i = 0; i < 8; i++)
#pragma unroll
                for (int q = 0; q < 4; q++) sacc[i][q] = 0.f;

#pragma unroll
            for (int ks = 0; ks < 4; ++ks) {
                const uint32_t colB = (uint32_t)(ks * 32 + (t8 & 1) * 16);
#pragma unroll
                for (int ng = 0; ng < 4; ++ng) {
                    const int rK = ng * 16 + ((t8 >> 1) * 8) + (lane & 7);
                    const uint32_t off = swz((uint32_t)rK * 128 + colB);
                    uint32_t kk[4];
                    ldsm4(kk[0], kk[1], kk[2], kk[3], KK + off);
                    mma16816h(sacc[2*ng],   qA[ks], kk);
                    mma16816h(sacc[2*ng+1], qA[ks], kk + 2);
                }
            }

            // ---- causal mask (diagonal pair only) ----
            if (j >= 2 * qt) {
#pragma unroll
                for (int nf = 0; nf < 8; ++nf) {
                    const int col = k0 + nf * 8 + tig * 2;
                    if (col     > qrow0) sacc[nf][0] = -1e30f;
                    if (col + 1 > qrow0) sacc[nf][1] = -1e30f;
                    if (col     > qrow1) sacc[nf][2] = -1e30f;
                    if (col + 1 > qrow1) sacc[nf][3] = -1e30f;
                }
            }

            // ---- online softmax (f16x2 exponentials) ----
            float rm0 = -1e30f, rm1 = -1e30f;
#pragma unroll
            for (int nf = 0; nf < 8; ++nf) {
                rm0 = fmaxf(rm0, fmaxf(sacc[nf][0], sacc[nf][1]));
                rm1 = fmaxf(rm1, fmaxf(sacc[nf][2], sacc[nf][3]));
            }
            rm0 = fmaxf(rm0, __shfl_xor_sync(0xffffffffu, rm0, 1));
            rm0 = fmaxf(rm0, __shfl_xor_sync(0xffffffffu, rm0, 2));
            rm1 = fmaxf(rm1, __shfl_xor_sync(0xffffffffu, rm1, 1));
            rm1 = fmaxf(rm1, __shfl_xor_sync(0xffffffffu, rm1, 2));
            const float mn0 = fmaxf(m0v, rm0);
            const float mn1 = fmaxf(m1v, rm1);
            const bool up0 = (mn0 > m0v);
            const bool up1 = (mn1 > m1v);
            const float al0 = up0 ? ex2(m0v - mn0) : 1.f;
            const float al1 = up1 ? ex2(m1v - mn1) : 1.f;

            uint32_t pP[4][4];
            uint32_t racc0 = 0u, racc1 = 0u;
#pragma unroll
            for (int nf = 0; nf < 8; ++nf) {
                uint32_t p01 = ex2_h2(packh(sacc[nf][0] - mn0, sacc[nf][1] - mn0));
                uint32_t p23 = ex2_h2(packh(sacc[nf][2] - mn1, sacc[nf][3] - mn1));
                pP[nf >> 1][(nf & 1) * 2 + 0] = p01;
                pP[nf >> 1][(nf & 1) * 2 + 1] = p23;
                racc0 = hadd2(racc0, p01);
                racc1 = hadd2(racc1, p23);
            }
            float2 f0 = __half22float2(*(__half2*)&racc0);
            float2 f1 = __half22float2(*(__half2*)&racc1);
            float rs0 = f0.x + f0.y;
            float rs1 = f1.x + f1.y;
            rs0 += __shfl_xor_sync(0xffffffffu, rs0, 1);
            rs0 += __shfl_xor_sync(0xffffffffu, rs0, 2);
            rs1 += __shfl_xor_sync(0xffffffffu, rs1, 1);
            rs1 += __shfl_xor_sync(0xffffffffu, rs1, 2);
            l0v = l0v * al0 + rs0;  m0v = mn0;
            l1v = l1v * al1 + rs1;  m1v = mn1;
            if (up0) {
#pragma unroll
                for (int nf = 0; nf < 8; ++nf) { o[nf][0] *= al0; o[nf][1] *= al0; }
            }
            if (up1) {
#pragma unroll
                for (int nf = 0; nf < 8; ++nf) { o[nf][2] *= al1; o[nf][3] *= al1; }
            }

            // ---- O += P @ V  (P pre-packed; V via trans-ldmatrix) ----
#pragma unroll
            for (int ks2 = 0; ks2 < 4; ++ks2) {
                const int kq = ks2 * 16 + (t8 & 1) * 8 + (lane & 7);
#pragma unroll
                for (int og = 0; og < 4; ++og) {
                    const uint32_t off = swz((uint32_t)kq * 128 + og * 32 + (t8 >> 1) * 16);
                    uint32_t vv[4];
                    ldsm4t(vv[0], vv[1], vv[2], vv[3], VV + off);
                    mma16816h(o[2*og],   pP[ks2], vv);
                    mma16816h(o[2*og+1], pP[ks2], vv + 2);
                }
            }
        }
    }

    // ---- normalize, write ctx single fp16 row-major ----
    const float inv0 = 1.f / l0v;
    const float inv1 = 1.f / l1v;
#pragma unroll
    for (int nf = 0; nf < 8; ++nf) {
        const int dh = nf * 8 + tig * 2;
        *(__half2*)(g_c1 + (size_t)(b * S_ + qrow0) * D_ + h * DH_ + dh) =
            __floats2half2_rn(o[nf][0] * inv0, o[nf][1] * inv0);
        *(__half2*)(g_c1 + (size_t)(b * S_ + qrow1) * D_ + h * DH_ + dh) =
            __floats2half2_rn(o[nf][2] * inv1, o[nf][3] * inv1);
    }
}

// ---------------------------------------------------------------------------
extern "C" void kernel_launch(void* const* d_in, const int* in_sizes, int n_in,
                              void* d_out, int out_size)
{
    const float* x  = (const float*)d_in[0];
    const float* Wq = (const float*)d_in[1];
    const float* Wk = (const float*)d_in[2];
    const float* Wv = (const float*)d_in[3];
    const float* Wo = (const float*)d_in[4];
    const float* bo = (const float*)d_in[5];
    float* out = (float*)d_out;

    __half *x16, *w16, *c1;
    cudaGetSymbolAddress((void**)&x16, g_x16);
    cudaGetSymbolAddress((void**)&w16, g_w16);
    cudaGetSymbolAddress((void**)&c1,  g_c1);

    cudaFuncSetAttribute(tgemm<0>, cudaFuncAttributeMaxDynamicSharedMemorySize, TG_SMEM);
    cudaFuncSetAttribute(tgemm<1>, cudaFuncAttributeMaxDynamicSharedMemorySize, TG_SMEM);
    cudaFuncSetAttribute(attn_tc,  cudaFuncAttributeMaxDynamicSharedMemorySize, ATT_SMEM);

    const int n1m = D_ * D_;    // 1M elems
    convall<<<dim3(n1m/1024, 8), 256>>>(x, Wq, Wk, Wv, Wo, x16, w16);

    // fused QKV projection: N = 3072 against stacked Wq|Wk|Wv (single-term)
    tgemm<0><<<dim3(3*D_/128, M_/128), 256, TG_SMEM>>>(x16, w16, nullptr, nullptr);

    attn_tc<<<dim3(S_/128, B_*H_), 256, ATT_SMEM>>>();

    // out-projection (single-term): ctx @ Wo^T + bias
    tgemm<1><<<dim3(D_/128, M_/128), 256, TG_SMEM>>>(c1, w16 + 3*(size_t)n1m,
                                                     bo, out);
}